// round 5
// baseline (speedup 1.0000x reference)
#include <cuda_runtime.h>
#include <math.h>

// ---------------- problem constants ----------------
#define M_TOT 131072
#define CDIM  128
#define HIDDEN 512
#define HEADS 4

// ---------------- scratch ----------------
__device__ float g_qkv [(size_t)M_TOT * 3 * CDIM];
__device__ float g_attn[(size_t)M_TOT * CDIM];
__device__ float g_xres[(size_t)M_TOT * CDIM];
__device__ float g_h1  [(size_t)M_TOT * HIDDEN];
__device__ unsigned g_wtf[196608];   // tf32-converted weights: qkv|proj|fc1|fc2

__device__ __forceinline__ int perm_row(int r) {
    int b_ = r >> 7, tt = r & 127;
    int b = b_ >> 8, w = b_ & 255;
    int wh = w >> 4, ww = w & 15;
    int t = tt >> 6, n = tt & 63;
    int i = n >> 3, j = n & 7;
    int oh = (wh * 8 + i + 4) & 127;
    int ow = (ww * 8 + j + 4) & 127;
    return (b * 2 + t) * 16384 + oh * 128 + ow;
}

__device__ __forceinline__ unsigned f2tf(float f) {
    unsigned u;
    asm("cvt.rna.tf32.f32 %0, %1;" : "=r"(u) : "f"(f));
    return u;
}
__device__ __forceinline__ float round_tf(float f) { return __uint_as_float(f2tf(f)); }

#define MMA_TF32(d, a0, a1, a2, a3, b0, b1)                                            \
    asm volatile(                                                                      \
        "mma.sync.aligned.m16n8k8.row.col.f32.tf32.tf32.f32 "                          \
        "{%0,%1,%2,%3},{%4,%5,%6,%7},{%8,%9},{%0,%1,%2,%3};"                           \
        : "+f"(d[0]), "+f"(d[1]), "+f"(d[2]), "+f"(d[3])                               \
        : "r"(a0), "r"(a1), "r"(a2), "r"(a3), "r"(b0), "r"(b1))

#define GEMM_SMEM (16896 * 4)   // 2 bufs x (A 4224 + B 4224) unsigned

// ---------------- weight pre-conversion ----------------
__global__ void cvt_weights(const float* __restrict__ qkv_w, const float* __restrict__ proj_w,
                            const float* __restrict__ fc1_w, const float* __restrict__ fc2_w,
                            unsigned* __restrict__ wtf) {
    int i = blockIdx.x * 256 + threadIdx.x;
    float v;
    if (i < 49152) v = qkv_w[i];
    else if (i < 65536) v = proj_w[i - 49152];
    else if (i < 131072) v = fc1_w[i - 65536];
    else v = fc2_w[i - 131072];
    wtf[i] = f2tf(v);
}

// ---------------- tf32 GEMM, BM=128 BN=128, double-buffered ----------------
// EPI 0: qkv — A via perm_row + cvt (fused gather), plain out
// EPI 2: fc1 — A raw (pre-rounded), bias + exact gelu, out tf32-rounded
template <int EPI>
__global__ void __launch_bounds__(256, 2) mma_gemm(
    const float* __restrict__ A, const unsigned* __restrict__ Bt,
    const float* __restrict__ bias, float* __restrict__ out, int Nn, int K) {
    extern __shared__ unsigned sm[];
    unsigned* As = sm;            // 2 x 4224
    unsigned* Bs = sm + 8448;     // 2 x 4224

    const int tid = threadIdx.x;
    const int lane = tid & 31;
    const int wid = tid >> 5;
    const int wm = wid >> 1, wn = wid & 1;     // 4m x 2n; warp tile 32x64
    const int g = lane >> 2, t = lane & 3;
    const int bm = blockIdx.y * 128, bn = blockIdx.x * 128;

    int aKq[4], aSrc[4], aSts[4], bN[4], bKq[4], bSts[4];
#pragma unroll
    for (int it = 0; it < 4; it++) {
        int c = tid + it * 256;
        int row = c >> 3, kq = c & 7;
        aKq[it] = kq;
        int grow = bm + row;
        aSrc[it] = (EPI == 0) ? perm_row(grow) : grow;
        aSts[it] = ((row >> 4) * 2 + ((row >> 3) & 1)) * 264 + (kq >> 1) * 66 + (row & 7) * 8 + (kq & 1);
        bN[it] = bn + row; bKq[it] = kq;
        bSts[it] = (row >> 3) * 264 + (kq >> 1) * 66 + (row & 7) * 8 + (kq & 1);
    }

    float acc[2][8][4];
#pragma unroll
    for (int mi = 0; mi < 2; mi++)
#pragma unroll
        for (int ni = 0; ni < 8; ni++)
#pragma unroll
            for (int c = 0; c < 4; c++) acc[mi][ni][c] = 0.f;

    uint4 av[4], bv[4];
#pragma unroll
    for (int it = 0; it < 4; it++) {
        av[it] = *reinterpret_cast<const uint4*>(A + (size_t)aSrc[it] * K + aKq[it] * 4);
        bv[it] = *reinterpret_cast<const uint4*>(Bt + (size_t)bN[it] * K + bKq[it] * 4);
    }

    int p = 0;
    for (int kt = 0; kt < K; kt += 32) {
        unsigned* Ap = As + p * 4224;
        unsigned* Bp = Bs + p * 4224;
#pragma unroll
        for (int it = 0; it < 4; it++) {
            if (EPI == 0) {
                Ap[aSts[it] + 0] = f2tf(__uint_as_float(av[it].x));
                Ap[aSts[it] + 2] = f2tf(__uint_as_float(av[it].y));
                Ap[aSts[it] + 4] = f2tf(__uint_as_float(av[it].z));
                Ap[aSts[it] + 6] = f2tf(__uint_as_float(av[it].w));
            } else {
                Ap[aSts[it] + 0] = av[it].x;
                Ap[aSts[it] + 2] = av[it].y;
                Ap[aSts[it] + 4] = av[it].z;
                Ap[aSts[it] + 6] = av[it].w;
            }
            Bp[bSts[it] + 0] = bv[it].x;
            Bp[bSts[it] + 2] = bv[it].y;
            Bp[bSts[it] + 4] = bv[it].z;
            Bp[bSts[it] + 6] = bv[it].w;
        }
        __syncthreads();
        if (kt + 32 < K) {
#pragma unroll
            for (int it = 0; it < 4; it++) {
                av[it] = *reinterpret_cast<const uint4*>(A + (size_t)aSrc[it] * K + kt + 32 + aKq[it] * 4);
                bv[it] = *reinterpret_cast<const uint4*>(Bt + (size_t)bN[it] * K + kt + 32 + bKq[it] * 4);
            }
        }
#pragma unroll
        for (int k8 = 0; k8 < 4; k8++) {
            unsigned a[2][4], b[8][2];
#pragma unroll
            for (int mi = 0; mi < 2; mi++) {
                int base = ((wm * 2 + mi) * 2) * 264 + k8 * 66 + lane * 2;
                uint2 q0 = *reinterpret_cast<const uint2*>(&Ap[base]);
                uint2 q1 = *reinterpret_cast<const uint2*>(&Ap[base + 264]);
                a[mi][0] = q0.x; a[mi][2] = q0.y;
                a[mi][1] = q1.x; a[mi][3] = q1.y;
            }
#pragma unroll
            for (int ni = 0; ni < 8; ni++) {
                uint2 q = *reinterpret_cast<const uint2*>(&Bp[(wn * 8 + ni) * 264 + k8 * 66 + lane * 2]);
                b[ni][0] = q.x; b[ni][1] = q.y;
            }
#pragma unroll
            for (int mi = 0; mi < 2; mi++)
#pragma unroll
                for (int ni = 0; ni < 8; ni++)
                    MMA_TF32(acc[mi][ni], a[mi][0], a[mi][1], a[mi][2], a[mi][3],
                             b[ni][0], b[ni][1]);
        }
        p ^= 1;
    }

#pragma unroll
    for (int mi = 0; mi < 2; mi++) {
#pragma unroll
        for (int rh = 0; rh < 2; rh++) {
            int r = bm + wm * 32 + mi * 16 + g + rh * 8;
#pragma unroll
            for (int ni = 0; ni < 8; ni++) {
                int c0 = bn + wn * 64 + ni * 8 + t * 2;
#pragma unroll
                for (int ch = 0; ch < 2; ch++) {
                    float v = acc[mi][ni][rh * 2 + ch] + bias[c0 + ch];
                    if (EPI == 2) {
                        v = 0.5f * v * (1.0f + erff(v * 0.7071067811865475f));
                        v = round_tf(v);
                    }
                    out[(size_t)r * Nn + c0 + ch] = v;
                }
            }
        }
    }
}

// ---------------- tf32 GEMM + residual + LayerNorm, BM=128 BN=128 ----------------
// EPI 1: proj — res/aux/dst rows at perm(r): aux=xres gets v, dst=xln gets LN(v) rounded
// EPI 3: fc2  — rows aligned, dst=final out gets LN(v) full precision
template <int EPI>
__global__ void __launch_bounds__(256, 2) mma_gemm_ln(
    const float* __restrict__ A, const unsigned* __restrict__ Bt,
    const float* __restrict__ bias, const float* __restrict__ res,
    float* __restrict__ aux, float* __restrict__ dst,
    const float* __restrict__ gw, const float* __restrict__ bw, int K) {
    extern __shared__ unsigned sm[];
    unsigned* As = sm;
    unsigned* Bs = sm + 8448;
    __shared__ float smS[128][2], smQ[128][2];

    const int tid = threadIdx.x;
    const int lane = tid & 31;
    const int wid = tid >> 5;
    const int wm = wid >> 1, wn = wid & 1;
    const int g = lane >> 2, t = lane & 3;
    const int bm = blockIdx.y * 128;

    int aKq[4], aSrc[4], aSts[4], bN[4], bKq[4], bSts[4];
#pragma unroll
    for (int it = 0; it < 4; it++) {
        int c = tid + it * 256;
        int row = c >> 3, kq = c & 7;
        aKq[it] = kq; aSrc[it] = bm + row;
        aSts[it] = ((row >> 4) * 2 + ((row >> 3) & 1)) * 264 + (kq >> 1) * 66 + (row & 7) * 8 + (kq & 1);
        bN[it] = row; bKq[it] = kq;
        bSts[it] = (row >> 3) * 264 + (kq >> 1) * 66 + (row & 7) * 8 + (kq & 1);
    }

    float acc[2][8][4];
#pragma unroll
    for (int mi = 0; mi < 2; mi++)
#pragma unroll
        for (int ni = 0; ni < 8; ni++)
#pragma unroll
            for (int c = 0; c < 4; c++) acc[mi][ni][c] = 0.f;

    uint4 av[4], bv[4];
#pragma unroll
    for (int it = 0; it < 4; it++) {
        av[it] = *reinterpret_cast<const uint4*>(A + (size_t)aSrc[it] * K + aKq[it] * 4);
        bv[it] = *reinterpret_cast<const uint4*>(Bt + (size_t)bN[it] * K + bKq[it] * 4);
    }

    int p = 0;
    for (int kt = 0; kt < K; kt += 32) {
        unsigned* Ap = As + p * 4224;
        unsigned* Bp = Bs + p * 4224;
#pragma unroll
        for (int it = 0; it < 4; it++) {
            Ap[aSts[it] + 0] = av[it].x;
            Ap[aSts[it] + 2] = av[it].y;
            Ap[aSts[it] + 4] = av[it].z;
            Ap[aSts[it] + 6] = av[it].w;
            Bp[bSts[it] + 0] = bv[it].x;
            Bp[bSts[it] + 2] = bv[it].y;
            Bp[bSts[it] + 4] = bv[it].z;
            Bp[bSts[it] + 6] = bv[it].w;
        }
        __syncthreads();
        if (kt + 32 < K) {
#pragma unroll
            for (int it = 0; it < 4; it++) {
                av[it] = *reinterpret_cast<const uint4*>(A + (size_t)aSrc[it] * K + kt + 32 + aKq[it] * 4);
                bv[it] = *reinterpret_cast<const uint4*>(Bt + (size_t)bN[it] * K + kt + 32 + bKq[it] * 4);
            }
        }
#pragma unroll
        for (int k8 = 0; k8 < 4; k8++) {
            unsigned a[2][4], b[8][2];
#pragma unroll
            for (int mi = 0; mi < 2; mi++) {
                int base = ((wm * 2 + mi) * 2) * 264 + k8 * 66 + lane * 2;
                uint2 q0 = *reinterpret_cast<const uint2*>(&Ap[base]);
                uint2 q1 = *reinterpret_cast<const uint2*>(&Ap[base + 264]);
                a[mi][0] = q0.x; a[mi][2] = q0.y;
                a[mi][1] = q1.x; a[mi][3] = q1.y;
            }
#pragma unroll
            for (int ni = 0; ni < 8; ni++) {
                uint2 q = *reinterpret_cast<const uint2*>(&Bp[(wn * 8 + ni) * 264 + k8 * 66 + lane * 2]);
                b[ni][0] = q.x; b[ni][1] = q.y;
            }
#pragma unroll
            for (int mi = 0; mi < 2; mi++)
#pragma unroll
                for (int ni = 0; ni < 8; ni++)
                    MMA_TF32(acc[mi][ni], a[mi][0], a[mi][1], a[mi][2], a[mi][3],
                             b[ni][0], b[ni][1]);
        }
        p ^= 1;
    }

    // epilogue: bias + residual, row LayerNorm over 128 cols (2 warps per row)
#pragma unroll
    for (int mi = 0; mi < 2; mi++) {
#pragma unroll
        for (int rh = 0; rh < 2; rh++) {
            int lrow = wm * 32 + mi * 16 + g + rh * 8;
            int r = bm + lrow;
            int xrow = (EPI == 1) ? perm_row(r) : r;
            float v[16];
            float s = 0.f, q = 0.f;
#pragma unroll
            for (int ni = 0; ni < 8; ni++) {
                int c = wn * 64 + ni * 8 + t * 2;
#pragma unroll
                for (int ch = 0; ch < 2; ch++) {
                    float x = acc[mi][ni][rh * 2 + ch] + bias[c + ch] +
                              res[(size_t)xrow * 128 + c + ch];
                    if (EPI == 1) aux[(size_t)xrow * 128 + c + ch] = x;
                    v[ni * 2 + ch] = x;
                    s += x; q += x * x;
                }
            }
            s += __shfl_xor_sync(0xffffffffu, s, 1);
            s += __shfl_xor_sync(0xffffffffu, s, 2);
            q += __shfl_xor_sync(0xffffffffu, q, 1);
            q += __shfl_xor_sync(0xffffffffu, q, 2);
            if (t == 0) { smS[lrow][wn] = s; smQ[lrow][wn] = q; }
            __syncthreads();
            float S = smS[lrow][0] + smS[lrow][1];
            float Q = smQ[lrow][0] + smQ[lrow][1];
            float mu = S * (1.f / 128.f);
            float var = Q * (1.f / 128.f) - mu * mu;
            float rs = rsqrtf(var + 1e-5f);
#pragma unroll
            for (int ni = 0; ni < 8; ni++) {
                int c = wn * 64 + ni * 8 + t * 2;
#pragma unroll
                for (int ch = 0; ch < 2; ch++) {
                    float o = (v[ni * 2 + ch] - mu) * rs * gw[c + ch] + bw[c + ch];
                    if (EPI == 1) o = round_tf(o);
                    dst[(size_t)xrow * 128 + c + ch] = o;
                }
            }
        }
    }
}

// ---------------- tensor-core window attention ----------------
#define SM_QA 0
#define SM_KB 4224
#define SM_VB 8448
#define SM_PS 12704
#define SMEM_ATTN ((12704 + 4096) * 4)

__global__ __launch_bounds__(256) void attn_kernel(const float* __restrict__ qkv,
                                                   const float* __restrict__ rpb,
                                                   float* __restrict__ attout) {
    extern __shared__ unsigned sm[];
    unsigned* QA = sm + SM_QA;
    unsigned* KB = sm + SM_KB;
    unsigned* VB = sm + SM_VB;
    float* Psf = (float*)(sm + SM_PS);

    const int win = blockIdx.x, head = blockIdx.y;
    const int tid = threadIdx.x;
    const int lane = tid & 31, w = tid >> 5;
    const int g = lane >> 2, t = lane & 3;
    const float scale = 0.17677669529663687f;

#pragma unroll
    for (int it = 0; it < 4; it++) {
        int c = tid + it * 256;
        int row = c >> 3, kq = c & 7;
        size_t base = ((size_t)(win * 128 + row)) * 384 + head * 32 + kq * 4;
        float4 qv = *reinterpret_cast<const float4*>(qkv + base);
        float4 kv = *reinterpret_cast<const float4*>(qkv + base + 128);
        float4 vv = *reinterpret_cast<const float4*>(qkv + base + 256);
        int k8 = kq >> 1, kh = kq & 1;
        int qa = ((row >> 4) * 2 + ((row >> 3) & 1)) * 264 + k8 * 66 + (row & 7) * 8 + kh;
        QA[qa + 0] = f2tf(qv.x * scale); QA[qa + 2] = f2tf(qv.y * scale);
        QA[qa + 4] = f2tf(qv.z * scale); QA[qa + 6] = f2tf(qv.w * scale);
        int kb = (row >> 3) * 264 + k8 * 66 + (row & 7) * 8 + kh;
        KB[kb + 0] = f2tf(kv.x); KB[kb + 2] = f2tf(kv.y);
        KB[kb + 4] = f2tf(kv.z); KB[kb + 6] = f2tf(kv.w);
        int vb = (kq >> 1) * 1064 + (row >> 3) * 66 + ((kq & 1) * 4) * 8 +
                 ((row >> 2) & 1) + 2 * (row & 3);
        VB[vb + 0]  = f2tf(vv.x); VB[vb + 8]  = f2tf(vv.y);
        VB[vb + 16] = f2tf(vv.z); VB[vb + 24] = f2tf(vv.w);
    }

    {
        int wwin = win & 255;
        int wh = wwin >> 4, ww = wwin & 15;
#pragma unroll
        for (int it = 0; it < 16; it++) {
            int e = tid + it * 256;
            int qn = e >> 6, kn = e & 63;
            int qi2 = qn >> 3, qj = qn & 7, ki = kn >> 3, kj = kn & 7;
            int rel = (qi2 - ki + 7) * 15 + (qj - kj + 7);
            float v = rpb[rel * HEADS + head];
            int gqh = wh * 8 + qi2, gqw = ww * 8 + qj;
            int gkh = wh * 8 + ki,  gkw = ww * 8 + kj;
            int rq = (gqh < 120 ? 0 : (gqh < 124 ? 1 : 2)) * 3 + (gqw < 120 ? 0 : (gqw < 124 ? 1 : 2));
            int rk = (gkh < 120 ? 0 : (gkh < 124 ? 1 : 2)) * 3 + (gkw < 120 ? 0 : (gkw < 124 ? 1 : 2));
            if (rq != rk) v -= 100.0f;
            int qtile = qn >> 4, ntile = kn >> 3;
            int ln = (qn & 7) * 4 + ((kn & 7) >> 1);
            int reg = ((qn >> 3) & 1) * 2 + (kn & 1);
            Psf[((qtile * 8 + ntile) * 32 + ln) * 4 + reg] = v;
        }
    }
    __syncthreads();

    float acc[16][4];
#pragma unroll
    for (int nt = 0; nt < 16; nt++)
#pragma unroll
        for (int i = 0; i < 4; i++) acc[nt][i] = 0.f;

#pragma unroll
    for (int k8 = 0; k8 < 4; k8++) {
        int abase = (w * 2) * 264 + k8 * 66 + lane * 2;
        uint2 q0 = *reinterpret_cast<const uint2*>(&QA[abase]);
        uint2 q1 = *reinterpret_cast<const uint2*>(&QA[abase + 264]);
#pragma unroll
        for (int nt = 0; nt < 16; nt++) {
            uint2 b = *reinterpret_cast<const uint2*>(&KB[nt * 264 + k8 * 66 + lane * 2]);
            MMA_TF32(acc[nt], q0.x, q1.x, q0.y, q1.y, b.x, b.y);
        }
    }

    const int qtile = w & 3;
    float m0 = -1e30f, m1 = -1e30f;
#pragma unroll
    for (int nt = 0; nt < 16; nt++) {
        float4 p = *reinterpret_cast<const float4*>(&Psf[((qtile * 8 + (nt & 7)) * 32 + lane) * 4]);
        acc[nt][0] += p.x; acc[nt][1] += p.y;
        acc[nt][2] += p.z; acc[nt][3] += p.w;
        m0 = fmaxf(m0, fmaxf(acc[nt][0], acc[nt][1]));
        m1 = fmaxf(m1, fmaxf(acc[nt][2], acc[nt][3]));
    }
    m0 = fmaxf(m0, __shfl_xor_sync(0xffffffffu, m0, 1));
    m0 = fmaxf(m0, __shfl_xor_sync(0xffffffffu, m0, 2));
    m1 = fmaxf(m1, __shfl_xor_sync(0xffffffffu, m1, 1));
    m1 = fmaxf(m1, __shfl_xor_sync(0xffffffffu, m1, 2));

    float l0 = 0.f, l1 = 0.f;
#pragma unroll
    for (int nt = 0; nt < 16; nt++) {
        acc[nt][0] = __expf(acc[nt][0] - m0);
        acc[nt][1] = __expf(acc[nt][1] - m0);
        acc[nt][2] = __expf(acc[nt][2] - m1);
        acc[nt][3] = __expf(acc[nt][3] - m1);
        l0 += acc[nt][0] + acc[nt][1];
        l1 += acc[nt][2] + acc[nt][3];
    }
    l0 += __shfl_xor_sync(0xffffffffu, l0, 1);
    l0 += __shfl_xor_sync(0xffffffffu, l0, 2);
    l1 += __shfl_xor_sync(0xffffffffu, l1, 1);
    l1 += __shfl_xor_sync(0xffffffffu, l1, 2);
    float inv0 = 1.0f / l0, inv1 = 1.0f / l1;

#pragma unroll
    for (int nt = 0; nt < 16; nt++)
#pragma unroll
        for (int i = 0; i < 4; i++)
            acc[nt][i] = __uint_as_float(f2tf(acc[nt][i]));

    float oacc[4][4];
#pragma unroll
    for (int n8 = 0; n8 < 4; n8++)
#pragma unroll
        for (int i = 0; i < 4; i++) oacc[n8][i] = 0.f;

    const int s0 = (lane & 28) | (t >> 1);
    const int s1 = s0 + 2;
    const bool oddt = (t & 1);
#pragma unroll
    for (int c = 0; c < 16; c++) {
        float e0 = __shfl_sync(0xffffffffu, acc[c][0], s0);
        float o0 = __shfl_sync(0xffffffffu, acc[c][1], s0);
        float e1 = __shfl_sync(0xffffffffu, acc[c][2], s0);
        float o1 = __shfl_sync(0xffffffffu, acc[c][3], s0);
        float e2 = __shfl_sync(0xffffffffu, acc[c][0], s1);
        float o2 = __shfl_sync(0xffffffffu, acc[c][1], s1);
        float e3 = __shfl_sync(0xffffffffu, acc[c][2], s1);
        float o3 = __shfl_sync(0xffffffffu, acc[c][3], s1);
        unsigned a0 = __float_as_uint(oddt ? o0 : e0);
        unsigned a1 = __float_as_uint(oddt ? o1 : e1);
        unsigned a2 = __float_as_uint(oddt ? o2 : e2);
        unsigned a3 = __float_as_uint(oddt ? o3 : e3);
#pragma unroll
        for (int n8 = 0; n8 < 4; n8++) {
            uint2 b = *reinterpret_cast<const uint2*>(&VB[n8 * 1064 + c * 66 + lane * 2]);
            MMA_TF32(oacc[n8], a0, a1, a2, a3, b.x, b.y);
        }
    }

    // write tf32-rounded so proj GEMM consumes raw bits with no cvt
    int r0 = win * 128 + w * 16 + g;
#pragma unroll
    for (int n8 = 0; n8 < 4; n8++) {
        int col = head * 32 + n8 * 8 + t * 2;
        attout[(size_t)r0 * 128 + col]           = round_tf(oacc[n8][0] * inv0);
        attout[(size_t)r0 * 128 + col + 1]       = round_tf(oacc[n8][1] * inv0);
        attout[(size_t)(r0 + 8) * 128 + col]     = round_tf(oacc[n8][2] * inv1);
        attout[(size_t)(r0 + 8) * 128 + col + 1] = round_tf(oacc[n8][3] * inv1);
    }
}

// ---------------- launch ----------------
extern "C" void kernel_launch(void* const* d_in, const int* in_sizes, int n_in,
                              void* d_out, int out_size) {
    const float* x_v    = (const float*)d_in[0];
    const float* qkv_w  = (const float*)d_in[1];
    const float* qkv_b  = (const float*)d_in[2];
    const float* proj_w = (const float*)d_in[3];
    const float* proj_b = (const float*)d_in[4];
    const float* rpb    = (const float*)d_in[5];
    const float* n1w    = (const float*)d_in[6];
    const float* n1b    = (const float*)d_in[7];
    const float* n2w    = (const float*)d_in[8];
    const float* n2b    = (const float*)d_in[9];
    const float* fc1w   = (const float*)d_in[10];
    const float* fc1b   = (const float*)d_in[11];
    const float* fc2w   = (const float*)d_in[12];
    const float* fc2b   = (const float*)d_in[13];
    float* out = (float*)d_out;

    float *qkvb, *attn, *xres, *h1;
    unsigned* wtf;
    cudaGetSymbolAddress((void**)&qkvb, g_qkv);
    cudaGetSymbolAddress((void**)&attn, g_attn);
    cudaGetSymbolAddress((void**)&xres, g_xres);
    cudaGetSymbolAddress((void**)&h1,   g_h1);
    cudaGetSymbolAddress((void**)&wtf,  g_wtf);
    float* xln = qkvb;   // reuse: qkv dead after attention

    cudaFuncSetAttribute(attn_kernel, cudaFuncAttributeMaxDynamicSharedMemorySize, SMEM_ATTN);
    cudaFuncSetAttribute(mma_gemm<0>, cudaFuncAttributeMaxDynamicSharedMemorySize, GEMM_SMEM);
    cudaFuncSetAttribute(mma_gemm<2>, cudaFuncAttributeMaxDynamicSharedMemorySize, GEMM_SMEM);
    cudaFuncSetAttribute(mma_gemm_ln<1>, cudaFuncAttributeMaxDynamicSharedMemorySize, GEMM_SMEM);
    cudaFuncSetAttribute(mma_gemm_ln<3>, cudaFuncAttributeMaxDynamicSharedMemorySize, GEMM_SMEM);

    // 0. convert weights to tf32 once
    cvt_weights<<<768, 256>>>(qkv_w, proj_w, fc1w, fc2w, wtf);
    // 1. qkv = gather(x_v) @ qkv_w^T + b
    mma_gemm<0><<<dim3(3, 1024), 256, GEMM_SMEM>>>(x_v, wtf, qkv_b, qkvb, 384, 128);
    // 2. tensor-core window attention (writes tf32-rounded)
    attn_kernel<<<dim3(1024, HEADS), 256, SMEM_ATTN>>>(qkvb, rpb, attn);
    // 3. proj + scatter + residual + LN2 (xres full, xln rounded)
    mma_gemm_ln<1><<<dim3(1, 1024), 256, GEMM_SMEM>>>(attn, wtf + 49152, proj_b, x_v,
                                                      xres, xln, n2w, n2b, 128);
    // 4. fc1 + gelu (h1 rounded)
    mma_gemm<2><<<dim3(4, 1024), 256, GEMM_SMEM>>>(xln, wtf + 65536, fc1b, h1, 512, 128);
    // 5. fc2 + residual + LN1 -> final output (full precision)
    mma_gemm_ln<3><<<dim3(1, 1024), 256, GEMM_SMEM>>>(h1, wtf + 131072, fc2b, xres,
                                                      nullptr, out, n1w, n1b, 512);
}

// round 6
// speedup vs baseline: 1.4379x; 1.4379x over previous
#include <cuda_runtime.h>
#include <math.h>

// ---------------- problem constants ----------------
#define M_TOT 131072
#define CDIM  128
#define HIDDEN 512
#define HEADS 4

// ---------------- scratch ----------------
__device__ float g_qkv [(size_t)M_TOT * 3 * CDIM];
__device__ float g_attn[(size_t)M_TOT * CDIM];
__device__ float g_xres[(size_t)M_TOT * CDIM];
__device__ float g_h1  [(size_t)M_TOT * HIDDEN];
__device__ unsigned g_wtf[196608];   // tf32 weights: qkv|proj|fc1|fc2

__device__ __forceinline__ int perm_row(int r) {
    int b_ = r >> 7, tt = r & 127;
    int b = b_ >> 8, w = b_ & 255;
    int wh = w >> 4, ww = w & 15;
    int t = tt >> 6, n = tt & 63;
    int i = n >> 3, j = n & 7;
    int oh = (wh * 8 + i + 4) & 127;
    int ow = (ww * 8 + j + 4) & 127;
    return (b * 2 + t) * 16384 + oh * 128 + ow;
}

__device__ __forceinline__ unsigned f2tf(float f) {
    unsigned u;
    asm("cvt.rna.tf32.f32 %0, %1;" : "=r"(u) : "f"(f));
    return u;
}
__device__ __forceinline__ float round_tf(float f) { return __uint_as_float(f2tf(f)); }

#define MMA_TF32(d, a0, a1, a2, a3, b0, b1)                                            \
    asm volatile(                                                                      \
        "mma.sync.aligned.m16n8k8.row.col.f32.tf32.tf32.f32 "                          \
        "{%0,%1,%2,%3},{%4,%5,%6,%7},{%8,%9},{%0,%1,%2,%3};"                           \
        : "+f"(d[0]), "+f"(d[1]), "+f"(d[2]), "+f"(d[3])                               \
        : "r"(a0), "r"(a1), "r"(a2), "r"(a3), "r"(b0), "r"(b1))

#define GEMM_SMEM (12672 * 4)   // 50688 B: double-buffered tiles

// ---------------- weight pre-conversion ----------------
__global__ void cvt_weights(const float* __restrict__ qkv_w, const float* __restrict__ proj_w,
                            const float* __restrict__ fc1_w, const float* __restrict__ fc2_w,
                            unsigned* __restrict__ wtf) {
    int i = blockIdx.x * 256 + threadIdx.x;
    float v;
    if (i < 49152) v = qkv_w[i];
    else if (i < 65536) v = proj_w[i - 49152];
    else if (i < 131072) v = fc1_w[i - 65536];
    else v = fc2_w[i - 131072];
    wtf[i] = f2tf(v);
}

// ---------------- tf32 GEMM, BM=128 BN=64, double-buffered ----------------
// EPI 0: qkv — A via perm_row + cvt (fused gather), plain out
// EPI 2: fc1 — A raw (pre-rounded), bias + exact gelu, out tf32-rounded
template <int EPI>
__global__ __launch_bounds__(256) void mma_gemm(
    const float* __restrict__ A, const unsigned* __restrict__ Bt,
    const float* __restrict__ bias, float* __restrict__ out, int Nn, int K) {
    extern __shared__ unsigned sm[];
    unsigned* As = sm;            // 2 x 4224
    unsigned* Bs = sm + 8448;     // 2 x 2112

    const int tid = threadIdx.x;
    const int lane = tid & 31;
    const int wid = tid >> 5;
    const int wm = wid >> 1, wn = wid & 1;
    const int g = lane >> 2, t = lane & 3;
    const int bm = blockIdx.y * 128, bn = blockIdx.x * 64;

    int aKq[4], aSrc[4], aSts[4];
#pragma unroll
    for (int it = 0; it < 4; it++) {
        int c = tid + it * 256;
        int row = c >> 3, kq = c & 7;
        aKq[it] = kq;
        int grow = bm + row;
        aSrc[it] = (EPI == 0) ? perm_row(grow) : grow;
        aSts[it] = ((row >> 4) * 2 + ((row >> 3) & 1)) * 264 + (kq >> 1) * 66 + (row & 7) * 8 + (kq & 1);
    }
    int bN[2], bKq[2], bSts[2];
#pragma unroll
    for (int it = 0; it < 2; it++) {
        int c = tid + it * 256;
        int n = c >> 3, kq = c & 7;
        bN[it] = bn + n; bKq[it] = kq;
        bSts[it] = (n >> 3) * 264 + (kq >> 1) * 66 + (n & 7) * 8 + (kq & 1);
    }

    float acc[2][4][4];
#pragma unroll
    for (int mi = 0; mi < 2; mi++)
#pragma unroll
        for (int ni = 0; ni < 4; ni++)
#pragma unroll
            for (int c = 0; c < 4; c++) acc[mi][ni][c] = 0.f;

    uint4 av[4], bv[2];
#pragma unroll
    for (int it = 0; it < 4; it++)
        av[it] = *reinterpret_cast<const uint4*>(A + (size_t)aSrc[it] * K + aKq[it] * 4);
#pragma unroll
    for (int it = 0; it < 2; it++)
        bv[it] = *reinterpret_cast<const uint4*>(Bt + (size_t)bN[it] * K + bKq[it] * 4);

    int p = 0;
    for (int kt = 0; kt < K; kt += 32) {
        unsigned* Ap = As + p * 4224;
        unsigned* Bp = Bs + p * 2112;
#pragma unroll
        for (int it = 0; it < 4; it++) {
            if (EPI == 0) {
                Ap[aSts[it] + 0] = f2tf(__uint_as_float(av[it].x));
                Ap[aSts[it] + 2] = f2tf(__uint_as_float(av[it].y));
                Ap[aSts[it] + 4] = f2tf(__uint_as_float(av[it].z));
                Ap[aSts[it] + 6] = f2tf(__uint_as_float(av[it].w));
            } else {
                Ap[aSts[it] + 0] = av[it].x;
                Ap[aSts[it] + 2] = av[it].y;
                Ap[aSts[it] + 4] = av[it].z;
                Ap[aSts[it] + 6] = av[it].w;
            }
        }
#pragma unroll
        for (int it = 0; it < 2; it++) {
            Bp[bSts[it] + 0] = bv[it].x;
            Bp[bSts[it] + 2] = bv[it].y;
            Bp[bSts[it] + 4] = bv[it].z;
            Bp[bSts[it] + 6] = bv[it].w;
        }
        __syncthreads();
        if (kt + 32 < K) {
#pragma unroll
            for (int it = 0; it < 4; it++)
                av[it] = *reinterpret_cast<const uint4*>(A + (size_t)aSrc[it] * K + kt + 32 + aKq[it] * 4);
#pragma unroll
            for (int it = 0; it < 2; it++)
                bv[it] = *reinterpret_cast<const uint4*>(Bt + (size_t)bN[it] * K + kt + 32 + bKq[it] * 4);
        }
#pragma unroll
        for (int k8 = 0; k8 < 4; k8++) {
            unsigned a[2][4], b[4][2];
#pragma unroll
            for (int mi = 0; mi < 2; mi++) {
                int base = ((wm * 2 + mi) * 2) * 264 + k8 * 66 + lane * 2;
                uint2 q0 = *reinterpret_cast<const uint2*>(&Ap[base]);
                uint2 q1 = *reinterpret_cast<const uint2*>(&Ap[base + 264]);
                a[mi][0] = q0.x; a[mi][2] = q0.y;
                a[mi][1] = q1.x; a[mi][3] = q1.y;
            }
#pragma unroll
            for (int ni = 0; ni < 4; ni++) {
                uint2 q = *reinterpret_cast<const uint2*>(&Bp[(wn * 4 + ni) * 264 + k8 * 66 + lane * 2]);
                b[ni][0] = q.x; b[ni][1] = q.y;
            }
#pragma unroll
            for (int mi = 0; mi < 2; mi++)
#pragma unroll
                for (int ni = 0; ni < 4; ni++)
                    MMA_TF32(acc[mi][ni], a[mi][0], a[mi][1], a[mi][2], a[mi][3],
                             b[ni][0], b[ni][1]);
        }
        p ^= 1;
    }

#pragma unroll
    for (int mi = 0; mi < 2; mi++) {
        int r0 = bm + wm * 32 + mi * 16 + g;
#pragma unroll
        for (int rh = 0; rh < 2; rh++) {
            int r = r0 + rh * 8;
#pragma unroll
            for (int ni = 0; ni < 4; ni++) {
                int c0 = bn + wn * 32 + ni * 8 + t * 2;
#pragma unroll
                for (int ch = 0; ch < 2; ch++) {
                    int c = c0 + ch;
                    float v = acc[mi][ni][rh * 2 + ch] + bias[c];
                    if (EPI == 2) {
                        v = 0.5f * v * (1.0f + erff(v * 0.7071067811865475f));
                        v = round_tf(v);
                    }
                    out[(size_t)r * Nn + c] = v;
                }
            }
        }
    }
}

// ---------------- tf32 GEMM + residual + LayerNorm, BM=64 BN=128 ----------------
// EPI 1: proj — rows at perm(r): aux=xres gets full v, dst=xln gets LN(v) rounded
// EPI 3: fc2  — rows aligned, dst=final out gets LN(v) full precision
template <int EPI>
__global__ __launch_bounds__(256) void mma_gemm_ln(
    const float* __restrict__ A, const unsigned* __restrict__ Bt,
    const float* __restrict__ bias, const float* __restrict__ res,
    float* __restrict__ aux, float* __restrict__ dst,
    const float* __restrict__ gw, const float* __restrict__ bw, int K) {
    extern __shared__ unsigned sm[];
    unsigned* As = sm;            // 2 x 2112
    unsigned* Bs = sm + 4224;     // 2 x 4224
    __shared__ float smS[64][4], smQ[64][4];

    const int tid = threadIdx.x;
    const int lane = tid & 31;
    const int wid = tid >> 5;
    const int wm = wid >> 2, wn = wid & 3;     // 2m x 4n
    const int g = lane >> 2, t = lane & 3;
    const int bm = blockIdx.y * 64;

    int aKq[2], aSrc[2], aSts[2];
#pragma unroll
    for (int it = 0; it < 2; it++) {
        int c = tid + it * 256;
        int row = c >> 3, kq = c & 7;
        aKq[it] = kq; aSrc[it] = bm + row;
        aSts[it] = ((row >> 4) * 2 + ((row >> 3) & 1)) * 264 + (kq >> 1) * 66 + (row & 7) * 8 + (kq & 1);
    }
    int bN[4], bKq[4], bSts[4];
#pragma unroll
    for (int it = 0; it < 4; it++) {
        int c = tid + it * 256;
        int n = c >> 3, kq = c & 7;
        bN[it] = n; bKq[it] = kq;
        bSts[it] = (n >> 3) * 264 + (kq >> 1) * 66 + (n & 7) * 8 + (kq & 1);
    }

    float acc[2][4][4];
#pragma unroll
    for (int mi = 0; mi < 2; mi++)
#pragma unroll
        for (int ni = 0; ni < 4; ni++)
#pragma unroll
            for (int c = 0; c < 4; c++) acc[mi][ni][c] = 0.f;

    uint4 av[2], bv[4];
#pragma unroll
    for (int it = 0; it < 2; it++)
        av[it] = *reinterpret_cast<const uint4*>(A + (size_t)aSrc[it] * K + aKq[it] * 4);
#pragma unroll
    for (int it = 0; it < 4; it++)
        bv[it] = *reinterpret_cast<const uint4*>(Bt + (size_t)bN[it] * K + bKq[it] * 4);

    int p = 0;
    for (int kt = 0; kt < K; kt += 32) {
        unsigned* Ap = As + p * 2112;
        unsigned* Bp = Bs + p * 4224;
#pragma unroll
        for (int it = 0; it < 2; it++) {
            Ap[aSts[it] + 0] = av[it].x;
            Ap[aSts[it] + 2] = av[it].y;
            Ap[aSts[it] + 4] = av[it].z;
            Ap[aSts[it] + 6] = av[it].w;
        }
#pragma unroll
        for (int it = 0; it < 4; it++) {
            Bp[bSts[it] + 0] = bv[it].x;
            Bp[bSts[it] + 2] = bv[it].y;
            Bp[bSts[it] + 4] = bv[it].z;
            Bp[bSts[it] + 6] = bv[it].w;
        }
        __syncthreads();
        if (kt + 32 < K) {
#pragma unroll
            for (int it = 0; it < 2; it++)
                av[it] = *reinterpret_cast<const uint4*>(A + (size_t)aSrc[it] * K + kt + 32 + aKq[it] * 4);
#pragma unroll
            for (int it = 0; it < 4; it++)
                bv[it] = *reinterpret_cast<const uint4*>(Bt + (size_t)bN[it] * K + kt + 32 + bKq[it] * 4);
        }
#pragma unroll
        for (int k8 = 0; k8 < 4; k8++) {
            unsigned a[2][4], b[4][2];
#pragma unroll
            for (int mi = 0; mi < 2; mi++) {
                int base = ((wm * 2 + mi) * 2) * 264 + k8 * 66 + lane * 2;
                uint2 q0 = *reinterpret_cast<const uint2*>(&Ap[base]);
                uint2 q1 = *reinterpret_cast<const uint2*>(&Ap[base + 264]);
                a[mi][0] = q0.x; a[mi][2] = q0.y;
                a[mi][1] = q1.x; a[mi][3] = q1.y;
            }
#pragma unroll
            for (int ni = 0; ni < 4; ni++) {
                uint2 q = *reinterpret_cast<const uint2*>(&Bp[(wn * 4 + ni) * 264 + k8 * 66 + lane * 2]);
                b[ni][0] = q.x; b[ni][1] = q.y;
            }
#pragma unroll
            for (int mi = 0; mi < 2; mi++)
#pragma unroll
                for (int ni = 0; ni < 4; ni++)
                    MMA_TF32(acc[mi][ni], a[mi][0], a[mi][1], a[mi][2], a[mi][3],
                             b[ni][0], b[ni][1]);
        }
        p ^= 1;
    }

    // epilogue: bias + residual, row LayerNorm over 128 cols
#pragma unroll
    for (int mi = 0; mi < 2; mi++) {
#pragma unroll
        for (int rh = 0; rh < 2; rh++) {
            int lrow = (wm * 2 + mi) * 16 + g + rh * 8;
            int r = bm + lrow;
            int xrow = (EPI == 1) ? perm_row(r) : r;
            float v[8];
            float s = 0.f, q = 0.f;
#pragma unroll
            for (int ni = 0; ni < 4; ni++) {
                int c = wn * 32 + ni * 8 + t * 2;
#pragma unroll
                for (int ch = 0; ch < 2; ch++) {
                    float x = acc[mi][ni][rh * 2 + ch] + bias[c + ch] +
                              res[(size_t)xrow * 128 + c + ch];
                    if (EPI == 1) aux[(size_t)xrow * 128 + c + ch] = x;
                    v[ni * 2 + ch] = x;
                    s += x; q += x * x;
                }
            }
            s += __shfl_xor_sync(0xffffffffu, s, 1);
            s += __shfl_xor_sync(0xffffffffu, s, 2);
            q += __shfl_xor_sync(0xffffffffu, q, 1);
            q += __shfl_xor_sync(0xffffffffu, q, 2);
            if (t == 0) { smS[lrow][wn] = s; smQ[lrow][wn] = q; }
            __syncthreads();
            float S = smS[lrow][0] + smS[lrow][1] + smS[lrow][2] + smS[lrow][3];
            float Q = smQ[lrow][0] + smQ[lrow][1] + smQ[lrow][2] + smQ[lrow][3];
            float mu = S * (1.f / 128.f);
            float var = Q * (1.f / 128.f) - mu * mu;
            float rs = rsqrtf(var + 1e-5f);
#pragma unroll
            for (int ni = 0; ni < 4; ni++) {
                int c = wn * 32 + ni * 8 + t * 2;
#pragma unroll
                for (int ch = 0; ch < 2; ch++) {
                    float o = (v[ni * 2 + ch] - mu) * rs * gw[c + ch] + bw[c + ch];
                    if (EPI == 1) o = round_tf(o);
                    dst[(size_t)xrow * 128 + c + ch] = o;
                }
            }
        }
    }
}

// ---------------- tensor-core window attention ----------------
#define SM_QA 0
#define SM_KB 4224
#define SM_VB 8448
#define SM_PS 12704
#define SMEM_ATTN ((12704 + 4096) * 4)

__global__ __launch_bounds__(256) void attn_kernel(const float* __restrict__ qkv,
                                                   const float* __restrict__ rpb,
                                                   float* __restrict__ attout) {
    extern __shared__ unsigned sm[];
    unsigned* QA = sm + SM_QA;
    unsigned* KB = sm + SM_KB;
    unsigned* VB = sm + SM_VB;
    float* Psf = (float*)(sm + SM_PS);

    const int win = blockIdx.x, head = blockIdx.y;
    const int tid = threadIdx.x;
    const int lane = tid & 31, w = tid >> 5;
    const int g = lane >> 2, t = lane & 3;
    const float scale = 0.17677669529663687f;

#pragma unroll
    for (int it = 0; it < 4; it++) {
        int c = tid + it * 256;
        int row = c >> 3, kq = c & 7;
        size_t base = ((size_t)(win * 128 + row)) * 384 + head * 32 + kq * 4;
        float4 qv = *reinterpret_cast<const float4*>(qkv + base);
        float4 kv = *reinterpret_cast<const float4*>(qkv + base + 128);
        float4 vv = *reinterpret_cast<const float4*>(qkv + base + 256);
        int k8 = kq >> 1, kh = kq & 1;
        int qa = ((row >> 4) * 2 + ((row >> 3) & 1)) * 264 + k8 * 66 + (row & 7) * 8 + kh;
        QA[qa + 0] = f2tf(qv.x * scale); QA[qa + 2] = f2tf(qv.y * scale);
        QA[qa + 4] = f2tf(qv.z * scale); QA[qa + 6] = f2tf(qv.w * scale);
        int kb = (row >> 3) * 264 + k8 * 66 + (row & 7) * 8 + kh;
        KB[kb + 0] = f2tf(kv.x); KB[kb + 2] = f2tf(kv.y);
        KB[kb + 4] = f2tf(kv.z); KB[kb + 6] = f2tf(kv.w);
        int vb = (kq >> 1) * 1064 + (row >> 3) * 66 + ((kq & 1) * 4) * 8 +
                 ((row >> 2) & 1) + 2 * (row & 3);
        VB[vb + 0]  = f2tf(vv.x); VB[vb + 8]  = f2tf(vv.y);
        VB[vb + 16] = f2tf(vv.z); VB[vb + 24] = f2tf(vv.w);
    }

    {
        int wwin = win & 255;
        int wh = wwin >> 4, ww = wwin & 15;
#pragma unroll
        for (int it = 0; it < 16; it++) {
            int e = tid + it * 256;
            int qn = e >> 6, kn = e & 63;
            int qi2 = qn >> 3, qj = qn & 7, ki = kn >> 3, kj = kn & 7;
            int rel = (qi2 - ki + 7) * 15 + (qj - kj + 7);
            float v = rpb[rel * HEADS + head];
            int gqh = wh * 8 + qi2, gqw = ww * 8 + qj;
            int gkh = wh * 8 + ki,  gkw = ww * 8 + kj;
            int rq = (gqh < 120 ? 0 : (gqh < 124 ? 1 : 2)) * 3 + (gqw < 120 ? 0 : (gqw < 124 ? 1 : 2));
            int rk = (gkh < 120 ? 0 : (gkh < 124 ? 1 : 2)) * 3 + (gkw < 120 ? 0 : (gkw < 124 ? 1 : 2));
            if (rq != rk) v -= 100.0f;
            int qtile = qn >> 4, ntile = kn >> 3;
            int ln = (qn & 7) * 4 + ((kn & 7) >> 1);
            int reg = ((qn >> 3) & 1) * 2 + (kn & 1);
            Psf[((qtile * 8 + ntile) * 32 + ln) * 4 + reg] = v;
        }
    }
    __syncthreads();

    float acc[16][4];
#pragma unroll
    for (int nt = 0; nt < 16; nt++)
#pragma unroll
        for (int i = 0; i < 4; i++) acc[nt][i] = 0.f;

#pragma unroll
    for (int k8 = 0; k8 < 4; k8++) {
        int abase = (w * 2) * 264 + k8 * 66 + lane * 2;
        uint2 q0 = *reinterpret_cast<const uint2*>(&QA[abase]);
        uint2 q1 = *reinterpret_cast<const uint2*>(&QA[abase + 264]);
#pragma unroll
        for (int nt = 0; nt < 16; nt++) {
            uint2 b = *reinterpret_cast<const uint2*>(&KB[nt * 264 + k8 * 66 + lane * 2]);
            MMA_TF32(acc[nt], q0.x, q1.x, q0.y, q1.y, b.x, b.y);
        }
    }

    const int qtile = w & 3;
    float m0 = -1e30f, m1 = -1e30f;
#pragma unroll
    for (int nt = 0; nt < 16; nt++) {
        float4 p = *reinterpret_cast<const float4*>(&Psf[((qtile * 8 + (nt & 7)) * 32 + lane) * 4]);
        acc[nt][0] += p.x; acc[nt][1] += p.y;
        acc[nt][2] += p.z; acc[nt][3] += p.w;
        m0 = fmaxf(m0, fmaxf(acc[nt][0], acc[nt][1]));
        m1 = fmaxf(m1, fmaxf(acc[nt][2], acc[nt][3]));
    }
    m0 = fmaxf(m0, __shfl_xor_sync(0xffffffffu, m0, 1));
    m0 = fmaxf(m0, __shfl_xor_sync(0xffffffffu, m0, 2));
    m1 = fmaxf(m1, __shfl_xor_sync(0xffffffffu, m1, 1));
    m1 = fmaxf(m1, __shfl_xor_sync(0xffffffffu, m1, 2));

    float l0 = 0.f, l1 = 0.f;
#pragma unroll
    for (int nt = 0; nt < 16; nt++) {
        acc[nt][0] = __expf(acc[nt][0] - m0);
        acc[nt][1] = __expf(acc[nt][1] - m0);
        acc[nt][2] = __expf(acc[nt][2] - m1);
        acc[nt][3] = __expf(acc[nt][3] - m1);
        l0 += acc[nt][0] + acc[nt][1];
        l1 += acc[nt][2] + acc[nt][3];
    }
    l0 += __shfl_xor_sync(0xffffffffu, l0, 1);
    l0 += __shfl_xor_sync(0xffffffffu, l0, 2);
    l1 += __shfl_xor_sync(0xffffffffu, l1, 1);
    l1 += __shfl_xor_sync(0xffffffffu, l1, 2);
    float inv0 = 1.0f / l0, inv1 = 1.0f / l1;

#pragma unroll
    for (int nt = 0; nt < 16; nt++)
#pragma unroll
        for (int i = 0; i < 4; i++)
            acc[nt][i] = __uint_as_float(f2tf(acc[nt][i]));

    float oacc[4][4];
#pragma unroll
    for (int n8 = 0; n8 < 4; n8++)
#pragma unroll
        for (int i = 0; i < 4; i++) oacc[n8][i] = 0.f;

    const int s0 = (lane & 28) | (t >> 1);
    const int s1 = s0 + 2;
    const bool oddt = (t & 1);
#pragma unroll
    for (int c = 0; c < 16; c++) {
        float e0 = __shfl_sync(0xffffffffu, acc[c][0], s0);
        float o0 = __shfl_sync(0xffffffffu, acc[c][1], s0);
        float e1 = __shfl_sync(0xffffffffu, acc[c][2], s0);
        float o1 = __shfl_sync(0xffffffffu, acc[c][3], s0);
        float e2 = __shfl_sync(0xffffffffu, acc[c][0], s1);
        float o2 = __shfl_sync(0xffffffffu, acc[c][1], s1);
        float e3 = __shfl_sync(0xffffffffu, acc[c][2], s1);
        float o3 = __shfl_sync(0xffffffffu, acc[c][3], s1);
        unsigned a0 = __float_as_uint(oddt ? o0 : e0);
        unsigned a1 = __float_as_uint(oddt ? o1 : e1);
        unsigned a2 = __float_as_uint(oddt ? o2 : e2);
        unsigned a3 = __float_as_uint(oddt ? o3 : e3);
#pragma unroll
        for (int n8 = 0; n8 < 4; n8++) {
            uint2 b = *reinterpret_cast<const uint2*>(&VB[n8 * 1064 + c * 66 + lane * 2]);
            MMA_TF32(oacc[n8], a0, a1, a2, a3, b.x, b.y);
        }
    }

    // write tf32-rounded so proj GEMM consumes raw bits with no cvt
    int r0 = win * 128 + w * 16 + g;
#pragma unroll
    for (int n8 = 0; n8 < 4; n8++) {
        int col = head * 32 + n8 * 8 + t * 2;
        attout[(size_t)r0 * 128 + col]           = round_tf(oacc[n8][0] * inv0);
        attout[(size_t)r0 * 128 + col + 1]       = round_tf(oacc[n8][1] * inv0);
        attout[(size_t)(r0 + 8) * 128 + col]     = round_tf(oacc[n8][2] * inv1);
        attout[(size_t)(r0 + 8) * 128 + col + 1] = round_tf(oacc[n8][3] * inv1);
    }
}

// ---------------- launch ----------------
extern "C" void kernel_launch(void* const* d_in, const int* in_sizes, int n_in,
                              void* d_out, int out_size) {
    const float* x_v    = (const float*)d_in[0];
    const float* qkv_w  = (const float*)d_in[1];
    const float* qkv_b  = (const float*)d_in[2];
    const float* proj_w = (const float*)d_in[3];
    const float* proj_b = (const float*)d_in[4];
    const float* rpb    = (const float*)d_in[5];
    const float* n1w    = (const float*)d_in[6];
    const float* n1b    = (const float*)d_in[7];
    const float* n2w    = (const float*)d_in[8];
    const float* n2b    = (const float*)d_in[9];
    const float* fc1w   = (const float*)d_in[10];
    const float* fc1b   = (const float*)d_in[11];
    const float* fc2w   = (const float*)d_in[12];
    const float* fc2b   = (const float*)d_in[13];
    float* out = (float*)d_out;

    float *qkvb, *attn, *xres, *h1;
    unsigned* wtf;
    cudaGetSymbolAddress((void**)&qkvb, g_qkv);
    cudaGetSymbolAddress((void**)&attn, g_attn);
    cudaGetSymbolAddress((void**)&xres, g_xres);
    cudaGetSymbolAddress((void**)&h1,   g_h1);
    cudaGetSymbolAddress((void**)&wtf,  g_wtf);
    float* xln = qkvb;   // reuse: qkv dead after attention

    cudaFuncSetAttribute(attn_kernel, cudaFuncAttributeMaxDynamicSharedMemorySize, SMEM_ATTN);
    cudaFuncSetAttribute(mma_gemm<0>, cudaFuncAttributeMaxDynamicSharedMemorySize, GEMM_SMEM);
    cudaFuncSetAttribute(mma_gemm<2>, cudaFuncAttributeMaxDynamicSharedMemorySize, GEMM_SMEM);
    cudaFuncSetAttribute(mma_gemm_ln<1>, cudaFuncAttributeMaxDynamicSharedMemorySize, GEMM_SMEM);
    cudaFuncSetAttribute(mma_gemm_ln<3>, cudaFuncAttributeMaxDynamicSharedMemorySize, GEMM_SMEM);

    // 0. convert weights to tf32 once
    cvt_weights<<<768, 256>>>(qkv_w, proj_w, fc1w, fc2w, wtf);
    // 1. qkv = gather(x_v) @ qkv_w^T + b
    mma_gemm<0><<<dim3(6, 1024), 256, GEMM_SMEM>>>(x_v, wtf, qkv_b, qkvb, 384, 128);
    // 2. tensor-core window attention (writes tf32-rounded)
    attn_kernel<<<dim3(1024, HEADS), 256, SMEM_ATTN>>>(qkvb, rpb, attn);
    // 3. proj + scatter + residual + LN2 (xres full, xln rounded)
    mma_gemm_ln<1><<<dim3(1, 2048), 256, GEMM_SMEM>>>(attn, wtf + 49152, proj_b, x_v,
                                                      xres, xln, n2w, n2b, 128);
    // 4. fc1 + gelu (h1 rounded)
    mma_gemm<2><<<dim3(8, 1024), 256, GEMM_SMEM>>>(xln, wtf + 65536, fc1b, h1, 512, 128);
    // 5. fc2 + residual + LN1 -> final output (full precision)
    mma_gemm_ln<3><<<dim3(1, 2048), 256, GEMM_SMEM>>>(h1, wtf + 131072, fc2b, xres,
                                                      nullptr, out, n1w, n1b, 512);
}

// round 7
// speedup vs baseline: 1.6570x; 1.1524x over previous
#include <cuda_runtime.h>
#include <math.h>

// ---------------- problem constants ----------------
#define M_TOT 131072
#define CDIM  128
#define HEADS 4

// ---------------- scratch ----------------
__device__ float g_qkv [(size_t)M_TOT * 3 * CDIM];
__device__ float g_attn[(size_t)M_TOT * CDIM];
__device__ float g_xres[(size_t)M_TOT * CDIM];
__device__ unsigned g_wtf[196608];   // tf32 weights: qkv|proj|fc1|fc2

__device__ __forceinline__ int perm_row(int r) {
    int b_ = r >> 7, tt = r & 127;
    int b = b_ >> 8, w = b_ & 255;
    int wh = w >> 4, ww = w & 15;
    int t = tt >> 6, n = tt & 63;
    int i = n >> 3, j = n & 7;
    int oh = (wh * 8 + i + 4) & 127;
    int ow = (ww * 8 + j + 4) & 127;
    return (b * 2 + t) * 16384 + oh * 128 + ow;
}

__device__ __forceinline__ unsigned f2tf(float f) {
    unsigned u;
    asm("cvt.rna.tf32.f32 %0, %1;" : "=r"(u) : "f"(f));
    return u;
}
__device__ __forceinline__ float round_tf(float f) { return __uint_as_float(f2tf(f)); }

#define MMA_TF32(d, a0, a1, a2, a3, b0, b1)                                            \
    asm volatile(                                                                      \
        "mma.sync.aligned.m16n8k8.row.col.f32.tf32.tf32.f32 "                          \
        "{%0,%1,%2,%3},{%4,%5,%6,%7},{%8,%9},{%0,%1,%2,%3};"                           \
        : "+f"(d[0]), "+f"(d[1]), "+f"(d[2]), "+f"(d[3])                               \
        : "r"(a0), "r"(a1), "r"(a2), "r"(a3), "r"(b0), "r"(b1))

#define GEMM_SMEM (12672 * 4)

// ---------------- weight pre-conversion ----------------
__global__ void cvt_weights(const float* __restrict__ qkv_w, const float* __restrict__ proj_w,
                            const float* __restrict__ fc1_w, const float* __restrict__ fc2_w,
                            unsigned* __restrict__ wtf) {
    int i = blockIdx.x * 256 + threadIdx.x;
    float v;
    if (i < 49152) v = qkv_w[i];
    else if (i < 65536) v = proj_w[i - 49152];
    else if (i < 131072) v = fc1_w[i - 65536];
    else v = fc2_w[i - 131072];
    wtf[i] = f2tf(v);
}

// ---------------- tf32 GEMM, BM=128 BN=64, double-buffered (qkv only) ----------------
__global__ __launch_bounds__(256) void mma_gemm(
    const float* __restrict__ A, const unsigned* __restrict__ Bt,
    const float* __restrict__ bias, float* __restrict__ out, int Nn, int K) {
    extern __shared__ unsigned sm[];
    unsigned* As = sm;            // 2 x 4224
    unsigned* Bs = sm + 8448;     // 2 x 2112

    const int tid = threadIdx.x;
    const int lane = tid & 31;
    const int wid = tid >> 5;
    const int wm = wid >> 1, wn = wid & 1;
    const int g = lane >> 2, t = lane & 3;
    const int bm = blockIdx.y * 128, bn = blockIdx.x * 64;

    int aKq[4], aSrc[4], aSts[4];
#pragma unroll
    for (int it = 0; it < 4; it++) {
        int c = tid + it * 256;
        int row = c >> 3, kq = c & 7;
        aKq[it] = kq;
        aSrc[it] = perm_row(bm + row);
        aSts[it] = ((row >> 4) * 2 + ((row >> 3) & 1)) * 264 + (kq >> 1) * 66 + (row & 7) * 8 + (kq & 1);
    }
    int bN[2], bKq[2], bSts[2];
#pragma unroll
    for (int it = 0; it < 2; it++) {
        int c = tid + it * 256;
        int n = c >> 3, kq = c & 7;
        bN[it] = bn + n; bKq[it] = kq;
        bSts[it] = (n >> 3) * 264 + (kq >> 1) * 66 + (n & 7) * 8 + (kq & 1);
    }

    float acc[2][4][4];
#pragma unroll
    for (int mi = 0; mi < 2; mi++)
#pragma unroll
        for (int ni = 0; ni < 4; ni++)
#pragma unroll
            for (int c = 0; c < 4; c++) acc[mi][ni][c] = 0.f;

    float4 av[4];
    uint4 bv[2];
#pragma unroll
    for (int it = 0; it < 4; it++)
        av[it] = *reinterpret_cast<const float4*>(A + (size_t)aSrc[it] * K + aKq[it] * 4);
#pragma unroll
    for (int it = 0; it < 2; it++)
        bv[it] = *reinterpret_cast<const uint4*>(Bt + (size_t)bN[it] * K + bKq[it] * 4);

    int p = 0;
    for (int kt = 0; kt < K; kt += 32) {
        unsigned* Ap = As + p * 4224;
        unsigned* Bp = Bs + p * 2112;
#pragma unroll
        for (int it = 0; it < 4; it++) {
            Ap[aSts[it] + 0] = f2tf(av[it].x);
            Ap[aSts[it] + 2] = f2tf(av[it].y);
            Ap[aSts[it] + 4] = f2tf(av[it].z);
            Ap[aSts[it] + 6] = f2tf(av[it].w);
        }
#pragma unroll
        for (int it = 0; it < 2; it++) {
            Bp[bSts[it] + 0] = bv[it].x;
            Bp[bSts[it] + 2] = bv[it].y;
            Bp[bSts[it] + 4] = bv[it].z;
            Bp[bSts[it] + 6] = bv[it].w;
        }
        __syncthreads();
        if (kt + 32 < K) {
#pragma unroll
            for (int it = 0; it < 4; it++)
                av[it] = *reinterpret_cast<const float4*>(A + (size_t)aSrc[it] * K + kt + 32 + aKq[it] * 4);
#pragma unroll
            for (int it = 0; it < 2; it++)
                bv[it] = *reinterpret_cast<const uint4*>(Bt + (size_t)bN[it] * K + kt + 32 + bKq[it] * 4);
        }
#pragma unroll
        for (int k8 = 0; k8 < 4; k8++) {
            unsigned a[2][4], b[4][2];
#pragma unroll
            for (int mi = 0; mi < 2; mi++) {
                int base = ((wm * 2 + mi) * 2) * 264 + k8 * 66 + lane * 2;
                uint2 q0 = *reinterpret_cast<const uint2*>(&Ap[base]);
                uint2 q1 = *reinterpret_cast<const uint2*>(&Ap[base + 264]);
                a[mi][0] = q0.x; a[mi][2] = q0.y;
                a[mi][1] = q1.x; a[mi][3] = q1.y;
            }
#pragma unroll
            for (int ni = 0; ni < 4; ni++) {
                uint2 q = *reinterpret_cast<const uint2*>(&Bp[(wn * 4 + ni) * 264 + k8 * 66 + lane * 2]);
                b[ni][0] = q.x; b[ni][1] = q.y;
            }
#pragma unroll
            for (int mi = 0; mi < 2; mi++)
#pragma unroll
                for (int ni = 0; ni < 4; ni++)
                    MMA_TF32(acc[mi][ni], a[mi][0], a[mi][1], a[mi][2], a[mi][3],
                             b[ni][0], b[ni][1]);
        }
        p ^= 1;
    }

#pragma unroll
    for (int mi = 0; mi < 2; mi++) {
        int r0 = bm + wm * 32 + mi * 16 + g;
#pragma unroll
        for (int rh = 0; rh < 2; rh++) {
            int r = r0 + rh * 8;
#pragma unroll
            for (int ni = 0; ni < 4; ni++) {
                int c0 = bn + wn * 32 + ni * 8 + t * 2;
#pragma unroll
                for (int ch = 0; ch < 2; ch++) {
                    out[(size_t)r * Nn + c0 + ch] = acc[mi][ni][rh * 2 + ch] + bias[c0 + ch];
                }
            }
        }
    }
}

// ---------------- proj GEMM + scatter + residual + LN2, BM=64 BN=128 ----------------
__global__ __launch_bounds__(256) void mma_gemm_ln(
    const float* __restrict__ A, const unsigned* __restrict__ Bt,
    const float* __restrict__ bias, const float* __restrict__ res,
    float* __restrict__ aux, float* __restrict__ dst,
    const float* __restrict__ gw, const float* __restrict__ bw, int K) {
    extern __shared__ unsigned sm[];
    unsigned* As = sm;            // 2 x 2112
    unsigned* Bs = sm + 4224;     // 2 x 4224
    __shared__ float smS[64][4], smQ[64][4];

    const int tid = threadIdx.x;
    const int lane = tid & 31;
    const int wid = tid >> 5;
    const int wm = wid >> 2, wn = wid & 3;
    const int g = lane >> 2, t = lane & 3;
    const int bm = blockIdx.y * 64;

    int aKq[2], aSrc[2], aSts[2];
#pragma unroll
    for (int it = 0; it < 2; it++) {
        int c = tid + it * 256;
        int row = c >> 3, kq = c & 7;
        aKq[it] = kq; aSrc[it] = bm + row;
        aSts[it] = ((row >> 4) * 2 + ((row >> 3) & 1)) * 264 + (kq >> 1) * 66 + (row & 7) * 8 + (kq & 1);
    }
    int bN[4], bKq[4], bSts[4];
#pragma unroll
    for (int it = 0; it < 4; it++) {
        int c = tid + it * 256;
        int n = c >> 3, kq = c & 7;
        bN[it] = n; bKq[it] = kq;
        bSts[it] = (n >> 3) * 264 + (kq >> 1) * 66 + (n & 7) * 8 + (kq & 1);
    }

    float acc[2][4][4];
#pragma unroll
    for (int mi = 0; mi < 2; mi++)
#pragma unroll
        for (int ni = 0; ni < 4; ni++)
#pragma unroll
            for (int c = 0; c < 4; c++) acc[mi][ni][c] = 0.f;

    uint4 av[2], bv[4];
#pragma unroll
    for (int it = 0; it < 2; it++)
        av[it] = *reinterpret_cast<const uint4*>(A + (size_t)aSrc[it] * K + aKq[it] * 4);
#pragma unroll
    for (int it = 0; it < 4; it++)
        bv[it] = *reinterpret_cast<const uint4*>(Bt + (size_t)bN[it] * K + bKq[it] * 4);

    int p = 0;
    for (int kt = 0; kt < K; kt += 32) {
        unsigned* Ap = As + p * 2112;
        unsigned* Bp = Bs + p * 4224;
#pragma unroll
        for (int it = 0; it < 2; it++) {
            Ap[aSts[it] + 0] = av[it].x;
            Ap[aSts[it] + 2] = av[it].y;
            Ap[aSts[it] + 4] = av[it].z;
            Ap[aSts[it] + 6] = av[it].w;
        }
#pragma unroll
        for (int it = 0; it < 4; it++) {
            Bp[bSts[it] + 0] = bv[it].x;
            Bp[bSts[it] + 2] = bv[it].y;
            Bp[bSts[it] + 4] = bv[it].z;
            Bp[bSts[it] + 6] = bv[it].w;
        }
        __syncthreads();
        if (kt + 32 < K) {
#pragma unroll
            for (int it = 0; it < 2; it++)
                av[it] = *reinterpret_cast<const uint4*>(A + (size_t)aSrc[it] * K + kt + 32 + aKq[it] * 4);
#pragma unroll
            for (int it = 0; it < 4; it++)
                bv[it] = *reinterpret_cast<const uint4*>(Bt + (size_t)bN[it] * K + kt + 32 + bKq[it] * 4);
        }
#pragma unroll
        for (int k8 = 0; k8 < 4; k8++) {
            unsigned a[2][4], b[4][2];
#pragma unroll
            for (int mi = 0; mi < 2; mi++) {
                int base = ((wm * 2 + mi) * 2) * 264 + k8 * 66 + lane * 2;
                uint2 q0 = *reinterpret_cast<const uint2*>(&Ap[base]);
                uint2 q1 = *reinterpret_cast<const uint2*>(&Ap[base + 264]);
                a[mi][0] = q0.x; a[mi][2] = q0.y;
                a[mi][1] = q1.x; a[mi][3] = q1.y;
            }
#pragma unroll
            for (int ni = 0; ni < 4; ni++) {
                uint2 q = *reinterpret_cast<const uint2*>(&Bp[(wn * 4 + ni) * 264 + k8 * 66 + lane * 2]);
                b[ni][0] = q.x; b[ni][1] = q.y;
            }
#pragma unroll
            for (int mi = 0; mi < 2; mi++)
#pragma unroll
                for (int ni = 0; ni < 4; ni++)
                    MMA_TF32(acc[mi][ni], a[mi][0], a[mi][1], a[mi][2], a[mi][3],
                             b[ni][0], b[ni][1]);
        }
        p ^= 1;
    }

#pragma unroll
    for (int mi = 0; mi < 2; mi++) {
#pragma unroll
        for (int rh = 0; rh < 2; rh++) {
            int lrow = (wm * 2 + mi) * 16 + g + rh * 8;
            int r = bm + lrow;
            int xrow = perm_row(r);
            float v[8];
            float s = 0.f, q = 0.f;
#pragma unroll
            for (int ni = 0; ni < 4; ni++) {
                int c = wn * 32 + ni * 8 + t * 2;
#pragma unroll
                for (int ch = 0; ch < 2; ch++) {
                    float x = acc[mi][ni][rh * 2 + ch] + bias[c + ch] +
                              res[(size_t)xrow * 128 + c + ch];
                    aux[(size_t)xrow * 128 + c + ch] = x;
                    v[ni * 2 + ch] = x;
                    s += x; q += x * x;
                }
            }
            s += __shfl_xor_sync(0xffffffffu, s, 1);
            s += __shfl_xor_sync(0xffffffffu, s, 2);
            q += __shfl_xor_sync(0xffffffffu, q, 1);
            q += __shfl_xor_sync(0xffffffffu, q, 2);
            if (t == 0) { smS[lrow][wn] = s; smQ[lrow][wn] = q; }
            __syncthreads();
            float S = smS[lrow][0] + smS[lrow][1] + smS[lrow][2] + smS[lrow][3];
            float Q = smQ[lrow][0] + smQ[lrow][1] + smQ[lrow][2] + smQ[lrow][3];
            float mu = S * (1.f / 128.f);
            float var = Q * (1.f / 128.f) - mu * mu;
            float rs = rsqrtf(var + 1e-5f);
#pragma unroll
            for (int ni = 0; ni < 4; ni++) {
                int c = wn * 32 + ni * 8 + t * 2;
#pragma unroll
                for (int ch = 0; ch < 2; ch++) {
                    dst[(size_t)xrow * 128 + c + ch] =
                        round_tf((v[ni * 2 + ch] - mu) * rs * gw[c + ch] + bw[c + ch]);
                }
            }
        }
    }
}

// ---------------- fused MLP: fc1 + gelu + fc2 + residual + LN1 ----------------
// 512 threads, BM=128 rows. xln tile held in smem; hidden in 8 chunks of 64.
// smem (unsigned units): XA 0(16896) | W1 16896(8448) | W2 25344(8448) | H 33792(8448)
#define MLP_SMEM (42240 * 4)
__global__ __launch_bounds__(512) void mlp_kernel(
    const float* __restrict__ xln, const unsigned* __restrict__ W1g4_,
    const unsigned* __restrict__ W2g4_,
    const float* __restrict__ b1, const float* __restrict__ b2,
    const float* __restrict__ res, float* __restrict__ out,
    const float* __restrict__ gw, const float* __restrict__ bw) {
    extern __shared__ unsigned sm[];
    unsigned* XA = sm;
    unsigned* W1 = sm + 16896;
    unsigned* W2 = sm + 25344;
    unsigned* HH = sm + 33792;
    __shared__ float smS[128][4], smQ[128][4];

    const uint4* W1g = reinterpret_cast<const uint4*>(W1g4_);
    const uint4* W2g = reinterpret_cast<const uint4*>(W2g4_);

    const int tid = threadIdx.x;
    const int lane = tid & 31;
    const int wid = tid >> 5;
    const int wm = wid >> 2, wn = wid & 3;   // 4m x 4n
    const int g = lane >> 2, t = lane & 3;
    const int bm = blockIdx.x * 128;

    // ---- load XA (128 rows x 128 k, A-frag layout, raw tf32 bits) ----
#pragma unroll
    for (int it = 0; it < 8; it++) {
        int c = tid + it * 512;              // 0..4095
        int row = c >> 5, kq = c & 31;
        uint4 v = *reinterpret_cast<const uint4*>(xln + (size_t)(bm + row) * 128 + kq * 4);
        int sts = ((row >> 4) * 2 + ((row >> 3) & 1)) * 1056 + (kq >> 1) * 66 + (row & 7) * 8 + (kq & 1);
        XA[sts + 0] = v.x; XA[sts + 2] = v.y; XA[sts + 4] = v.z; XA[sts + 6] = v.w;
    }

    // per-thread W1/W2 load coords
    int w1n, w1kq, w1sts, w2n, w2klq, w2sts;
    int w1src[4], w2src[4], w1st[4], w2st[4];
#pragma unroll
    for (int it = 0; it < 4; it++) {
        int e = tid + it * 512;              // 0..2047
        int n = e >> 5, kq = e & 31;         // W1: 64 rows x 32 quads
        w1src[it] = n * 32 + kq;             // + chunk*2048
        w1st[it] = (n >> 3) * 1056 + (kq >> 1) * 66 + (n & 7) * 8 + (kq & 1);
        int n2 = e >> 4, klq = e & 15;       // W2: 128 rows x 16 quads
        w2src[it] = n2 * 128 + klq;          // + chunk*16
        w2st[it] = (n2 >> 3) * 528 + (klq >> 1) * 66 + (n2 & 7) * 8 + (klq & 1);
    }

    // preload W1 chunk 0
    {
        uint4 v[4];
#pragma unroll
        for (int it = 0; it < 4; it++) v[it] = W1g[w1src[it]];
#pragma unroll
        for (int it = 0; it < 4; it++) {
            W1[w1st[it] + 0] = v[it].x; W1[w1st[it] + 2] = v[it].y;
            W1[w1st[it] + 4] = v[it].z; W1[w1st[it] + 6] = v[it].w;
        }
    }
    __syncthreads();

    float acco[2][4][4];
#pragma unroll
    for (int mi = 0; mi < 2; mi++)
#pragma unroll
        for (int ni = 0; ni < 4; ni++)
#pragma unroll
            for (int c = 0; c < 4; c++) acco[mi][ni][c] = 0.f;

    for (int c = 0; c < 8; c++) {
        // prefetch W2 chunk c (consumed after sync below)
        uint4 w2v[4];
#pragma unroll
        for (int it = 0; it < 4; it++) w2v[it] = W2g[w2src[it] + c * 16];

        // ---- GEMM1: S(128x64) = XA @ W1^T ----
        float accs[2][2][4];
#pragma unroll
        for (int mi = 0; mi < 2; mi++)
#pragma unroll
            for (int ni = 0; ni < 2; ni++)
#pragma unroll
                for (int q = 0; q < 4; q++) accs[mi][ni][q] = 0.f;
#pragma unroll
        for (int k8 = 0; k8 < 16; k8++) {
            unsigned a[2][4], b[2][2];
#pragma unroll
            for (int mi = 0; mi < 2; mi++) {
                int base = ((wm * 2 + mi) * 2) * 1056 + k8 * 66 + lane * 2;
                uint2 q0 = *reinterpret_cast<const uint2*>(&XA[base]);
                uint2 q1 = *reinterpret_cast<const uint2*>(&XA[base + 1056]);
                a[mi][0] = q0.x; a[mi][2] = q0.y;
                a[mi][1] = q1.x; a[mi][3] = q1.y;
            }
#pragma unroll
            for (int ni = 0; ni < 2; ni++) {
                uint2 q = *reinterpret_cast<const uint2*>(&W1[(wn * 2 + ni) * 1056 + k8 * 66 + lane * 2]);
                b[ni][0] = q.x; b[ni][1] = q.y;
            }
#pragma unroll
            for (int mi = 0; mi < 2; mi++)
#pragma unroll
                for (int ni = 0; ni < 2; ni++)
                    MMA_TF32(accs[mi][ni], a[mi][0], a[mi][1], a[mi][2], a[mi][3],
                             b[ni][0], b[ni][1]);
        }

        // store W2 stage
#pragma unroll
        for (int it = 0; it < 4; it++) {
            W2[w2st[it] + 0] = w2v[it].x; W2[w2st[it] + 2] = w2v[it].y;
            W2[w2st[it] + 4] = w2v[it].z; W2[w2st[it] + 6] = w2v[it].w;
        }

        // gelu + bias1, write H in A-frag layout
#pragma unroll
        for (int mi = 0; mi < 2; mi++) {
            int rgR = (wm * 2 + mi) * 2;
#pragma unroll
            for (int ni = 0; ni < 2; ni++) {
                int kl0 = wn * 16 + ni * 8 + t * 2;
                float bb0 = b1[c * 64 + kl0], bb1 = b1[c * 64 + kl0 + 1];
#pragma unroll
                for (int rh = 0; rh < 2; rh++) {
#pragma unroll
                    for (int ch = 0; ch < 2; ch++) {
                        float v = accs[mi][ni][rh * 2 + ch] + (ch ? bb1 : bb0);
                        v = 0.5f * v * (1.0f + erff(v * 0.7071067811865475f));
                        int k = kl0 + ch;
                        int addr = (rgR + rh) * 528 + (k >> 3) * 66 + g * 8 +
                                   ((k >> 2) & 1) + (k & 3) * 2;
                        HH[addr] = f2tf(v);
                    }
                }
            }
        }
        __syncthreads();

        // prefetch W1 chunk c+1
        uint4 w1v[4];
        if (c < 7) {
#pragma unroll
            for (int it = 0; it < 4; it++) w1v[it] = W1g[w1src[it] + (c + 1) * 2048];
        }

        // ---- GEMM2: out(128x128) += H @ W2^T ----
#pragma unroll
        for (int k8 = 0; k8 < 8; k8++) {
            unsigned a[2][4], b[4][2];
#pragma unroll
            for (int mi = 0; mi < 2; mi++) {
                int base = ((wm * 2 + mi) * 2) * 528 + k8 * 66 + lane * 2;
                uint2 q0 = *reinterpret_cast<const uint2*>(&HH[base]);
                uint2 q1 = *reinterpret_cast<const uint2*>(&HH[base + 528]);
                a[mi][0] = q0.x; a[mi][2] = q0.y;
                a[mi][1] = q1.x; a[mi][3] = q1.y;
            }
#pragma unroll
            for (int ni = 0; ni < 4; ni++) {
                uint2 q = *reinterpret_cast<const uint2*>(&W2[(wn * 4 + ni) * 528 + k8 * 66 + lane * 2]);
                b[ni][0] = q.x; b[ni][1] = q.y;
            }
#pragma unroll
            for (int mi = 0; mi < 2; mi++)
#pragma unroll
                for (int ni = 0; ni < 4; ni++)
                    MMA_TF32(acco[mi][ni], a[mi][0], a[mi][1], a[mi][2], a[mi][3],
                             b[ni][0], b[ni][1]);
        }

        if (c < 7) {
#pragma unroll
            for (int it = 0; it < 4; it++) {
                W1[w1st[it] + 0] = w1v[it].x; W1[w1st[it] + 2] = w1v[it].y;
                W1[w1st[it] + 4] = w1v[it].z; W1[w1st[it] + 6] = w1v[it].w;
            }
        }
        __syncthreads();
    }

    // ---- epilogue: bias2 + residual + LN1 -> out ----
#pragma unroll
    for (int mi = 0; mi < 2; mi++) {
#pragma unroll
        for (int rh = 0; rh < 2; rh++) {
            int lrow = wm * 32 + mi * 16 + g + rh * 8;
            int r = bm + lrow;
            float v[8];
            float s = 0.f, q = 0.f;
#pragma unroll
            for (int ni = 0; ni < 4; ni++) {
                int cc = wn * 32 + ni * 8 + t * 2;
#pragma unroll
                for (int ch = 0; ch < 2; ch++) {
                    float x = acco[mi][ni][rh * 2 + ch] + b2[cc + ch] +
                              res[(size_t)r * 128 + cc + ch];
                    v[ni * 2 + ch] = x;
                    s += x; q += x * x;
                }
            }
            s += __shfl_xor_sync(0xffffffffu, s, 1);
            s += __shfl_xor_sync(0xffffffffu, s, 2);
            q += __shfl_xor_sync(0xffffffffu, q, 1);
            q += __shfl_xor_sync(0xffffffffu, q, 2);
            if (t == 0) { smS[lrow][wn] = s; smQ[lrow][wn] = q; }
            __syncthreads();
            float S = smS[lrow][0] + smS[lrow][1] + smS[lrow][2] + smS[lrow][3];
            float Q = smQ[lrow][0] + smQ[lrow][1] + smQ[lrow][2] + smQ[lrow][3];
            float mu = S * (1.f / 128.f);
            float var = Q * (1.f / 128.f) - mu * mu;
            float rs = rsqrtf(var + 1e-5f);
#pragma unroll
            for (int ni = 0; ni < 4; ni++) {
                int cc = wn * 32 + ni * 8 + t * 2;
#pragma unroll
                for (int ch = 0; ch < 2; ch++) {
                    out[(size_t)r * 128 + cc + ch] =
                        (v[ni * 2 + ch] - mu) * rs * gw[cc + ch] + bw[cc + ch];
                }
            }
        }
    }
}

// ---------------- tensor-core window attention ----------------
#define SM_QA 0
#define SM_KB 4224
#define SM_VB 8448
#define SM_PS 12704
#define SMEM_ATTN ((12704 + 4096) * 4)

__global__ __launch_bounds__(256) void attn_kernel(const float* __restrict__ qkv,
                                                   const float* __restrict__ rpb,
                                                   float* __restrict__ attout) {
    extern __shared__ unsigned sm[];
    unsigned* QA = sm + SM_QA;
    unsigned* KB = sm + SM_KB;
    unsigned* VB = sm + SM_VB;
    float* Psf = (float*)(sm + SM_PS);

    const int win = blockIdx.x, head = blockIdx.y;
    const int tid = threadIdx.x;
    const int lane = tid & 31, w = tid >> 5;
    const int g = lane >> 2, t = lane & 3;
    const float scale = 0.17677669529663687f;

#pragma unroll
    for (int it = 0; it < 4; it++) {
        int c = tid + it * 256;
        int row = c >> 3, kq = c & 7;
        size_t base = ((size_t)(win * 128 + row)) * 384 + head * 32 + kq * 4;
        float4 qv = *reinterpret_cast<const float4*>(qkv + base);
        float4 kv = *reinterpret_cast<const float4*>(qkv + base + 128);
        float4 vv = *reinterpret_cast<const float4*>(qkv + base + 256);
        int k8 = kq >> 1, kh = kq & 1;
        int qa = ((row >> 4) * 2 + ((row >> 3) & 1)) * 264 + k8 * 66 + (row & 7) * 8 + kh;
        QA[qa + 0] = f2tf(qv.x * scale); QA[qa + 2] = f2tf(qv.y * scale);
        QA[qa + 4] = f2tf(qv.z * scale); QA[qa + 6] = f2tf(qv.w * scale);
        int kb = (row >> 3) * 264 + k8 * 66 + (row & 7) * 8 + kh;
        KB[kb + 0] = f2tf(kv.x); KB[kb + 2] = f2tf(kv.y);
        KB[kb + 4] = f2tf(kv.z); KB[kb + 6] = f2tf(kv.w);
        int vb = (kq >> 1) * 1064 + (row >> 3) * 66 + ((kq & 1) * 4) * 8 +
                 ((row >> 2) & 1) + 2 * (row & 3);
        VB[vb + 0]  = f2tf(vv.x); VB[vb + 8]  = f2tf(vv.y);
        VB[vb + 16] = f2tf(vv.z); VB[vb + 24] = f2tf(vv.w);
    }

    {
        int wwin = win & 255;
        int wh = wwin >> 4, ww = wwin & 15;
#pragma unroll
        for (int it = 0; it < 16; it++) {
            int e = tid + it * 256;
            int qn = e >> 6, kn = e & 63;
            int qi2 = qn >> 3, qj = qn & 7, ki = kn >> 3, kj = kn & 7;
            int rel = (qi2 - ki + 7) * 15 + (qj - kj + 7);
            float v = rpb[rel * HEADS + head];
            int gqh = wh * 8 + qi2, gqw = ww * 8 + qj;
            int gkh = wh * 8 + ki,  gkw = ww * 8 + kj;
            int rq = (gqh < 120 ? 0 : (gqh < 124 ? 1 : 2)) * 3 + (gqw < 120 ? 0 : (gqw < 124 ? 1 : 2));
            int rk = (gkh < 120 ? 0 : (gkh < 124 ? 1 : 2)) * 3 + (gkw < 120 ? 0 : (gkw < 124 ? 1 : 2));
            if (rq != rk) v -= 100.0f;
            int qtile = qn >> 4, ntile = kn >> 3;
            int ln = (qn & 7) * 4 + ((kn & 7) >> 1);
            int reg = ((qn >> 3) & 1) * 2 + (kn & 1);
            Psf[((qtile * 8 + ntile) * 32 + ln) * 4 + reg] = v;
        }
    }
    __syncthreads();

    float acc[16][4];
#pragma unroll
    for (int nt = 0; nt < 16; nt++)
#pragma unroll
        for (int i = 0; i < 4; i++) acc[nt][i] = 0.f;

#pragma unroll
    for (int k8 = 0; k8 < 4; k8++) {
        int abase = (w * 2) * 264 + k8 * 66 + lane * 2;
        uint2 q0 = *reinterpret_cast<const uint2*>(&QA[abase]);
        uint2 q1 = *reinterpret_cast<const uint2*>(&QA[abase + 264]);
#pragma unroll
        for (int nt = 0; nt < 16; nt++) {
            uint2 b = *reinterpret_cast<const uint2*>(&KB[nt * 264 + k8 * 66 + lane * 2]);
            MMA_TF32(acc[nt], q0.x, q1.x, q0.y, q1.y, b.x, b.y);
        }
    }

    const int qtile = w & 3;
    float m0 = -1e30f, m1 = -1e30f;
#pragma unroll
    for (int nt = 0; nt < 16; nt++) {
        float4 p = *reinterpret_cast<const float4*>(&Psf[((qtile * 8 + (nt & 7)) * 32 + lane) * 4]);
        acc[nt][0] += p.x; acc[nt][1] += p.y;
        acc[nt][2] += p.z; acc[nt][3] += p.w;
        m0 = fmaxf(m0, fmaxf(acc[nt][0], acc[nt][1]));
        m1 = fmaxf(m1, fmaxf(acc[nt][2], acc[nt][3]));
    }
    m0 = fmaxf(m0, __shfl_xor_sync(0xffffffffu, m0, 1));
    m0 = fmaxf(m0, __shfl_xor_sync(0xffffffffu, m0, 2));
    m1 = fmaxf(m1, __shfl_xor_sync(0xffffffffu, m1, 1));
    m1 = fmaxf(m1, __shfl_xor_sync(0xffffffffu, m1, 2));

    float l0 = 0.f, l1 = 0.f;
#pragma unroll
    for (int nt = 0; nt < 16; nt++) {
        acc[nt][0] = __expf(acc[nt][0] - m0);
        acc[nt][1] = __expf(acc[nt][1] - m0);
        acc[nt][2] = __expf(acc[nt][2] - m1);
        acc[nt][3] = __expf(acc[nt][3] - m1);
        l0 += acc[nt][0] + acc[nt][1];
        l1 += acc[nt][2] + acc[nt][3];
    }
    l0 += __shfl_xor_sync(0xffffffffu, l0, 1);
    l0 += __shfl_xor_sync(0xffffffffu, l0, 2);
    l1 += __shfl_xor_sync(0xffffffffu, l1, 1);
    l1 += __shfl_xor_sync(0xffffffffu, l1, 2);
    float inv0 = 1.0f / l0, inv1 = 1.0f / l1;

#pragma unroll
    for (int nt = 0; nt < 16; nt++)
#pragma unroll
        for (int i = 0; i < 4; i++)
            acc[nt][i] = __uint_as_float(f2tf(acc[nt][i]));

    float oacc[4][4];
#pragma unroll
    for (int n8 = 0; n8 < 4; n8++)
#pragma unroll
        for (int i = 0; i < 4; i++) oacc[n8][i] = 0.f;

    const int s0 = (lane & 28) | (t >> 1);
    const int s1 = s0 + 2;
    const bool oddt = (t & 1);
#pragma unroll
    for (int c = 0; c < 16; c++) {
        float e0 = __shfl_sync(0xffffffffu, acc[c][0], s0);
        float o0 = __shfl_sync(0xffffffffu, acc[c][1], s0);
        float e1 = __shfl_sync(0xffffffffu, acc[c][2], s0);
        float o1 = __shfl_sync(0xffffffffu, acc[c][3], s0);
        float e2 = __shfl_sync(0xffffffffu, acc[c][0], s1);
        float o2 = __shfl_sync(0xffffffffu, acc[c][1], s1);
        float e3 = __shfl_sync(0xffffffffu, acc[c][2], s1);
        float o3 = __shfl_sync(0xffffffffu, acc[c][3], s1);
        unsigned a0 = __float_as_uint(oddt ? o0 : e0);
        unsigned a1 = __float_as_uint(oddt ? o1 : e1);
        unsigned a2 = __float_as_uint(oddt ? o2 : e2);
        unsigned a3 = __float_as_uint(oddt ? o3 : e3);
#pragma unroll
        for (int n8 = 0; n8 < 4; n8++) {
            uint2 b = *reinterpret_cast<const uint2*>(&VB[n8 * 1064 + c * 66 + lane * 2]);
            MMA_TF32(oacc[n8], a0, a1, a2, a3, b.x, b.y);
        }
    }

    int r0 = win * 128 + w * 16 + g;
#pragma unroll
    for (int n8 = 0; n8 < 4; n8++) {
        int col = head * 32 + n8 * 8 + t * 2;
        attout[(size_t)r0 * 128 + col]           = round_tf(oacc[n8][0] * inv0);
        attout[(size_t)r0 * 128 + col + 1]       = round_tf(oacc[n8][1] * inv0);
        attout[(size_t)(r0 + 8) * 128 + col]     = round_tf(oacc[n8][2] * inv1);
        attout[(size_t)(r0 + 8) * 128 + col + 1] = round_tf(oacc[n8][3] * inv1);
    }
}

// ---------------- launch ----------------
extern "C" void kernel_launch(void* const* d_in, const int* in_sizes, int n_in,
                              void* d_out, int out_size) {
    const float* x_v    = (const float*)d_in[0];
    const float* qkv_w  = (const float*)d_in[1];
    const float* qkv_b  = (const float*)d_in[2];
    const float* proj_w = (const float*)d_in[3];
    const float* proj_b = (const float*)d_in[4];
    const float* rpb    = (const float*)d_in[5];
    const float* n1w    = (const float*)d_in[6];
    const float* n1b    = (const float*)d_in[7];
    const float* n2w    = (const float*)d_in[8];
    const float* n2b    = (const float*)d_in[9];
    const float* fc1w   = (const float*)d_in[10];
    const float* fc1b   = (const float*)d_in[11];
    const float* fc2w   = (const float*)d_in[12];
    const float* fc2b   = (const float*)d_in[13];
    float* out = (float*)d_out;

    float *qkvb, *attn, *xres;
    unsigned* wtf;
    cudaGetSymbolAddress((void**)&qkvb, g_qkv);
    cudaGetSymbolAddress((void**)&attn, g_attn);
    cudaGetSymbolAddress((void**)&xres, g_xres);
    cudaGetSymbolAddress((void**)&wtf,  g_wtf);
    float* xln = qkvb;   // reuse: qkv dead after attention

    cudaFuncSetAttribute(attn_kernel, cudaFuncAttributeMaxDynamicSharedMemorySize, SMEM_ATTN);
    cudaFuncSetAttribute(mma_gemm, cudaFuncAttributeMaxDynamicSharedMemorySize, GEMM_SMEM);
    cudaFuncSetAttribute(mma_gemm_ln, cudaFuncAttributeMaxDynamicSharedMemorySize, GEMM_SMEM);
    cudaFuncSetAttribute(mlp_kernel, cudaFuncAttributeMaxDynamicSharedMemorySize, MLP_SMEM);

    // 0. convert weights to tf32 once
    cvt_weights<<<768, 256>>>(qkv_w, proj_w, fc1w, fc2w, wtf);
    // 1. qkv = gather(x_v) @ qkv_w^T + b
    mma_gemm<<<dim3(6, 1024), 256, GEMM_SMEM>>>(x_v, wtf, qkv_b, qkvb, 384, 128);
    // 2. tensor-core window attention (writes tf32-rounded)
    attn_kernel<<<dim3(1024, HEADS), 256, SMEM_ATTN>>>(qkvb, rpb, attn);
    // 3. proj + scatter + residual + LN2 (xres full, xln rounded)
    mma_gemm_ln<<<dim3(1, 2048), 256, GEMM_SMEM>>>(attn, wtf + 49152, proj_b, x_v,
                                                   xres, xln, n2w, n2b, 128);
    // 4. fused MLP: fc1 + gelu + fc2 + residual + LN1 -> final output
    mlp_kernel<<<1024, 512, MLP_SMEM>>>(xln, wtf + 65536, wtf + 131072,
                                        fc1b, fc2b, xres, out, n1w, n1b);
}

// round 8
// speedup vs baseline: 1.6637x; 1.0040x over previous
#include <cuda_runtime.h>
#include <math.h>

// ---------------- problem constants ----------------
#define M_TOT 131072
#define HEADS 4

// ---------------- scratch ----------------
__device__ float g_qkv [(size_t)M_TOT * 3 * 128];
__device__ float g_xln [(size_t)M_TOT * 128];
__device__ float g_xres[(size_t)M_TOT * 128];
__device__ float g_ps  [256 * 4 * 4096];     // rpb+mask, C-frag order per (winmod, head)
__device__ unsigned g_wtf[196608];           // tf32 weights: qkv(rm)|proj(frag)|fc1(rm)|fc2(rm)

__device__ __forceinline__ int perm_row(int r) {
    int b_ = r >> 7, tt = r & 127;
    int b = b_ >> 8, w = b_ & 255;
    int wh = w >> 4, ww = w & 15;
    int t = tt >> 6, n = tt & 63;
    int i = n >> 3, j = n & 7;
    int oh = (wh * 8 + i + 4) & 127;
    int ow = (ww * 8 + j + 4) & 127;
    return (b * 2 + t) * 16384 + oh * 128 + ow;
}

__device__ __forceinline__ unsigned f2tf(float f) {
    unsigned u;
    asm("cvt.rna.tf32.f32 %0, %1;" : "=r"(u) : "f"(f));
    return u;
}
__device__ __forceinline__ float round_tf(float f) { return __uint_as_float(f2tf(f)); }

#define MMA_TF32(d, a0, a1, a2, a3, b0, b1)                                            \
    asm volatile(                                                                      \
        "mma.sync.aligned.m16n8k8.row.col.f32.tf32.tf32.f32 "                          \
        "{%0,%1,%2,%3},{%4,%5,%6,%7},{%8,%9},{%0,%1,%2,%3};"                           \
        : "+f"(d[0]), "+f"(d[1]), "+f"(d[2]), "+f"(d[3])                               \
        : "r"(a0), "r"(a1), "r"(a2), "r"(a3), "r"(b0), "r"(b1))

// ---------------- weight pre-conversion ----------------
// qkv/fc1/fc2 row-major tf32 bits; proj in B-fragment order for direct LDG.64
__global__ void cvt_weights(const float* __restrict__ qkv_w, const float* __restrict__ proj_w,
                            const float* __restrict__ fc1_w, const float* __restrict__ fc2_w,
                            unsigned* __restrict__ wtf) {
    int i = blockIdx.x * 256 + threadIdx.x;
    if (i < 49152) { wtf[i] = f2tf(qkv_w[i]); return; }
    if (i < 65536) {
        int j = i - 49152;
        int pair = j >> 1, half = j & 1;
        int lane = pair & 31, k8 = (pair >> 5) & 15, n8 = pair >> 9;
        int g = lane >> 2, t = lane & 3;
        int n = n8 * 8 + g, k = k8 * 8 + t + (half ? 4 : 0);
        wtf[i] = f2tf(proj_w[n * 128 + k]);
        return;
    }
    if (i < 131072) { wtf[i] = f2tf(fc1_w[i - 65536]); return; }
    wtf[i] = f2tf(fc2_w[i - 131072]);
}

// ---------------- rpb + shift-mask table in C-frag order ----------------
__global__ void ps_kernel(const float* __restrict__ rpb, float* __restrict__ ps) {
    int wwin = blockIdx.x;   // window mod 256
    int head = blockIdx.y;
    int wh = wwin >> 4, ww = wwin & 15;
    int tid = threadIdx.x;
    float* dst = ps + (size_t)(wwin * 4 + head) * 4096;
#pragma unroll
    for (int it = 0; it < 16; it++) {
        int e = tid + it * 256;
        int qn = e >> 6, kn = e & 63;
        int qi2 = qn >> 3, qj = qn & 7, ki = kn >> 3, kj = kn & 7;
        int rel = (qi2 - ki + 7) * 15 + (qj - kj + 7);
        float v = rpb[rel * HEADS + head];
        int gqh = wh * 8 + qi2, gqw = ww * 8 + qj;
        int gkh = wh * 8 + ki,  gkw = ww * 8 + kj;
        int rq = (gqh < 120 ? 0 : (gqh < 124 ? 1 : 2)) * 3 + (gqw < 120 ? 0 : (gqw < 124 ? 1 : 2));
        int rk = (gkh < 120 ? 0 : (gkh < 124 ? 1 : 2)) * 3 + (gkw < 120 ? 0 : (gkw < 124 ? 1 : 2));
        if (rq != rk) v -= 100.0f;
        int qtile = qn >> 4, ntile = kn >> 3;
        int ln = (qn & 7) * 4 + ((kn & 7) >> 1);
        int reg = ((qn >> 3) & 1) * 2 + (kn & 1);
        dst[((qtile * 8 + ntile) * 32 + ln) * 4 + reg] = v;
    }
}

// ---------------- qkv GEMM, MLP-style: A staged once, weights streamed ----------------
// 512 threads, BM=128 (one window), N=384 in 6 chunks of 64, K=128.
#define QKV_SMEM ((16896 + 16896) * 4)
__global__ __launch_bounds__(512) void qkv_kernel(
    const float* __restrict__ xv, const unsigned* __restrict__ Wq_,
    const float* __restrict__ bias, float* __restrict__ out) {
    extern __shared__ unsigned sm[];
    unsigned* XA = sm;           // 16896 = 16 rowgrps x 1056
    unsigned* WB = sm + 16896;   // 2 x 8448

    const uint4* Wg = reinterpret_cast<const uint4*>(Wq_);
    const int tid = threadIdx.x;
    const int lane = tid & 31;
    const int wid = tid >> 5;
    const int wm = wid >> 2, wn = wid & 3;   // 4m x 4n, warp tile 32x16
    const int g = lane >> 2, t = lane & 3;
    const int bm = blockIdx.x * 128;

    // stage A (perm gather + cvt), A-frag layout
#pragma unroll
    for (int it = 0; it < 8; it++) {
        int c = tid + it * 512;
        int row = c >> 5, kq = c & 31;
        int src = perm_row(bm + row);
        float4 v = *reinterpret_cast<const float4*>(xv + (size_t)src * 128 + kq * 4);
        int sts = ((row >> 4) * 2 + ((row >> 3) & 1)) * 1056 + (kq >> 1) * 66 + (row & 7) * 8 + (kq & 1);
        XA[sts + 0] = f2tf(v.x); XA[sts + 2] = f2tf(v.y);
        XA[sts + 4] = f2tf(v.z); XA[sts + 6] = f2tf(v.w);
    }

    int wsrc[4], wst[4];
#pragma unroll
    for (int it = 0; it < 4; it++) {
        int e = tid + it * 512;              // 0..2047
        int n = e >> 5, kq = e & 31;
        wsrc[it] = n * 32 + kq;              // + chunk*2048 (uint4 units)
        wst[it] = (n >> 3) * 1056 + (kq >> 1) * 66 + (n & 7) * 8 + (kq & 1);
    }
    {
        uint4 v[4];
#pragma unroll
        for (int it = 0; it < 4; it++) v[it] = Wg[wsrc[it]];
#pragma unroll
        for (int it = 0; it < 4; it++) {
            WB[wst[it] + 0] = v[it].x; WB[wst[it] + 2] = v[it].y;
            WB[wst[it] + 4] = v[it].z; WB[wst[it] + 6] = v[it].w;
        }
    }
    __syncthreads();

    int p = 0;
    for (int c = 0; c < 6; c++) {
        uint4 wv[4];
        if (c < 5) {
#pragma unroll
            for (int it = 0; it < 4; it++) wv[it] = Wg[wsrc[it] + (c + 1) * 2048];
        }
        unsigned* Wp = WB + p * 8448;

        float accs[2][2][4];
#pragma unroll
        for (int mi = 0; mi < 2; mi++)
#pragma unroll
            for (int ni = 0; ni < 2; ni++)
#pragma unroll
                for (int q = 0; q < 4; q++) accs[mi][ni][q] = 0.f;

#pragma unroll
        for (int k8 = 0; k8 < 16; k8++) {
            unsigned a[2][4], b[2][2];
#pragma unroll
            for (int mi = 0; mi < 2; mi++) {
                int base = ((wm * 2 + mi) * 2) * 1056 + k8 * 66 + lane * 2;
                uint2 q0 = *reinterpret_cast<const uint2*>(&XA[base]);
                uint2 q1 = *reinterpret_cast<const uint2*>(&XA[base + 1056]);
                a[mi][0] = q0.x; a[mi][2] = q0.y;
                a[mi][1] = q1.x; a[mi][3] = q1.y;
            }
#pragma unroll
            for (int ni = 0; ni < 2; ni++) {
                uint2 q = *reinterpret_cast<const uint2*>(&Wp[(wn * 2 + ni) * 1056 + k8 * 66 + lane * 2]);
                b[ni][0] = q.x; b[ni][1] = q.y;
            }
#pragma unroll
            for (int mi = 0; mi < 2; mi++)
#pragma unroll
                for (int ni = 0; ni < 2; ni++)
                    MMA_TF32(accs[mi][ni], a[mi][0], a[mi][1], a[mi][2], a[mi][3],
                             b[ni][0], b[ni][1]);
        }

        // write this n-chunk
#pragma unroll
        for (int mi = 0; mi < 2; mi++) {
#pragma unroll
            for (int rh = 0; rh < 2; rh++) {
                int r = bm + wm * 32 + mi * 16 + g + rh * 8;
#pragma unroll
                for (int ni = 0; ni < 2; ni++) {
                    int col = c * 64 + wn * 16 + ni * 8 + t * 2;
                    float2 o;
                    o.x = accs[mi][ni][rh * 2 + 0] + bias[col];
                    o.y = accs[mi][ni][rh * 2 + 1] + bias[col + 1];
                    *reinterpret_cast<float2*>(out + (size_t)r * 384 + col) = o;
                }
            }
        }

        if (c < 5) {
            unsigned* Wn = WB + (p ^ 1) * 8448;
#pragma unroll
            for (int it = 0; it < 4; it++) {
                Wn[wst[it] + 0] = wv[it].x; Wn[wst[it] + 2] = wv[it].y;
                Wn[wst[it] + 4] = wv[it].z; Wn[wst[it] + 6] = wv[it].w;
            }
            p ^= 1;
        }
        __syncthreads();
    }
}

// ---------------- fused attention + proj + scatter + residual + LN2 ----------------
// one block (256 thr) per window; 4 heads looped; O accumulated in smem A-frag;
// proj weights read directly from L2 in B-frag order.
#define AP_OA 0
#define AP_KB 16896
#define AP_VB 21120
#define AP_SMEM (25376 * 4)

__global__ __launch_bounds__(256) void attnproj_kernel(
    const float* __restrict__ qkv, const float* __restrict__ ps,
    const unsigned* __restrict__ Wp_, const float* __restrict__ bias,
    const float* __restrict__ res, float* __restrict__ xres, float* __restrict__ xln,
    const float* __restrict__ gw, const float* __restrict__ bw) {
    extern __shared__ unsigned sm[];
    unsigned* OA = sm + AP_OA;   // 16 rowgrps x 1056
    unsigned* KB = sm + AP_KB;   // 16 x 264
    unsigned* VB = sm + AP_VB;   // 4 x 1064
    __shared__ float smS[128][2], smQ[128][2];

    const int win = blockIdx.x;
    const int tid = threadIdx.x;
    const int lane = tid & 31, w = tid >> 5;
    const int g = lane >> 2, t = lane & 3;
    const int qtile = w & 3;
    const float scale = 0.17677669529663687f;
    const float* psW = ps + (size_t)((win & 255) * 4) * 4096;

    for (int head = 0; head < HEADS; head++) {
        // stage K, V
#pragma unroll
        for (int it = 0; it < 4; it++) {
            int c = tid + it * 256;
            int row = c >> 3, kq = c & 7;
            size_t base = ((size_t)(win * 128 + row)) * 384 + head * 32 + kq * 4;
            float4 kv = *reinterpret_cast<const float4*>(qkv + base + 128);
            float4 vv = *reinterpret_cast<const float4*>(qkv + base + 256);
            int k8 = kq >> 1, kh = kq & 1;
            int kb = (row >> 3) * 264 + k8 * 66 + (row & 7) * 8 + kh;
            KB[kb + 0] = f2tf(kv.x); KB[kb + 2] = f2tf(kv.y);
            KB[kb + 4] = f2tf(kv.z); KB[kb + 6] = f2tf(kv.w);
            int vb = (kq >> 1) * 1064 + (row >> 3) * 66 + ((kq & 1) * 4) * 8 +
                     ((row >> 2) & 1) + 2 * (row & 3);
            VB[vb + 0]  = f2tf(vv.x); VB[vb + 8]  = f2tf(vv.y);
            VB[vb + 16] = f2tf(vv.z); VB[vb + 24] = f2tf(vv.w);
        }
        __syncthreads();

        // Q fragments direct from gmem (rows 16w+g, 16w+g+8)
        unsigned qa[4][4];
        {
            size_t q0r = ((size_t)(win * 128 + w * 16 + g)) * 384 + head * 32;
#pragma unroll
            for (int k8 = 0; k8 < 4; k8++) {
                qa[k8][0] = f2tf(qkv[q0r + k8 * 8 + t] * scale);
                qa[k8][2] = f2tf(qkv[q0r + k8 * 8 + 4 + t] * scale);
                qa[k8][1] = f2tf(qkv[q0r + 8 * 384 + k8 * 8 + t] * scale);
                qa[k8][3] = f2tf(qkv[q0r + 8 * 384 + k8 * 8 + 4 + t] * scale);
            }
        }

        // S = Q @ K^T
        float acc[16][4];
#pragma unroll
        for (int nt = 0; nt < 16; nt++)
#pragma unroll
            for (int i = 0; i < 4; i++) acc[nt][i] = 0.f;
#pragma unroll
        for (int k8 = 0; k8 < 4; k8++) {
#pragma unroll
            for (int nt = 0; nt < 16; nt++) {
                uint2 b = *reinterpret_cast<const uint2*>(&KB[nt * 264 + k8 * 66 + lane * 2]);
                MMA_TF32(acc[nt], qa[k8][0], qa[k8][1], qa[k8][2], qa[k8][3], b.x, b.y);
            }
        }

        // + rpb/mask from precomputed table; softmax
        const float* psh = psW + head * 4096;
        float m0 = -1e30f, m1 = -1e30f;
#pragma unroll
        for (int nt = 0; nt < 16; nt++) {
            float4 p = *reinterpret_cast<const float4*>(psh + ((qtile * 8 + (nt & 7)) * 32 + lane) * 4);
            acc[nt][0] += p.x; acc[nt][1] += p.y;
            acc[nt][2] += p.z; acc[nt][3] += p.w;
            m0 = fmaxf(m0, fmaxf(acc[nt][0], acc[nt][1]));
            m1 = fmaxf(m1, fmaxf(acc[nt][2], acc[nt][3]));
        }
        m0 = fmaxf(m0, __shfl_xor_sync(0xffffffffu, m0, 1));
        m0 = fmaxf(m0, __shfl_xor_sync(0xffffffffu, m0, 2));
        m1 = fmaxf(m1, __shfl_xor_sync(0xffffffffu, m1, 1));
        m1 = fmaxf(m1, __shfl_xor_sync(0xffffffffu, m1, 2));

        float l0 = 0.f, l1 = 0.f;
#pragma unroll
        for (int nt = 0; nt < 16; nt++) {
            acc[nt][0] = __expf(acc[nt][0] - m0);
            acc[nt][1] = __expf(acc[nt][1] - m0);
            acc[nt][2] = __expf(acc[nt][2] - m1);
            acc[nt][3] = __expf(acc[nt][3] - m1);
            l0 += acc[nt][0] + acc[nt][1];
            l1 += acc[nt][2] + acc[nt][3];
        }
        l0 += __shfl_xor_sync(0xffffffffu, l0, 1);
        l0 += __shfl_xor_sync(0xffffffffu, l0, 2);
        l1 += __shfl_xor_sync(0xffffffffu, l1, 1);
        l1 += __shfl_xor_sync(0xffffffffu, l1, 2);
        float inv0 = 1.0f / l0, inv1 = 1.0f / l1;

#pragma unroll
        for (int nt = 0; nt < 16; nt++)
#pragma unroll
            for (int i = 0; i < 4; i++)
                acc[nt][i] = __uint_as_float(f2tf(acc[nt][i]));

        // O = P @ V
        float oacc[4][4];
#pragma unroll
        for (int n8 = 0; n8 < 4; n8++)
#pragma unroll
            for (int i = 0; i < 4; i++) oacc[n8][i] = 0.f;

        const int s0 = (lane & 28) | (t >> 1);
        const int s1 = s0 + 2;
        const bool oddt = (t & 1);
#pragma unroll
        for (int c = 0; c < 16; c++) {
            float e0 = __shfl_sync(0xffffffffu, acc[c][0], s0);
            float o0 = __shfl_sync(0xffffffffu, acc[c][1], s0);
            float e1 = __shfl_sync(0xffffffffu, acc[c][2], s0);
            float o1 = __shfl_sync(0xffffffffu, acc[c][3], s0);
            float e2 = __shfl_sync(0xffffffffu, acc[c][0], s1);
            float o2 = __shfl_sync(0xffffffffu, acc[c][1], s1);
            float e3 = __shfl_sync(0xffffffffu, acc[c][2], s1);
            float o3 = __shfl_sync(0xffffffffu, acc[c][3], s1);
            unsigned a0 = __float_as_uint(oddt ? o0 : e0);
            unsigned a1 = __float_as_uint(oddt ? o1 : e1);
            unsigned a2 = __float_as_uint(oddt ? o2 : e2);
            unsigned a3 = __float_as_uint(oddt ? o3 : e3);
#pragma unroll
            for (int n8 = 0; n8 < 4; n8++) {
                uint2 b = *reinterpret_cast<const uint2*>(&VB[n8 * 1064 + c * 66 + lane * 2]);
                MMA_TF32(oacc[n8], a0, a1, a2, a3, b.x, b.y);
            }
        }

        // store O (rounded) into OA in A-frag layout: row = 16w+g+8rh, k = head*32+n8*8+t*2+ch
#pragma unroll
        for (int n8 = 0; n8 < 4; n8++) {
#pragma unroll
            for (int rh = 0; rh < 2; rh++) {
                float iv = rh ? inv1 : inv0;
#pragma unroll
                for (int ch = 0; ch < 2; ch++) {
                    int t2c = t * 2 + ch;
                    int addr = (w * 2 + rh) * 1056 + (head * 4 + n8) * 66 + g * 8 +
                               (t2c >> 2) + (t2c & 3) * 2;
                    OA[addr] = f2tf(oacc[n8][rh * 2 + ch] * iv);
                }
            }
        }
        __syncthreads();   // protect KB/VB restage + OA completeness
    }

    // ---- proj: C(128x128) = OA @ Wp^T, weights direct from L2 in frag order ----
    const uint2* Wp2 = reinterpret_cast<const uint2*>(Wp_);
    const int wm = w >> 1, wn = w & 1;   // 4m x 2n, warp tile 32x64
    float acc2[2][8][4];
#pragma unroll
    for (int mi = 0; mi < 2; mi++)
#pragma unroll
        for (int ni = 0; ni < 8; ni++)
#pragma unroll
            for (int q = 0; q < 4; q++) acc2[mi][ni][q] = 0.f;

#pragma unroll
    for (int k8 = 0; k8 < 16; k8++) {
        unsigned a[2][4];
#pragma unroll
        for (int mi = 0; mi < 2; mi++) {
            int base = ((wm * 2 + mi) * 2) * 1056 + k8 * 66 + lane * 2;
            uint2 q0 = *reinterpret_cast<const uint2*>(&OA[base]);
            uint2 q1 = *reinterpret_cast<const uint2*>(&OA[base + 1056]);
            a[mi][0] = q0.x; a[mi][2] = q0.y;
            a[mi][1] = q1.x; a[mi][3] = q1.y;
        }
#pragma unroll
        for (int ni = 0; ni < 8; ni++) {
            uint2 b = Wp2[((wn * 8 + ni) * 16 + k8) * 32 + lane];
#pragma unroll
            for (int mi = 0; mi < 2; mi++)
                MMA_TF32(acc2[mi][ni], a[mi][0], a[mi][1], a[mi][2], a[mi][3], b.x, b.y);
        }
    }

    // ---- epilogue: bias + residual(scatter) + LN2 ----
#pragma unroll
    for (int mi = 0; mi < 2; mi++) {
#pragma unroll
        for (int rh = 0; rh < 2; rh++) {
            int lrow = wm * 32 + mi * 16 + g + rh * 8;
            int xrow = perm_row(win * 128 + lrow);
            float v[16];
            float s = 0.f, q = 0.f;
#pragma unroll
            for (int ni = 0; ni < 8; ni++) {
                int cc = wn * 64 + ni * 8 + t * 2;
#pragma unroll
                for (int ch = 0; ch < 2; ch++) {
                    float x = acc2[mi][ni][rh * 2 + ch] + bias[cc + ch] +
                              res[(size_t)xrow * 128 + cc + ch];
                    xres[(size_t)xrow * 128 + cc + ch] = x;
                    v[ni * 2 + ch] = x;
                    s += x; q += x * x;
                }
            }
            s += __shfl_xor_sync(0xffffffffu, s, 1);
            s += __shfl_xor_sync(0xffffffffu, s, 2);
            q += __shfl_xor_sync(0xffffffffu, q, 1);
            q += __shfl_xor_sync(0xffffffffu, q, 2);
            if (t == 0) { smS[lrow][wn] = s; smQ[lrow][wn] = q; }
            __syncthreads();
            float S = smS[lrow][0] + smS[lrow][1];
            float Q = smQ[lrow][0] + smQ[lrow][1];
            float mu = S * (1.f / 128.f);
            float var = Q * (1.f / 128.f) - mu * mu;
            float rs = rsqrtf(var + 1e-5f);
#pragma unroll
            for (int ni = 0; ni < 8; ni++) {
                int cc = wn * 64 + ni * 8 + t * 2;
#pragma unroll
                for (int ch = 0; ch < 2; ch++) {
                    xln[(size_t)xrow * 128 + cc + ch] =
                        round_tf((v[ni * 2 + ch] - mu) * rs * gw[cc + ch] + bw[cc + ch]);
                }
            }
        }
    }
}

// ---------------- fused MLP: fc1 + gelu + fc2 + residual + LN1 (unchanged) ----------------
#define MLP_SMEM (42240 * 4)
__global__ __launch_bounds__(512) void mlp_kernel(
    const float* __restrict__ xln, const unsigned* __restrict__ W1g4_,
    const unsigned* __restrict__ W2g4_,
    const float* __restrict__ b1, const float* __restrict__ b2,
    const float* __restrict__ res, float* __restrict__ out,
    const float* __restrict__ gw, const float* __restrict__ bw) {
    extern __shared__ unsigned sm[];
    unsigned* XA = sm;
    unsigned* W1 = sm + 16896;
    unsigned* W2 = sm + 25344;
    unsigned* HH = sm + 33792;
    __shared__ float smS[128][4], smQ[128][4];

    const uint4* W1g = reinterpret_cast<const uint4*>(W1g4_);
    const uint4* W2g = reinterpret_cast<const uint4*>(W2g4_);

    const int tid = threadIdx.x;
    const int lane = tid & 31;
    const int wid = tid >> 5;
    const int wm = wid >> 2, wn = wid & 3;
    const int g = lane >> 2, t = lane & 3;
    const int bm = blockIdx.x * 128;

#pragma unroll
    for (int it = 0; it < 8; it++) {
        int c = tid + it * 512;
        int row = c >> 5, kq = c & 31;
        uint4 v = *reinterpret_cast<const uint4*>(xln + (size_t)(bm + row) * 128 + kq * 4);
        int sts = ((row >> 4) * 2 + ((row >> 3) & 1)) * 1056 + (kq >> 1) * 66 + (row & 7) * 8 + (kq & 1);
        XA[sts + 0] = v.x; XA[sts + 2] = v.y; XA[sts + 4] = v.z; XA[sts + 6] = v.w;
    }

    int w1src[4], w2src[4], w1st[4], w2st[4];
#pragma unroll
    for (int it = 0; it < 4; it++) {
        int e = tid + it * 512;
        int n = e >> 5, kq = e & 31;
        w1src[it] = n * 32 + kq;
        w1st[it] = (n >> 3) * 1056 + (kq >> 1) * 66 + (n & 7) * 8 + (kq & 1);
        int n2 = e >> 4, klq = e & 15;
        w2src[it] = n2 * 128 + klq;
        w2st[it] = (n2 >> 3) * 528 + (klq >> 1) * 66 + (n2 & 7) * 8 + (klq & 1);
    }

    {
        uint4 v[4];
#pragma unroll
        for (int it = 0; it < 4; it++) v[it] = W1g[w1src[it]];
#pragma unroll
        for (int it = 0; it < 4; it++) {
            W1[w1st[it] + 0] = v[it].x; W1[w1st[it] + 2] = v[it].y;
            W1[w1st[it] + 4] = v[it].z; W1[w1st[it] + 6] = v[it].w;
        }
    }
    __syncthreads();

    float acco[2][4][4];
#pragma unroll
    for (int mi = 0; mi < 2; mi++)
#pragma unroll
        for (int ni = 0; ni < 4; ni++)
#pragma unroll
            for (int c = 0; c < 4; c++) acco[mi][ni][c] = 0.f;

    for (int c = 0; c < 8; c++) {
        uint4 w2v[4];
#pragma unroll
        for (int it = 0; it < 4; it++) w2v[it] = W2g[w2src[it] + c * 16];

        float accs[2][2][4];
#pragma unroll
        for (int mi = 0; mi < 2; mi++)
#pragma unroll
            for (int ni = 0; ni < 2; ni++)
#pragma unroll
                for (int q = 0; q < 4; q++) accs[mi][ni][q] = 0.f;
#pragma unroll
        for (int k8 = 0; k8 < 16; k8++) {
            unsigned a[2][4], b[2][2];
#pragma unroll
            for (int mi = 0; mi < 2; mi++) {
                int base = ((wm * 2 + mi) * 2) * 1056 + k8 * 66 + lane * 2;
                uint2 q0 = *reinterpret_cast<const uint2*>(&XA[base]);
                uint2 q1 = *reinterpret_cast<const uint2*>(&XA[base + 1056]);
                a[mi][0] = q0.x; a[mi][2] = q0.y;
                a[mi][1] = q1.x; a[mi][3] = q1.y;
            }
#pragma unroll
            for (int ni = 0; ni < 2; ni++) {
                uint2 q = *reinterpret_cast<const uint2*>(&W1[(wn * 2 + ni) * 1056 + k8 * 66 + lane * 2]);
                b[ni][0] = q.x; b[ni][1] = q.y;
            }
#pragma unroll
            for (int mi = 0; mi < 2; mi++)
#pragma unroll
                for (int ni = 0; ni < 2; ni++)
                    MMA_TF32(accs[mi][ni], a[mi][0], a[mi][1], a[mi][2], a[mi][3],
                             b[ni][0], b[ni][1]);
        }

#pragma unroll
        for (int it = 0; it < 4; it++) {
            W2[w2st[it] + 0] = w2v[it].x; W2[w2st[it] + 2] = w2v[it].y;
            W2[w2st[it] + 4] = w2v[it].z; W2[w2st[it] + 6] = w2v[it].w;
        }

#pragma unroll
        for (int mi = 0; mi < 2; mi++) {
            int rgR = (wm * 2 + mi) * 2;
#pragma unroll
            for (int ni = 0; ni < 2; ni++) {
                int kl0 = wn * 16 + ni * 8 + t * 2;
                float bb0 = b1[c * 64 + kl0], bb1 = b1[c * 64 + kl0 + 1];
#pragma unroll
                for (int rh = 0; rh < 2; rh++) {
#pragma unroll
                    for (int ch = 0; ch < 2; ch++) {
                        float v = accs[mi][ni][rh * 2 + ch] + (ch ? bb1 : bb0);
                        v = 0.5f * v * (1.0f + erff(v * 0.7071067811865475f));
                        int k = kl0 + ch;
                        int addr = (rgR + rh) * 528 + (k >> 3) * 66 + g * 8 +
                                   ((k >> 2) & 1) + (k & 3) * 2;
                        HH[addr] = f2tf(v);
                    }
                }
            }
        }
        __syncthreads();

        uint4 w1v[4];
        if (c < 7) {
#pragma unroll
            for (int it = 0; it < 4; it++) w1v[it] = W1g[w1src[it] + (c + 1) * 2048];
        }

#pragma unroll
        for (int k8 = 0; k8 < 8; k8++) {
            unsigned a[2][4], b[4][2];
#pragma unroll
            for (int mi = 0; mi < 2; mi++) {
                int base = ((wm * 2 + mi) * 2) * 528 + k8 * 66 + lane * 2;
                uint2 q0 = *reinterpret_cast<const uint2*>(&HH[base]);
                uint2 q1 = *reinterpret_cast<const uint2*>(&HH[base + 528]);
                a[mi][0] = q0.x; a[mi][2] = q0.y;
                a[mi][1] = q1.x; a[mi][3] = q1.y;
            }
#pragma unroll
            for (int ni = 0; ni < 4; ni++) {
                uint2 q = *reinterpret_cast<const uint2*>(&W2[(wn * 4 + ni) * 528 + k8 * 66 + lane * 2]);
                b[ni][0] = q.x; b[ni][1] = q.y;
            }
#pragma unroll
            for (int mi = 0; mi < 2; mi++)
#pragma unroll
                for (int ni = 0; ni < 4; ni++)
                    MMA_TF32(acco[mi][ni], a[mi][0], a[mi][1], a[mi][2], a[mi][3],
                             b[ni][0], b[ni][1]);
        }

        if (c < 7) {
#pragma unroll
            for (int it = 0; it < 4; it++) {
                W1[w1st[it] + 0] = w1v[it].x; W1[w1st[it] + 2] = w1v[it].y;
                W1[w1st[it] + 4] = w1v[it].z; W1[w1st[it] + 6] = w1v[it].w;
            }
        }
        __syncthreads();
    }

#pragma unroll
    for (int mi = 0; mi < 2; mi++) {
#pragma unroll
        for (int rh = 0; rh < 2; rh++) {
            int lrow = wm * 32 + mi * 16 + g + rh * 8;
            int r = bm + lrow;
            float v[8];
            float s = 0.f, q = 0.f;
#pragma unroll
            for (int ni = 0; ni < 4; ni++) {
                int cc = wn * 32 + ni * 8 + t * 2;
#pragma unroll
                for (int ch = 0; ch < 2; ch++) {
                    float x = acco[mi][ni][rh * 2 + ch] + b2[cc + ch] +
                              res[(size_t)r * 128 + cc + ch];
                    v[ni * 2 + ch] = x;
                    s += x; q += x * x;
                }
            }
            s += __shfl_xor_sync(0xffffffffu, s, 1);
            s += __shfl_xor_sync(0xffffffffu, s, 2);
            q += __shfl_xor_sync(0xffffffffu, q, 1);
            q += __shfl_xor_sync(0xffffffffu, q, 2);
            if (t == 0) { smS[lrow][wn] = s; smQ[lrow][wn] = q; }
            __syncthreads();
            float S = smS[lrow][0] + smS[lrow][1] + smS[lrow][2] + smS[lrow][3];
            float Q = smQ[lrow][0] + smQ[lrow][1] + smQ[lrow][2] + smQ[lrow][3];
            float mu = S * (1.f / 128.f);
            float var = Q * (1.f / 128.f) - mu * mu;
            float rs = rsqrtf(var + 1e-5f);
#pragma unroll
            for (int ni = 0; ni < 4; ni++) {
                int cc = wn * 32 + ni * 8 + t * 2;
#pragma unroll
                for (int ch = 0; ch < 2; ch++) {
                    out[(size_t)r * 128 + cc + ch] =
                        (v[ni * 2 + ch] - mu) * rs * gw[cc + ch] + bw[cc + ch];
                }
            }
        }
    }
}

// ---------------- launch ----------------
extern "C" void kernel_launch(void* const* d_in, const int* in_sizes, int n_in,
                              void* d_out, int out_size) {
    const float* x_v    = (const float*)d_in[0];
    const float* qkv_w  = (const float*)d_in[1];
    const float* qkv_b  = (const float*)d_in[2];
    const float* proj_w = (const float*)d_in[3];
    const float* proj_b = (const float*)d_in[4];
    const float* rpb    = (const float*)d_in[5];
    const float* n1w    = (const float*)d_in[6];
    const float* n1b    = (const float*)d_in[7];
    const float* n2w    = (const float*)d_in[8];
    const float* n2b    = (const float*)d_in[9];
    const float* fc1w   = (const float*)d_in[10];
    const float* fc1b   = (const float*)d_in[11];
    const float* fc2w   = (const float*)d_in[12];
    const float* fc2b   = (const float*)d_in[13];
    float* out = (float*)d_out;

    float *qkvb, *xln, *xres, *ps;
    unsigned* wtf;
    cudaGetSymbolAddress((void**)&qkvb, g_qkv);
    cudaGetSymbolAddress((void**)&xln,  g_xln);
    cudaGetSymbolAddress((void**)&xres, g_xres);
    cudaGetSymbolAddress((void**)&ps,   g_ps);
    cudaGetSymbolAddress((void**)&wtf,  g_wtf);

    cudaFuncSetAttribute(qkv_kernel, cudaFuncAttributeMaxDynamicSharedMemorySize, QKV_SMEM);
    cudaFuncSetAttribute(attnproj_kernel, cudaFuncAttributeMaxDynamicSharedMemorySize, AP_SMEM);
    cudaFuncSetAttribute(mlp_kernel, cudaFuncAttributeMaxDynamicSharedMemorySize, MLP_SMEM);

    // 0. weight conversion + rpb/mask table
    cvt_weights<<<768, 256>>>(qkv_w, proj_w, fc1w, fc2w, wtf);
    ps_kernel<<<dim3(256, 4), 256>>>(rpb, ps);
    // 1. qkv = gather(x_v) @ qkv_w^T + b   (A staged once per window)
    qkv_kernel<<<1024, 512, QKV_SMEM>>>(x_v, wtf, qkv_b, qkvb);
    // 2. fused attention + proj + scatter + residual + LN2
    attnproj_kernel<<<1024, 256, AP_SMEM>>>(qkvb, ps, wtf + 49152, proj_b,
                                            x_v, xres, xln, n2w, n2b);
    // 3. fused MLP -> final output
    mlp_kernel<<<1024, 512, MLP_SMEM>>>(xln, wtf + 65536, wtf + 131072,
                                        fc1b, fc2b, xres, out, n1w, n1b);
}

// round 9
// speedup vs baseline: 1.7838x; 1.0722x over previous
#include <cuda_runtime.h>
#include <math.h>

// ---------------- problem constants ----------------
#define M_TOT 131072
#define HEADS 4

// ---------------- scratch ----------------
__device__ float g_qkv [(size_t)M_TOT * 3 * 128];
__device__ float g_attn[(size_t)M_TOT * 128];
__device__ float g_xln [(size_t)M_TOT * 128];
__device__ float g_xres[(size_t)M_TOT * 128];
__device__ float g_ps  [256 * 4 * 4096];     // rpb+mask, C-frag order per (winmod, head)
__device__ unsigned g_wtf[196608];           // tf32 weights: qkv(rm)|proj(frag)|fc1(rm)|fc2(rm)

__device__ __forceinline__ int perm_row(int r) {
    int b_ = r >> 7, tt = r & 127;
    int b = b_ >> 8, w = b_ & 255;
    int wh = w >> 4, ww = w & 15;
    int t = tt >> 6, n = tt & 63;
    int i = n >> 3, j = n & 7;
    int oh = (wh * 8 + i + 4) & 127;
    int ow = (ww * 8 + j + 4) & 127;
    return (b * 2 + t) * 16384 + oh * 128 + ow;
}

__device__ __forceinline__ unsigned f2tf(float f) {
    unsigned u;
    asm("cvt.rna.tf32.f32 %0, %1;" : "=r"(u) : "f"(f));
    return u;
}
__device__ __forceinline__ float round_tf(float f) { return __uint_as_float(f2tf(f)); }

#define MMA_TF32(d, a0, a1, a2, a3, b0, b1)                                            \
    asm volatile(                                                                      \
        "mma.sync.aligned.m16n8k8.row.col.f32.tf32.tf32.f32 "                          \
        "{%0,%1,%2,%3},{%4,%5,%6,%7},{%8,%9},{%0,%1,%2,%3};"                           \
        : "+f"(d[0]), "+f"(d[1]), "+f"(d[2]), "+f"(d[3])                               \
        : "r"(a0), "r"(a1), "r"(a2), "r"(a3), "r"(b0), "r"(b1))

// ---------------- weight pre-conversion ----------------
__global__ void cvt_weights(const float* __restrict__ qkv_w, const float* __restrict__ proj_w,
                            const float* __restrict__ fc1_w, const float* __restrict__ fc2_w,
                            unsigned* __restrict__ wtf) {
    int i = blockIdx.x * 256 + threadIdx.x;
    if (i < 49152) { wtf[i] = f2tf(qkv_w[i]); return; }
    if (i < 65536) {
        int j = i - 49152;
        int pair = j >> 1, half = j & 1;
        int lane = pair & 31, k8 = (pair >> 5) & 15, n8 = pair >> 9;
        int g = lane >> 2, t = lane & 3;
        int n = n8 * 8 + g, k = k8 * 8 + t + (half ? 4 : 0);
        wtf[i] = f2tf(proj_w[n * 128 + k]);
        return;
    }
    if (i < 131072) { wtf[i] = f2tf(fc1_w[i - 65536]); return; }
    wtf[i] = f2tf(fc2_w[i - 131072]);
}

// ---------------- rpb + shift-mask table in C-frag order ----------------
__global__ void ps_kernel(const float* __restrict__ rpb, float* __restrict__ ps) {
    int wwin = blockIdx.x;
    int head = blockIdx.y;
    int wh = wwin >> 4, ww = wwin & 15;
    int tid = threadIdx.x;
    float* dst = ps + (size_t)(wwin * 4 + head) * 4096;
#pragma unroll
    for (int it = 0; it < 16; it++) {
        int e = tid + it * 256;
        int qn = e >> 6, kn = e & 63;
        int qi2 = qn >> 3, qj = qn & 7, ki = kn >> 3, kj = kn & 7;
        int rel = (qi2 - ki + 7) * 15 + (qj - kj + 7);
        float v = rpb[rel * HEADS + head];
        int gqh = wh * 8 + qi2, gqw = ww * 8 + qj;
        int gkh = wh * 8 + ki,  gkw = ww * 8 + kj;
        int rq = (gqh < 120 ? 0 : (gqh < 124 ? 1 : 2)) * 3 + (gqw < 120 ? 0 : (gqw < 124 ? 1 : 2));
        int rk = (gkh < 120 ? 0 : (gkh < 124 ? 1 : 2)) * 3 + (gkw < 120 ? 0 : (gkw < 124 ? 1 : 2));
        if (rq != rk) v -= 100.0f;
        int qtile = qn >> 4, ntile = kn >> 3;
        int ln = (qn & 7) * 4 + ((kn & 7) >> 1);
        int reg = ((qn >> 3) & 1) * 2 + (kn & 1);
        dst[((qtile * 8 + ntile) * 32 + ln) * 4 + reg] = v;
    }
}

// ---------------- qkv GEMM, A staged once, weights streamed ----------------
#define QKV_SMEM ((16896 + 16896) * 4)
__global__ __launch_bounds__(512) void qkv_kernel(
    const float* __restrict__ xv, const unsigned* __restrict__ Wq_,
    const float* __restrict__ bias, float* __restrict__ out) {
    extern __shared__ unsigned sm[];
    unsigned* XA = sm;
    unsigned* WB = sm + 16896;

    const uint4* Wg = reinterpret_cast<const uint4*>(Wq_);
    const int tid = threadIdx.x;
    const int lane = tid & 31;
    const int wid = tid >> 5;
    const int wm = wid >> 2, wn = wid & 3;
    const int g = lane >> 2, t = lane & 3;
    const int bm = blockIdx.x * 128;

#pragma unroll
    for (int it = 0; it < 8; it++) {
        int c = tid + it * 512;
        int row = c >> 5, kq = c & 31;
        int src = perm_row(bm + row);
        float4 v = *reinterpret_cast<const float4*>(xv + (size_t)src * 128 + kq * 4);
        int sts = ((row >> 4) * 2 + ((row >> 3) & 1)) * 1056 + (kq >> 1) * 66 + (row & 7) * 8 + (kq & 1);
        XA[sts + 0] = f2tf(v.x); XA[sts + 2] = f2tf(v.y);
        XA[sts + 4] = f2tf(v.z); XA[sts + 6] = f2tf(v.w);
    }

    int wsrc[4], wst[4];
#pragma unroll
    for (int it = 0; it < 4; it++) {
        int e = tid + it * 512;
        int n = e >> 5, kq = e & 31;
        wsrc[it] = n * 32 + kq;
        wst[it] = (n >> 3) * 1056 + (kq >> 1) * 66 + (n & 7) * 8 + (kq & 1);
    }
    {
        uint4 v[4];
#pragma unroll
        for (int it = 0; it < 4; it++) v[it] = Wg[wsrc[it]];
#pragma unroll
        for (int it = 0; it < 4; it++) {
            WB[wst[it] + 0] = v[it].x; WB[wst[it] + 2] = v[it].y;
            WB[wst[it] + 4] = v[it].z; WB[wst[it] + 6] = v[it].w;
        }
    }
    __syncthreads();

    int p = 0;
    for (int c = 0; c < 6; c++) {
        uint4 wv[4];
        if (c < 5) {
#pragma unroll
            for (int it = 0; it < 4; it++) wv[it] = Wg[wsrc[it] + (c + 1) * 2048];
        }
        unsigned* Wp = WB + p * 8448;

        float accs[2][2][4];
#pragma unroll
        for (int mi = 0; mi < 2; mi++)
#pragma unroll
            for (int ni = 0; ni < 2; ni++)
#pragma unroll
                for (int q = 0; q < 4; q++) accs[mi][ni][q] = 0.f;

#pragma unroll
        for (int k8 = 0; k8 < 16; k8++) {
            unsigned a[2][4], b[2][2];
#pragma unroll
            for (int mi = 0; mi < 2; mi++) {
                int base = ((wm * 2 + mi) * 2) * 1056 + k8 * 66 + lane * 2;
                uint2 q0 = *reinterpret_cast<const uint2*>(&XA[base]);
                uint2 q1 = *reinterpret_cast<const uint2*>(&XA[base + 1056]);
                a[mi][0] = q0.x; a[mi][2] = q0.y;
                a[mi][1] = q1.x; a[mi][3] = q1.y;
            }
#pragma unroll
            for (int ni = 0; ni < 2; ni++) {
                uint2 q = *reinterpret_cast<const uint2*>(&Wp[(wn * 2 + ni) * 1056 + k8 * 66 + lane * 2]);
                b[ni][0] = q.x; b[ni][1] = q.y;
            }
#pragma unroll
            for (int mi = 0; mi < 2; mi++)
#pragma unroll
                for (int ni = 0; ni < 2; ni++)
                    MMA_TF32(accs[mi][ni], a[mi][0], a[mi][1], a[mi][2], a[mi][3],
                             b[ni][0], b[ni][1]);
        }

#pragma unroll
        for (int mi = 0; mi < 2; mi++) {
#pragma unroll
            for (int rh = 0; rh < 2; rh++) {
                int r = bm + wm * 32 + mi * 16 + g + rh * 8;
#pragma unroll
                for (int ni = 0; ni < 2; ni++) {
                    int col = c * 64 + wn * 16 + ni * 8 + t * 2;
                    float2 o;
                    o.x = accs[mi][ni][rh * 2 + 0] + bias[col];
                    o.y = accs[mi][ni][rh * 2 + 1] + bias[col + 1];
                    *reinterpret_cast<float2*>(out + (size_t)r * 384 + col) = o;
                }
            }
        }

        if (c < 5) {
            unsigned* Wn = WB + (p ^ 1) * 8448;
#pragma unroll
            for (int it = 0; it < 4; it++) {
                Wn[wst[it] + 0] = wv[it].x; Wn[wst[it] + 2] = wv[it].y;
                Wn[wst[it] + 4] = wv[it].z; Wn[wst[it] + 6] = wv[it].w;
            }
            p ^= 1;
        }
        __syncthreads();
    }
}

// ---------------- tensor-core window attention (ps table from gmem) ----------------
#define SM_QA 0
#define SM_KB 4224
#define SM_VB 8448
#define SMEM_ATTN (12704 * 4)

__global__ __launch_bounds__(256) void attn_kernel(const float* __restrict__ qkv,
                                                   const float* __restrict__ ps,
                                                   float* __restrict__ attout) {
    extern __shared__ unsigned sm[];
    unsigned* QA = sm + SM_QA;
    unsigned* KB = sm + SM_KB;
    unsigned* VB = sm + SM_VB;

    const int win = blockIdx.x, head = blockIdx.y;
    const int tid = threadIdx.x;
    const int lane = tid & 31, w = tid >> 5;
    const int g = lane >> 2, t = lane & 3;
    const float scale = 0.17677669529663687f;
    const float* psh = ps + (size_t)((win & 255) * 4 + head) * 4096;

#pragma unroll
    for (int it = 0; it < 4; it++) {
        int c = tid + it * 256;
        int row = c >> 3, kq = c & 7;
        size_t base = ((size_t)(win * 128 + row)) * 384 + head * 32 + kq * 4;
        float4 qv = *reinterpret_cast<const float4*>(qkv + base);
        float4 kv = *reinterpret_cast<const float4*>(qkv + base + 128);
        float4 vv = *reinterpret_cast<const float4*>(qkv + base + 256);
        int k8 = kq >> 1, kh = kq & 1;
        int qa = ((row >> 4) * 2 + ((row >> 3) & 1)) * 264 + k8 * 66 + (row & 7) * 8 + kh;
        QA[qa + 0] = f2tf(qv.x * scale); QA[qa + 2] = f2tf(qv.y * scale);
        QA[qa + 4] = f2tf(qv.z * scale); QA[qa + 6] = f2tf(qv.w * scale);
        int kb = (row >> 3) * 264 + k8 * 66 + (row & 7) * 8 + kh;
        KB[kb + 0] = f2tf(kv.x); KB[kb + 2] = f2tf(kv.y);
        KB[kb + 4] = f2tf(kv.z); KB[kb + 6] = f2tf(kv.w);
        int vb = (kq >> 1) * 1064 + (row >> 3) * 66 + ((kq & 1) * 4) * 8 +
                 ((row >> 2) & 1) + 2 * (row & 3);
        VB[vb + 0]  = f2tf(vv.x); VB[vb + 8]  = f2tf(vv.y);
        VB[vb + 16] = f2tf(vv.z); VB[vb + 24] = f2tf(vv.w);
    }
    __syncthreads();

    float acc[16][4];
#pragma unroll
    for (int nt = 0; nt < 16; nt++)
#pragma unroll
        for (int i = 0; i < 4; i++) acc[nt][i] = 0.f;

#pragma unroll
    for (int k8 = 0; k8 < 4; k8++) {
        int abase = (w * 2) * 264 + k8 * 66 + lane * 2;
        uint2 q0 = *reinterpret_cast<const uint2*>(&QA[abase]);
        uint2 q1 = *reinterpret_cast<const uint2*>(&QA[abase + 264]);
#pragma unroll
        for (int nt = 0; nt < 16; nt++) {
            uint2 b = *reinterpret_cast<const uint2*>(&KB[nt * 264 + k8 * 66 + lane * 2]);
            MMA_TF32(acc[nt], q0.x, q1.x, q0.y, q1.y, b.x, b.y);
        }
    }

    const int qtile = w & 3;
    float m0 = -1e30f, m1 = -1e30f;
#pragma unroll
    for (int nt = 0; nt < 16; nt++) {
        float4 p = *reinterpret_cast<const float4*>(psh + ((qtile * 8 + (nt & 7)) * 32 + lane) * 4);
        acc[nt][0] += p.x; acc[nt][1] += p.y;
        acc[nt][2] += p.z; acc[nt][3] += p.w;
        m0 = fmaxf(m0, fmaxf(acc[nt][0], acc[nt][1]));
        m1 = fmaxf(m1, fmaxf(acc[nt][2], acc[nt][3]));
    }
    m0 = fmaxf(m0, __shfl_xor_sync(0xffffffffu, m0, 1));
    m0 = fmaxf(m0, __shfl_xor_sync(0xffffffffu, m0, 2));
    m1 = fmaxf(m1, __shfl_xor_sync(0xffffffffu, m1, 1));
    m1 = fmaxf(m1, __shfl_xor_sync(0xffffffffu, m1, 2));

    float l0 = 0.f, l1 = 0.f;
#pragma unroll
    for (int nt = 0; nt < 16; nt++) {
        acc[nt][0] = __expf(acc[nt][0] - m0);
        acc[nt][1] = __expf(acc[nt][1] - m0);
        acc[nt][2] = __expf(acc[nt][2] - m1);
        acc[nt][3] = __expf(acc[nt][3] - m1);
        l0 += acc[nt][0] + acc[nt][1];
        l1 += acc[nt][2] + acc[nt][3];
    }
    l0 += __shfl_xor_sync(0xffffffffu, l0, 1);
    l0 += __shfl_xor_sync(0xffffffffu, l0, 2);
    l1 += __shfl_xor_sync(0xffffffffu, l1, 1);
    l1 += __shfl_xor_sync(0xffffffffu, l1, 2);
    float inv0 = 1.0f / l0, inv1 = 1.0f / l1;

#pragma unroll
    for (int nt = 0; nt < 16; nt++)
#pragma unroll
        for (int i = 0; i < 4; i++)
            acc[nt][i] = __uint_as_float(f2tf(acc[nt][i]));

    float oacc[4][4];
#pragma unroll
    for (int n8 = 0; n8 < 4; n8++)
#pragma unroll
        for (int i = 0; i < 4; i++) oacc[n8][i] = 0.f;

    const int s0 = (lane & 28) | (t >> 1);
    const int s1 = s0 + 2;
    const bool oddt = (t & 1);
#pragma unroll
    for (int c = 0; c < 16; c++) {
        float e0 = __shfl_sync(0xffffffffu, acc[c][0], s0);
        float o0 = __shfl_sync(0xffffffffu, acc[c][1], s0);
        float e1 = __shfl_sync(0xffffffffu, acc[c][2], s0);
        float o1 = __shfl_sync(0xffffffffu, acc[c][3], s0);
        float e2 = __shfl_sync(0xffffffffu, acc[c][0], s1);
        float o2 = __shfl_sync(0xffffffffu, acc[c][1], s1);
        float e3 = __shfl_sync(0xffffffffu, acc[c][2], s1);
        float o3 = __shfl_sync(0xffffffffu, acc[c][3], s1);
        unsigned a0 = __float_as_uint(oddt ? o0 : e0);
        unsigned a1 = __float_as_uint(oddt ? o1 : e1);
        unsigned a2 = __float_as_uint(oddt ? o2 : e2);
        unsigned a3 = __float_as_uint(oddt ? o3 : e3);
#pragma unroll
        for (int n8 = 0; n8 < 4; n8++) {
            uint2 b = *reinterpret_cast<const uint2*>(&VB[n8 * 1064 + c * 66 + lane * 2]);
            MMA_TF32(oacc[n8], a0, a1, a2, a3, b.x, b.y);
        }
    }

    int r0 = win * 128 + w * 16 + g;
#pragma unroll
    for (int n8 = 0; n8 < 4; n8++) {
        int col = head * 32 + n8 * 8 + t * 2;
        attout[(size_t)r0 * 128 + col]           = round_tf(oacc[n8][0] * inv0);
        attout[(size_t)r0 * 128 + col + 1]       = round_tf(oacc[n8][1] * inv0);
        attout[(size_t)(r0 + 8) * 128 + col]     = round_tf(oacc[n8][2] * inv1);
        attout[(size_t)(r0 + 8) * 128 + col + 1] = round_tf(oacc[n8][3] * inv1);
    }
}

// ---------------- proj + scatter + residual + LN2: A staged once, B from L2 ----------------
#define PROJ_SMEM (16896 * 4)
__global__ __launch_bounds__(256) void projln_kernel(
    const float* __restrict__ attn, const unsigned* __restrict__ Wp_,
    const float* __restrict__ bias, const float* __restrict__ res,
    float* __restrict__ xres, float* __restrict__ xln,
    const float* __restrict__ gw, const float* __restrict__ bw) {
    extern __shared__ unsigned sm[];
    unsigned* OA = sm;
    __shared__ float smS[128][2], smQ[128][2];

    const int win = blockIdx.x;
    const int tid = threadIdx.x;
    const int lane = tid & 31, w = tid >> 5;
    const int g = lane >> 2, t = lane & 3;
    const int wm = w >> 1, wn = w & 1;

    // stage A (attn out, already tf32 bits), A-frag layout, whole K=128
#pragma unroll
    for (int it = 0; it < 16; it++) {
        int c = tid + it * 256;
        int row = c >> 5, kq = c & 31;
        uint4 v = *reinterpret_cast<const uint4*>(attn + ((size_t)(win * 128 + row)) * 128 + kq * 4);
        int sts = ((row >> 4) * 2 + ((row >> 3) & 1)) * 1056 + (kq >> 1) * 66 + (row & 7) * 8 + (kq & 1);
        OA[sts + 0] = v.x; OA[sts + 2] = v.y; OA[sts + 4] = v.z; OA[sts + 6] = v.w;
    }
    __syncthreads();

    const uint2* Wp2 = reinterpret_cast<const uint2*>(Wp_);
    float acc2[2][8][4];
#pragma unroll
    for (int mi = 0; mi < 2; mi++)
#pragma unroll
        for (int ni = 0; ni < 8; ni++)
#pragma unroll
            for (int q = 0; q < 4; q++) acc2[mi][ni][q] = 0.f;

#pragma unroll
    for (int k8 = 0; k8 < 16; k8++) {
        unsigned a[2][4];
#pragma unroll
        for (int mi = 0; mi < 2; mi++) {
            int base = ((wm * 2 + mi) * 2) * 1056 + k8 * 66 + lane * 2;
            uint2 q0 = *reinterpret_cast<const uint2*>(&OA[base]);
            uint2 q1 = *reinterpret_cast<const uint2*>(&OA[base + 1056]);
            a[mi][0] = q0.x; a[mi][2] = q0.y;
            a[mi][1] = q1.x; a[mi][3] = q1.y;
        }
#pragma unroll
        for (int ni = 0; ni < 8; ni++) {
            uint2 b = Wp2[((wn * 8 + ni) * 16 + k8) * 32 + lane];
#pragma unroll
            for (int mi = 0; mi < 2; mi++)
                MMA_TF32(acc2[mi][ni], a[mi][0], a[mi][1], a[mi][2], a[mi][3], b.x, b.y);
        }
    }

#pragma unroll
    for (int mi = 0; mi < 2; mi++) {
#pragma unroll
        for (int rh = 0; rh < 2; rh++) {
            int lrow = wm * 32 + mi * 16 + g + rh * 8;
            int xrow = perm_row(win * 128 + lrow);
            float v[16];
            float s = 0.f, q = 0.f;
#pragma unroll
            for (int ni = 0; ni < 8; ni++) {
                int cc = wn * 64 + ni * 8 + t * 2;
#pragma unroll
                for (int ch = 0; ch < 2; ch++) {
                    float x = acc2[mi][ni][rh * 2 + ch] + bias[cc + ch] +
                              res[(size_t)xrow * 128 + cc + ch];
                    xres[(size_t)xrow * 128 + cc + ch] = x;
                    v[ni * 2 + ch] = x;
                    s += x; q += x * x;
                }
            }
            s += __shfl_xor_sync(0xffffffffu, s, 1);
            s += __shfl_xor_sync(0xffffffffu, s, 2);
            q += __shfl_xor_sync(0xffffffffu, q, 1);
            q += __shfl_xor_sync(0xffffffffu, q, 2);
            if (t == 0) { smS[lrow][wn] = s; smQ[lrow][wn] = q; }
            __syncthreads();
            float S = smS[lrow][0] + smS[lrow][1];
            float Q = smQ[lrow][0] + smQ[lrow][1];
            float mu = S * (1.f / 128.f);
            float var = Q * (1.f / 128.f) - mu * mu;
            float rs = rsqrtf(var + 1e-5f);
#pragma unroll
            for (int ni = 0; ni < 8; ni++) {
                int cc = wn * 64 + ni * 8 + t * 2;
#pragma unroll
                for (int ch = 0; ch < 2; ch++) {
                    xln[(size_t)xrow * 128 + cc + ch] =
                        round_tf((v[ni * 2 + ch] - mu) * rs * gw[cc + ch] + bw[cc + ch]);
                }
            }
        }
    }
}

// ---------------- fused MLP: fc1 + gelu + fc2 + residual + LN1 (unchanged) ----------------
#define MLP_SMEM (42240 * 4)
__global__ __launch_bounds__(512) void mlp_kernel(
    const float* __restrict__ xln, const unsigned* __restrict__ W1g4_,
    const unsigned* __restrict__ W2g4_,
    const float* __restrict__ b1, const float* __restrict__ b2,
    const float* __restrict__ res, float* __restrict__ out,
    const float* __restrict__ gw, const float* __restrict__ bw) {
    extern __shared__ unsigned sm[];
    unsigned* XA = sm;
    unsigned* W1 = sm + 16896;
    unsigned* W2 = sm + 25344;
    unsigned* HH = sm + 33792;
    __shared__ float smS[128][4], smQ[128][4];

    const uint4* W1g = reinterpret_cast<const uint4*>(W1g4_);
    const uint4* W2g = reinterpret_cast<const uint4*>(W2g4_);

    const int tid = threadIdx.x;
    const int lane = tid & 31;
    const int wid = tid >> 5;
    const int wm = wid >> 2, wn = wid & 3;
    const int g = lane >> 2, t = lane & 3;
    const int bm = blockIdx.x * 128;

#pragma unroll
    for (int it = 0; it < 8; it++) {
        int c = tid + it * 512;
        int row = c >> 5, kq = c & 31;
        uint4 v = *reinterpret_cast<const uint4*>(xln + (size_t)(bm + row) * 128 + kq * 4);
        int sts = ((row >> 4) * 2 + ((row >> 3) & 1)) * 1056 + (kq >> 1) * 66 + (row & 7) * 8 + (kq & 1);
        XA[sts + 0] = v.x; XA[sts + 2] = v.y; XA[sts + 4] = v.z; XA[sts + 6] = v.w;
    }

    int w1src[4], w2src[4], w1st[4], w2st[4];
#pragma unroll
    for (int it = 0; it < 4; it++) {
        int e = tid + it * 512;
        int n = e >> 5, kq = e & 31;
        w1src[it] = n * 32 + kq;
        w1st[it] = (n >> 3) * 1056 + (kq >> 1) * 66 + (n & 7) * 8 + (kq & 1);
        int n2 = e >> 4, klq = e & 15;
        w2src[it] = n2 * 128 + klq;
        w2st[it] = (n2 >> 3) * 528 + (klq >> 1) * 66 + (n2 & 7) * 8 + (klq & 1);
    }

    {
        uint4 v[4];
#pragma unroll
        for (int it = 0; it < 4; it++) v[it] = W1g[w1src[it]];
#pragma unroll
        for (int it = 0; it < 4; it++) {
            W1[w1st[it] + 0] = v[it].x; W1[w1st[it] + 2] = v[it].y;
            W1[w1st[it] + 4] = v[it].z; W1[w1st[it] + 6] = v[it].w;
        }
    }
    __syncthreads();

    float acco[2][4][4];
#pragma unroll
    for (int mi = 0; mi < 2; mi++)
#pragma unroll
        for (int ni = 0; ni < 4; ni++)
#pragma unroll
            for (int c = 0; c < 4; c++) acco[mi][ni][c] = 0.f;

    for (int c = 0; c < 8; c++) {
        uint4 w2v[4];
#pragma unroll
        for (int it = 0; it < 4; it++) w2v[it] = W2g[w2src[it] + c * 16];

        float accs[2][2][4];
#pragma unroll
        for (int mi = 0; mi < 2; mi++)
#pragma unroll
            for (int ni = 0; ni < 2; ni++)
#pragma unroll
                for (int q = 0; q < 4; q++) accs[mi][ni][q] = 0.f;
#pragma unroll
        for (int k8 = 0; k8 < 16; k8++) {
            unsigned a[2][4], b[2][2];
#pragma unroll
            for (int mi = 0; mi < 2; mi++) {
                int base = ((wm * 2 + mi) * 2) * 1056 + k8 * 66 + lane * 2;
                uint2 q0 = *reinterpret_cast<const uint2*>(&XA[base]);
                uint2 q1 = *reinterpret_cast<const uint2*>(&XA[base + 1056]);
                a[mi][0] = q0.x; a[mi][2] = q0.y;
                a[mi][1] = q1.x; a[mi][3] = q1.y;
            }
#pragma unroll
            for (int ni = 0; ni < 2; ni++) {
                uint2 q = *reinterpret_cast<const uint2*>(&W1[(wn * 2 + ni) * 1056 + k8 * 66 + lane * 2]);
                b[ni][0] = q.x; b[ni][1] = q.y;
            }
#pragma unroll
            for (int mi = 0; mi < 2; mi++)
#pragma unroll
                for (int ni = 0; ni < 2; ni++)
                    MMA_TF32(accs[mi][ni], a[mi][0], a[mi][1], a[mi][2], a[mi][3],
                             b[ni][0], b[ni][1]);
        }

#pragma unroll
        for (int it = 0; it < 4; it++) {
            W2[w2st[it] + 0] = w2v[it].x; W2[w2st[it] + 2] = w2v[it].y;
            W2[w2st[it] + 4] = w2v[it].z; W2[w2st[it] + 6] = w2v[it].w;
        }

#pragma unroll
        for (int mi = 0; mi < 2; mi++) {
            int rgR = (wm * 2 + mi) * 2;
#pragma unroll
            for (int ni = 0; ni < 2; ni++) {
                int kl0 = wn * 16 + ni * 8 + t * 2;
                float bb0 = b1[c * 64 + kl0], bb1 = b1[c * 64 + kl0 + 1];
#pragma unroll
                for (int rh = 0; rh < 2; rh++) {
#pragma unroll
                    for (int ch = 0; ch < 2; ch++) {
                        float v = accs[mi][ni][rh * 2 + ch] + (ch ? bb1 : bb0);
                        v = 0.5f * v * (1.0f + erff(v * 0.7071067811865475f));
                        int k = kl0 + ch;
                        int addr = (rgR + rh) * 528 + (k >> 3) * 66 + g * 8 +
                                   ((k >> 2) & 1) + (k & 3) * 2;
                        HH[addr] = f2tf(v);
                    }
                }
            }
        }
        __syncthreads();

        uint4 w1v[4];
        if (c < 7) {
#pragma unroll
            for (int it = 0; it < 4; it++) w1v[it] = W1g[w1src[it] + (c + 1) * 2048];
        }

#pragma unroll
        for (int k8 = 0; k8 < 8; k8++) {
            unsigned a[2][4], b[4][2];
#pragma unroll
            for (int mi = 0; mi < 2; mi++) {
                int base = ((wm * 2 + mi) * 2) * 528 + k8 * 66 + lane * 2;
                uint2 q0 = *reinterpret_cast<const uint2*>(&HH[base]);
                uint2 q1 = *reinterpret_cast<const uint2*>(&HH[base + 528]);
                a[mi][0] = q0.x; a[mi][2] = q0.y;
                a[mi][1] = q1.x; a[mi][3] = q1.y;
            }
#pragma unroll
            for (int ni = 0; ni < 4; ni++) {
                uint2 q = *reinterpret_cast<const uint2*>(&W2[(wn * 4 + ni) * 528 + k8 * 66 + lane * 2]);
                b[ni][0] = q.x; b[ni][1] = q.y;
            }
#pragma unroll
            for (int mi = 0; mi < 2; mi++)
#pragma unroll
                for (int ni = 0; ni < 4; ni++)
                    MMA_TF32(acco[mi][ni], a[mi][0], a[mi][1], a[mi][2], a[mi][3],
                             b[ni][0], b[ni][1]);
        }

        if (c < 7) {
#pragma unroll
            for (int it = 0; it < 4; it++) {
                W1[w1st[it] + 0] = w1v[it].x; W1[w1st[it] + 2] = w1v[it].y;
                W1[w1st[it] + 4] = w1v[it].z; W1[w1st[it] + 6] = w1v[it].w;
            }
        }
        __syncthreads();
    }

#pragma unroll
    for (int mi = 0; mi < 2; mi++) {
#pragma unroll
        for (int rh = 0; rh < 2; rh++) {
            int lrow = wm * 32 + mi * 16 + g + rh * 8;
            int r = bm + lrow;
            float v[8];
            float s = 0.f, q = 0.f;
#pragma unroll
            for (int ni = 0; ni < 4; ni++) {
                int cc = wn * 32 + ni * 8 + t * 2;
#pragma unroll
                for (int ch = 0; ch < 2; ch++) {
                    float x = acco[mi][ni][rh * 2 + ch] + b2[cc + ch] +
                              res[(size_t)r * 128 + cc + ch];
                    v[ni * 2 + ch] = x;
                    s += x; q += x * x;
                }
            }
            s += __shfl_xor_sync(0xffffffffu, s, 1);
            s += __shfl_xor_sync(0xffffffffu, s, 2);
            q += __shfl_xor_sync(0xffffffffu, q, 1);
            q += __shfl_xor_sync(0xffffffffu, q, 2);
            if (t == 0) { smS[lrow][wn] = s; smQ[lrow][wn] = q; }
            __syncthreads();
            float S = smS[lrow][0] + smS[lrow][1] + smS[lrow][2] + smS[lrow][3];
            float Q = smQ[lrow][0] + smQ[lrow][1] + smQ[lrow][2] + smQ[lrow][3];
            float mu = S * (1.f / 128.f);
            float var = Q * (1.f / 128.f) - mu * mu;
            float rs = rsqrtf(var + 1e-5f);
#pragma unroll
            for (int ni = 0; ni < 4; ni++) {
                int cc = wn * 32 + ni * 8 + t * 2;
#pragma unroll
                for (int ch = 0; ch < 2; ch++) {
                    out[(size_t)r * 128 + cc + ch] =
                        (v[ni * 2 + ch] - mu) * rs * gw[cc + ch] + bw[cc + ch];
                }
            }
        }
    }
}

// ---------------- launch ----------------
extern "C" void kernel_launch(void* const* d_in, const int* in_sizes, int n_in,
                              void* d_out, int out_size) {
    const float* x_v    = (const float*)d_in[0];
    const float* qkv_w  = (const float*)d_in[1];
    const float* qkv_b  = (const float*)d_in[2];
    const float* proj_w = (const float*)d_in[3];
    const float* proj_b = (const float*)d_in[4];
    const float* rpb    = (const float*)d_in[5];
    const float* n1w    = (const float*)d_in[6];
    const float* n1b    = (const float*)d_in[7];
    const float* n2w    = (const float*)d_in[8];
    const float* n2b    = (const float*)d_in[9];
    const float* fc1w   = (const float*)d_in[10];
    const float* fc1b   = (const float*)d_in[11];
    const float* fc2w   = (const float*)d_in[12];
    const float* fc2b   = (const float*)d_in[13];
    float* out = (float*)d_out;

    float *qkvb, *attn, *xln, *xres, *ps;
    unsigned* wtf;
    cudaGetSymbolAddress((void**)&qkvb, g_qkv);
    cudaGetSymbolAddress((void**)&attn, g_attn);
    cudaGetSymbolAddress((void**)&xln,  g_xln);
    cudaGetSymbolAddress((void**)&xres, g_xres);
    cudaGetSymbolAddress((void**)&ps,   g_ps);
    cudaGetSymbolAddress((void**)&wtf,  g_wtf);

    cudaFuncSetAttribute(qkv_kernel, cudaFuncAttributeMaxDynamicSharedMemorySize, QKV_SMEM);
    cudaFuncSetAttribute(attn_kernel, cudaFuncAttributeMaxDynamicSharedMemorySize, SMEM_ATTN);
    cudaFuncSetAttribute(projln_kernel, cudaFuncAttributeMaxDynamicSharedMemorySize, PROJ_SMEM);
    cudaFuncSetAttribute(mlp_kernel, cudaFuncAttributeMaxDynamicSharedMemorySize, MLP_SMEM);

    // 0. weight conversion + rpb/mask table
    cvt_weights<<<768, 256>>>(qkv_w, proj_w, fc1w, fc2w, wtf);
    ps_kernel<<<dim3(256, 4), 256>>>(rpb, ps);
    // 1. qkv = gather(x_v) @ qkv_w^T + b
    qkv_kernel<<<1024, 512, QKV_SMEM>>>(x_v, wtf, qkv_b, qkvb);
    // 2. window attention (ps table from gmem)
    attn_kernel<<<dim3(1024, HEADS), 256, SMEM_ATTN>>>(qkvb, ps, attn);
    // 3. proj + scatter + residual + LN2
    projln_kernel<<<1024, 256, PROJ_SMEM>>>(attn, wtf + 49152, proj_b,
                                            x_v, xres, xln, n2w, n2b);
    // 4. fused MLP -> final output
    mlp_kernel<<<1024, 512, MLP_SMEM>>>(xln, wtf + 65536, wtf + 131072,
                                        fc1b, fc2b, xres, out, n1w, n1b);
}

// round 10
// speedup vs baseline: 1.8406x; 1.0318x over previous
#include <cuda_runtime.h>
#include <math.h>

// ---------------- problem constants ----------------
#define M_TOT 131072
#define HEADS 4

// ---------------- scratch ----------------
__device__ float g_qkv [(size_t)M_TOT * 3 * 128];
__device__ float g_attn[(size_t)M_TOT * 128];
__device__ float g_xln [(size_t)M_TOT * 128];
__device__ float g_xres[(size_t)M_TOT * 128];
__device__ float g_ps  [256 * 4 * 4096];     // rpb+mask, C-frag order per (winmod, head)
__device__ unsigned g_wtf[196608];           // tf32 weights: qkv(rm)|proj(frag)|fc1(rm)|fc2(rm)

__device__ __forceinline__ int perm_row(int r) {
    int b_ = r >> 7, tt = r & 127;
    int b = b_ >> 8, w = b_ & 255;
    int wh = w >> 4, ww = w & 15;
    int t = tt >> 6, n = tt & 63;
    int i = n >> 3, j = n & 7;
    int oh = (wh * 8 + i + 4) & 127;
    int ow = (ww * 8 + j + 4) & 127;
    return (b * 2 + t) * 16384 + oh * 128 + ow;
}

__device__ __forceinline__ unsigned f2tf(float f) {
    unsigned u;
    asm("cvt.rna.tf32.f32 %0, %1;" : "=r"(u) : "f"(f));
    return u;
}
__device__ __forceinline__ float round_tf(float f) { return __uint_as_float(f2tf(f)); }

#define MMA_TF32(d, a0, a1, a2, a3, b0, b1)                                            \
    asm volatile(                                                                      \
        "mma.sync.aligned.m16n8k8.row.col.f32.tf32.tf32.f32 "                          \
        "{%0,%1,%2,%3},{%4,%5,%6,%7},{%8,%9},{%0,%1,%2,%3};"                           \
        : "+f"(d[0]), "+f"(d[1]), "+f"(d[2]), "+f"(d[3])                               \
        : "r"(a0), "r"(a1), "r"(a2), "r"(a3), "r"(b0), "r"(b1))

// ---------------- weight pre-conversion ----------------
__global__ void cvt_weights(const float* __restrict__ qkv_w, const float* __restrict__ proj_w,
                            const float* __restrict__ fc1_w, const float* __restrict__ fc2_w,
                            unsigned* __restrict__ wtf) {
    int i = blockIdx.x * 256 + threadIdx.x;
    if (i < 49152) { wtf[i] = f2tf(qkv_w[i]); return; }
    if (i < 65536) {
        int j = i - 49152;
        int pair = j >> 1, half = j & 1;
        int lane = pair & 31, k8 = (pair >> 5) & 15, n8 = pair >> 9;
        int g = lane >> 2, t = lane & 3;
        int n = n8 * 8 + g, k = k8 * 8 + t + (half ? 4 : 0);
        wtf[i] = f2tf(proj_w[n * 128 + k]);
        return;
    }
    if (i < 131072) { wtf[i] = f2tf(fc1_w[i - 65536]); return; }
    wtf[i] = f2tf(fc2_w[i - 131072]);
}

// ---------------- rpb + shift-mask table in C-frag order ----------------
__global__ void ps_kernel(const float* __restrict__ rpb, float* __restrict__ ps) {
    int wwin = blockIdx.x;
    int head = blockIdx.y;
    int wh = wwin >> 4, ww = wwin & 15;
    int tid = threadIdx.x;
    float* dst = ps + (size_t)(wwin * 4 + head) * 4096;
#pragma unroll
    for (int it = 0; it < 16; it++) {
        int e = tid + it * 256;
        int qn = e >> 6, kn = e & 63;
        int qi2 = qn >> 3, qj = qn & 7, ki = kn >> 3, kj = kn & 7;
        int rel = (qi2 - ki + 7) * 15 + (qj - kj + 7);
        float v = rpb[rel * HEADS + head];
        int gqh = wh * 8 + qi2, gqw = ww * 8 + qj;
        int gkh = wh * 8 + ki,  gkw = ww * 8 + kj;
        int rq = (gqh < 120 ? 0 : (gqh < 124 ? 1 : 2)) * 3 + (gqw < 120 ? 0 : (gqw < 124 ? 1 : 2));
        int rk = (gkh < 120 ? 0 : (gkh < 124 ? 1 : 2)) * 3 + (gkw < 120 ? 0 : (gkw < 124 ? 1 : 2));
        if (rq != rk) v -= 100.0f;
        int qtile = qn >> 4, ntile = kn >> 3;
        int ln = (qn & 7) * 4 + ((kn & 7) >> 1);
        int reg = ((qn >> 3) & 1) * 2 + (kn & 1);
        dst[((qtile * 8 + ntile) * 32 + ln) * 4 + reg] = v;
    }
}

// ---------------- qkv GEMM: A staged once, weights streamed ----------------
// outputs pre-rounded tf32 (Q pre-scaled by 1/sqrt(32)) so attn stages raw bits
#define QKV_SMEM ((16896 + 16896) * 4)
__global__ __launch_bounds__(512) void qkv_kernel(
    const float* __restrict__ xv, const unsigned* __restrict__ Wq_,
    const float* __restrict__ bias, float* __restrict__ out) {
    extern __shared__ unsigned sm[];
    unsigned* XA = sm;
    unsigned* WB = sm + 16896;

    const uint4* Wg = reinterpret_cast<const uint4*>(Wq_);
    const int tid = threadIdx.x;
    const int lane = tid & 31;
    const int wid = tid >> 5;
    const int wm = wid >> 2, wn = wid & 3;
    const int g = lane >> 2, t = lane & 3;
    const int bm = blockIdx.x * 128;
    const float scale = 0.17677669529663687f;

#pragma unroll
    for (int it = 0; it < 8; it++) {
        int c = tid + it * 512;
        int row = c >> 5, kq = c & 31;
        int src = perm_row(bm + row);
        float4 v = *reinterpret_cast<const float4*>(xv + (size_t)src * 128 + kq * 4);
        int sts = ((row >> 4) * 2 + ((row >> 3) & 1)) * 1056 + (kq >> 1) * 66 + (row & 7) * 8 + (kq & 1);
        XA[sts + 0] = f2tf(v.x); XA[sts + 2] = f2tf(v.y);
        XA[sts + 4] = f2tf(v.z); XA[sts + 6] = f2tf(v.w);
    }

    int wsrc[4], wst[4];
#pragma unroll
    for (int it = 0; it < 4; it++) {
        int e = tid + it * 512;
        int n = e >> 5, kq = e & 31;
        wsrc[it] = n * 32 + kq;
        wst[it] = (n >> 3) * 1056 + (kq >> 1) * 66 + (n & 7) * 8 + (kq & 1);
    }
    {
        uint4 v[4];
#pragma unroll
        for (int it = 0; it < 4; it++) v[it] = Wg[wsrc[it]];
#pragma unroll
        for (int it = 0; it < 4; it++) {
            WB[wst[it] + 0] = v[it].x; WB[wst[it] + 2] = v[it].y;
            WB[wst[it] + 4] = v[it].z; WB[wst[it] + 6] = v[it].w;
        }
    }
    __syncthreads();

    int p = 0;
    for (int c = 0; c < 6; c++) {
        uint4 wv[4];
        if (c < 5) {
#pragma unroll
            for (int it = 0; it < 4; it++) wv[it] = Wg[wsrc[it] + (c + 1) * 2048];
        }
        unsigned* Wp = WB + p * 8448;

        float accs[2][2][4];
#pragma unroll
        for (int mi = 0; mi < 2; mi++)
#pragma unroll
            for (int ni = 0; ni < 2; ni++)
#pragma unroll
                for (int q = 0; q < 4; q++) accs[mi][ni][q] = 0.f;

#pragma unroll
        for (int k8 = 0; k8 < 16; k8++) {
            unsigned a[2][4], b[2][2];
#pragma unroll
            for (int mi = 0; mi < 2; mi++) {
                int base = ((wm * 2 + mi) * 2) * 1056 + k8 * 66 + lane * 2;
                uint2 q0 = *reinterpret_cast<const uint2*>(&XA[base]);
                uint2 q1 = *reinterpret_cast<const uint2*>(&XA[base + 1056]);
                a[mi][0] = q0.x; a[mi][2] = q0.y;
                a[mi][1] = q1.x; a[mi][3] = q1.y;
            }
#pragma unroll
            for (int ni = 0; ni < 2; ni++) {
                uint2 q = *reinterpret_cast<const uint2*>(&Wp[(wn * 2 + ni) * 1056 + k8 * 66 + lane * 2]);
                b[ni][0] = q.x; b[ni][1] = q.y;
            }
#pragma unroll
            for (int mi = 0; mi < 2; mi++)
#pragma unroll
                for (int ni = 0; ni < 2; ni++)
                    MMA_TF32(accs[mi][ni], a[mi][0], a[mi][1], a[mi][2], a[mi][3],
                             b[ni][0], b[ni][1]);
        }

        float sc = (c < 2) ? scale : 1.0f;   // chunks 0,1 = Q columns
#pragma unroll
        for (int mi = 0; mi < 2; mi++) {
#pragma unroll
            for (int rh = 0; rh < 2; rh++) {
                int r = bm + wm * 32 + mi * 16 + g + rh * 8;
#pragma unroll
                for (int ni = 0; ni < 2; ni++) {
                    int col = c * 64 + wn * 16 + ni * 8 + t * 2;
                    float2 o;
                    o.x = round_tf((accs[mi][ni][rh * 2 + 0] + bias[col]) * sc);
                    o.y = round_tf((accs[mi][ni][rh * 2 + 1] + bias[col + 1]) * sc);
                    *reinterpret_cast<float2*>(out + (size_t)r * 384 + col) = o;
                }
            }
        }

        if (c < 5) {
            unsigned* Wn = WB + (p ^ 1) * 8448;
#pragma unroll
            for (int it = 0; it < 4; it++) {
                Wn[wst[it] + 0] = wv[it].x; Wn[wst[it] + 2] = wv[it].y;
                Wn[wst[it] + 4] = wv[it].z; Wn[wst[it] + 6] = wv[it].w;
            }
            p ^= 1;
        }
        __syncthreads();
    }
}

// ---------------- tensor-core window attention (raw staging, no cvt) ----------------
#define SM_QA 0
#define SM_KB 4224
#define SM_VB 8448
#define SMEM_ATTN (12704 * 4)

__global__ __launch_bounds__(256) void attn_kernel(const float* __restrict__ qkv,
                                                   const float* __restrict__ ps,
                                                   float* __restrict__ attout) {
    extern __shared__ unsigned sm[];
    unsigned* QA = sm + SM_QA;
    unsigned* KB = sm + SM_KB;
    unsigned* VB = sm + SM_VB;

    const int win = blockIdx.x, head = blockIdx.y;
    const int tid = threadIdx.x;
    const int lane = tid & 31, w = tid >> 5;
    const int g = lane >> 2, t = lane & 3;
    const float* psh = ps + (size_t)((win & 255) * 4 + head) * 4096;
    const uint4* qkv4 = reinterpret_cast<const uint4*>(qkv);

#pragma unroll
    for (int it = 0; it < 4; it++) {
        int c = tid + it * 256;
        int row = c >> 3, kq = c & 7;
        size_t base4 = ((size_t)(win * 128 + row)) * 96 + head * 8 + kq;
        uint4 qv = qkv4[base4];
        uint4 kv = qkv4[base4 + 32];
        uint4 vv = qkv4[base4 + 64];
        int k8 = kq >> 1, kh = kq & 1;
        int qa = ((row >> 4) * 2 + ((row >> 3) & 1)) * 264 + k8 * 66 + (row & 7) * 8 + kh;
        QA[qa + 0] = qv.x; QA[qa + 2] = qv.y; QA[qa + 4] = qv.z; QA[qa + 6] = qv.w;
        int kb = (row >> 3) * 264 + k8 * 66 + (row & 7) * 8 + kh;
        KB[kb + 0] = kv.x; KB[kb + 2] = kv.y; KB[kb + 4] = kv.z; KB[kb + 6] = kv.w;
        int vb = (kq >> 1) * 1064 + (row >> 3) * 66 + ((kq & 1) * 4) * 8 +
                 ((row >> 2) & 1) + 2 * (row & 3);
        VB[vb + 0]  = vv.x; VB[vb + 8]  = vv.y;
        VB[vb + 16] = vv.z; VB[vb + 24] = vv.w;
    }
    __syncthreads();

    float acc[16][4];
#pragma unroll
    for (int nt = 0; nt < 16; nt++)
#pragma unroll
        for (int i = 0; i < 4; i++) acc[nt][i] = 0.f;

#pragma unroll
    for (int k8 = 0; k8 < 4; k8++) {
        int abase = (w * 2) * 264 + k8 * 66 + lane * 2;
        uint2 q0 = *reinterpret_cast<const uint2*>(&QA[abase]);
        uint2 q1 = *reinterpret_cast<const uint2*>(&QA[abase + 264]);
#pragma unroll
        for (int nt = 0; nt < 16; nt++) {
            uint2 b = *reinterpret_cast<const uint2*>(&KB[nt * 264 + k8 * 66 + lane * 2]);
            MMA_TF32(acc[nt], q0.x, q1.x, q0.y, q1.y, b.x, b.y);
        }
    }

    const int qtile = w & 3;
    float m0 = -1e30f, m1 = -1e30f;
#pragma unroll
    for (int nt = 0; nt < 16; nt++) {
        float4 p = *reinterpret_cast<const float4*>(psh + ((qtile * 8 + (nt & 7)) * 32 + lane) * 4);
        acc[nt][0] += p.x; acc[nt][1] += p.y;
        acc[nt][2] += p.z; acc[nt][3] += p.w;
        m0 = fmaxf(m0, fmaxf(acc[nt][0], acc[nt][1]));
        m1 = fmaxf(m1, fmaxf(acc[nt][2], acc[nt][3]));
    }
    m0 = fmaxf(m0, __shfl_xor_sync(0xffffffffu, m0, 1));
    m0 = fmaxf(m0, __shfl_xor_sync(0xffffffffu, m0, 2));
    m1 = fmaxf(m1, __shfl_xor_sync(0xffffffffu, m1, 1));
    m1 = fmaxf(m1, __shfl_xor_sync(0xffffffffu, m1, 2));

    float l0 = 0.f, l1 = 0.f;
#pragma unroll
    for (int nt = 0; nt < 16; nt++) {
        acc[nt][0] = __expf(acc[nt][0] - m0);
        acc[nt][1] = __expf(acc[nt][1] - m0);
        acc[nt][2] = __expf(acc[nt][2] - m1);
        acc[nt][3] = __expf(acc[nt][3] - m1);
        l0 += acc[nt][0] + acc[nt][1];
        l1 += acc[nt][2] + acc[nt][3];
    }
    l0 += __shfl_xor_sync(0xffffffffu, l0, 1);
    l0 += __shfl_xor_sync(0xffffffffu, l0, 2);
    l1 += __shfl_xor_sync(0xffffffffu, l1, 1);
    l1 += __shfl_xor_sync(0xffffffffu, l1, 2);
    float inv0 = 1.0f / l0, inv1 = 1.0f / l1;

#pragma unroll
    for (int nt = 0; nt < 16; nt++)
#pragma unroll
        for (int i = 0; i < 4; i++)
            acc[nt][i] = __uint_as_float(f2tf(acc[nt][i]));

    float oacc[4][4];
#pragma unroll
    for (int n8 = 0; n8 < 4; n8++)
#pragma unroll
        for (int i = 0; i < 4; i++) oacc[n8][i] = 0.f;

    const int s0 = (lane & 28) | (t >> 1);
    const int s1 = s0 + 2;
    const bool oddt = (t & 1);
#pragma unroll
    for (int c = 0; c < 16; c++) {
        float e0 = __shfl_sync(0xffffffffu, acc[c][0], s0);
        float o0 = __shfl_sync(0xffffffffu, acc[c][1], s0);
        float e1 = __shfl_sync(0xffffffffu, acc[c][2], s0);
        float o1 = __shfl_sync(0xffffffffu, acc[c][3], s0);
        float e2 = __shfl_sync(0xffffffffu, acc[c][0], s1);
        float o2 = __shfl_sync(0xffffffffu, acc[c][1], s1);
        float e3 = __shfl_sync(0xffffffffu, acc[c][2], s1);
        float o3 = __shfl_sync(0xffffffffu, acc[c][3], s1);
        unsigned a0 = __float_as_uint(oddt ? o0 : e0);
        unsigned a1 = __float_as_uint(oddt ? o1 : e1);
        unsigned a2 = __float_as_uint(oddt ? o2 : e2);
        unsigned a3 = __float_as_uint(oddt ? o3 : e3);
#pragma unroll
        for (int n8 = 0; n8 < 4; n8++) {
            uint2 b = *reinterpret_cast<const uint2*>(&VB[n8 * 1064 + c * 66 + lane * 2]);
            MMA_TF32(oacc[n8], a0, a1, a2, a3, b.x, b.y);
        }
    }

    int r0 = win * 128 + w * 16 + g;
#pragma unroll
    for (int n8 = 0; n8 < 4; n8++) {
        int col = head * 32 + n8 * 8 + t * 2;
        float2 o0, o1;
        o0.x = round_tf(oacc[n8][0] * inv0);
        o0.y = round_tf(oacc[n8][1] * inv0);
        o1.x = round_tf(oacc[n8][2] * inv1);
        o1.y = round_tf(oacc[n8][3] * inv1);
        *reinterpret_cast<float2*>(attout + (size_t)r0 * 128 + col) = o0;
        *reinterpret_cast<float2*>(attout + (size_t)(r0 + 8) * 128 + col) = o1;
    }
}

// ---------------- proj + scatter + residual + LN2: A staged once, B from L2 ----------------
#define PROJ_SMEM (16896 * 4)
__global__ __launch_bounds__(256) void projln_kernel(
    const float* __restrict__ attn, const unsigned* __restrict__ Wp_,
    const float* __restrict__ bias, const float* __restrict__ res,
    float* __restrict__ xres, float* __restrict__ xln,
    const float* __restrict__ gw, const float* __restrict__ bw) {
    extern __shared__ unsigned sm[];
    unsigned* OA = sm;
    __shared__ float smS[128][2], smQ[128][2];

    const int win = blockIdx.x;
    const int tid = threadIdx.x;
    const int lane = tid & 31, w = tid >> 5;
    const int g = lane >> 2, t = lane & 3;
    const int wm = w >> 1, wn = w & 1;

#pragma unroll
    for (int it = 0; it < 16; it++) {
        int c = tid + it * 256;
        int row = c >> 5, kq = c & 31;
        uint4 v = *reinterpret_cast<const uint4*>(attn + ((size_t)(win * 128 + row)) * 128 + kq * 4);
        int sts = ((row >> 4) * 2 + ((row >> 3) & 1)) * 1056 + (kq >> 1) * 66 + (row & 7) * 8 + (kq & 1);
        OA[sts + 0] = v.x; OA[sts + 2] = v.y; OA[sts + 4] = v.z; OA[sts + 6] = v.w;
    }
    __syncthreads();

    const uint2* Wp2 = reinterpret_cast<const uint2*>(Wp_);
    float acc2[2][8][4];
#pragma unroll
    for (int mi = 0; mi < 2; mi++)
#pragma unroll
        for (int ni = 0; ni < 8; ni++)
#pragma unroll
            for (int q = 0; q < 4; q++) acc2[mi][ni][q] = 0.f;

#pragma unroll
    for (int k8 = 0; k8 < 16; k8++) {
        unsigned a[2][4];
#pragma unroll
        for (int mi = 0; mi < 2; mi++) {
            int base = ((wm * 2 + mi) * 2) * 1056 + k8 * 66 + lane * 2;
            uint2 q0 = *reinterpret_cast<const uint2*>(&OA[base]);
            uint2 q1 = *reinterpret_cast<const uint2*>(&OA[base + 1056]);
            a[mi][0] = q0.x; a[mi][2] = q0.y;
            a[mi][1] = q1.x; a[mi][3] = q1.y;
        }
#pragma unroll
        for (int ni = 0; ni < 8; ni++) {
            uint2 b = Wp2[((wn * 8 + ni) * 16 + k8) * 32 + lane];
#pragma unroll
            for (int mi = 0; mi < 2; mi++)
                MMA_TF32(acc2[mi][ni], a[mi][0], a[mi][1], a[mi][2], a[mi][3], b.x, b.y);
        }
    }

#pragma unroll
    for (int mi = 0; mi < 2; mi++) {
#pragma unroll
        for (int rh = 0; rh < 2; rh++) {
            int lrow = wm * 32 + mi * 16 + g + rh * 8;
            int xrow = perm_row(win * 128 + lrow);
            float v[16];
            float s = 0.f, q = 0.f;
#pragma unroll
            for (int ni = 0; ni < 8; ni++) {
                int cc = wn * 64 + ni * 8 + t * 2;
                float2 rr = *reinterpret_cast<const float2*>(res + (size_t)xrow * 128 + cc);
                float x0 = acc2[mi][ni][rh * 2 + 0] + bias[cc] + rr.x;
                float x1 = acc2[mi][ni][rh * 2 + 1] + bias[cc + 1] + rr.y;
                *reinterpret_cast<float2*>(xres + (size_t)xrow * 128 + cc) = make_float2(x0, x1);
                v[ni * 2 + 0] = x0; v[ni * 2 + 1] = x1;
                s += x0 + x1; q += x0 * x0 + x1 * x1;
            }
            s += __shfl_xor_sync(0xffffffffu, s, 1);
            s += __shfl_xor_sync(0xffffffffu, s, 2);
            q += __shfl_xor_sync(0xffffffffu, q, 1);
            q += __shfl_xor_sync(0xffffffffu, q, 2);
            if (t == 0) { smS[lrow][wn] = s; smQ[lrow][wn] = q; }
            __syncthreads();
            float S = smS[lrow][0] + smS[lrow][1];
            float Q = smQ[lrow][0] + smQ[lrow][1];
            float mu = S * (1.f / 128.f);
            float var = Q * (1.f / 128.f) - mu * mu;
            float rs = rsqrtf(var + 1e-5f);
#pragma unroll
            for (int ni = 0; ni < 8; ni++) {
                int cc = wn * 64 + ni * 8 + t * 2;
                float2 o;
                o.x = round_tf((v[ni * 2 + 0] - mu) * rs * gw[cc] + bw[cc]);
                o.y = round_tf((v[ni * 2 + 1] - mu) * rs * gw[cc + 1] + bw[cc + 1]);
                *reinterpret_cast<float2*>(xln + (size_t)xrow * 128 + cc) = o;
            }
        }
    }
}

// ---------------- fused MLP: fc1 + gelu + fc2 + residual + LN1 ----------------
#define MLP_SMEM (42240 * 4)
__global__ __launch_bounds__(512) void mlp_kernel(
    const float* __restrict__ xln, const unsigned* __restrict__ W1g4_,
    const unsigned* __restrict__ W2g4_,
    const float* __restrict__ b1, const float* __restrict__ b2,
    const float* __restrict__ res, float* __restrict__ out,
    const float* __restrict__ gw, const float* __restrict__ bw) {
    extern __shared__ unsigned sm[];
    unsigned* XA = sm;
    unsigned* W1 = sm + 16896;
    unsigned* W2 = sm + 25344;
    unsigned* HH = sm + 33792;
    __shared__ float smS[128][4], smQ[128][4];

    const uint4* W1g = reinterpret_cast<const uint4*>(W1g4_);
    const uint4* W2g = reinterpret_cast<const uint4*>(W2g4_);

    const int tid = threadIdx.x;
    const int lane = tid & 31;
    const int wid = tid >> 5;
    const int wm = wid >> 2, wn = wid & 3;
    const int g = lane >> 2, t = lane & 3;
    const int bm = blockIdx.x * 128;

#pragma unroll
    for (int it = 0; it < 8; it++) {
        int c = tid + it * 512;
        int row = c >> 5, kq = c & 31;
        uint4 v = *reinterpret_cast<const uint4*>(xln + (size_t)(bm + row) * 128 + kq * 4);
        int sts = ((row >> 4) * 2 + ((row >> 3) & 1)) * 1056 + (kq >> 1) * 66 + (row & 7) * 8 + (kq & 1);
        XA[sts + 0] = v.x; XA[sts + 2] = v.y; XA[sts + 4] = v.z; XA[sts + 6] = v.w;
    }

    int w1src[4], w2src[4], w1st[4], w2st[4];
#pragma unroll
    for (int it = 0; it < 4; it++) {
        int e = tid + it * 512;
        int n = e >> 5, kq = e & 31;
        w1src[it] = n * 32 + kq;
        w1st[it] = (n >> 3) * 1056 + (kq >> 1) * 66 + (n & 7) * 8 + (kq & 1);
        int n2 = e >> 4, klq = e & 15;
        w2src[it] = n2 * 128 + klq;
        w2st[it] = (n2 >> 3) * 528 + (klq >> 1) * 66 + (n2 & 7) * 8 + (klq & 1);
    }

    {
        uint4 v[4];
#pragma unroll
        for (int it = 0; it < 4; it++) v[it] = W1g[w1src[it]];
#pragma unroll
        for (int it = 0; it < 4; it++) {
            W1[w1st[it] + 0] = v[it].x; W1[w1st[it] + 2] = v[it].y;
            W1[w1st[it] + 4] = v[it].z; W1[w1st[it] + 6] = v[it].w;
        }
    }
    __syncthreads();

    float acco[2][4][4];
#pragma unroll
    for (int mi = 0; mi < 2; mi++)
#pragma unroll
        for (int ni = 0; ni < 4; ni++)
#pragma unroll
            for (int c = 0; c < 4; c++) acco[mi][ni][c] = 0.f;

    for (int c = 0; c < 8; c++) {
        uint4 w2v[4];
#pragma unroll
        for (int it = 0; it < 4; it++) w2v[it] = W2g[w2src[it] + c * 16];

        float accs[2][2][4];
#pragma unroll
        for (int mi = 0; mi < 2; mi++)
#pragma unroll
            for (int ni = 0; ni < 2; ni++)
#pragma unroll
                for (int q = 0; q < 4; q++) accs[mi][ni][q] = 0.f;
#pragma unroll
        for (int k8 = 0; k8 < 16; k8++) {
            unsigned a[2][4], b[2][2];
#pragma unroll
            for (int mi = 0; mi < 2; mi++) {
                int base = ((wm * 2 + mi) * 2) * 1056 + k8 * 66 + lane * 2;
                uint2 q0 = *reinterpret_cast<const uint2*>(&XA[base]);
                uint2 q1 = *reinterpret_cast<const uint2*>(&XA[base + 1056]);
                a[mi][0] = q0.x; a[mi][2] = q0.y;
                a[mi][1] = q1.x; a[mi][3] = q1.y;
            }
#pragma unroll
            for (int ni = 0; ni < 2; ni++) {
                uint2 q = *reinterpret_cast<const uint2*>(&W1[(wn * 2 + ni) * 1056 + k8 * 66 + lane * 2]);
                b[ni][0] = q.x; b[ni][1] = q.y;
            }
#pragma unroll
            for (int mi = 0; mi < 2; mi++)
#pragma unroll
                for (int ni = 0; ni < 2; ni++)
                    MMA_TF32(accs[mi][ni], a[mi][0], a[mi][1], a[mi][2], a[mi][3],
                             b[ni][0], b[ni][1]);
        }

#pragma unroll
        for (int it = 0; it < 4; it++) {
            W2[w2st[it] + 0] = w2v[it].x; W2[w2st[it] + 2] = w2v[it].y;
            W2[w2st[it] + 4] = w2v[it].z; W2[w2st[it] + 6] = w2v[it].w;
        }

#pragma unroll
        for (int mi = 0; mi < 2; mi++) {
            int rgR = (wm * 2 + mi) * 2;
#pragma unroll
            for (int ni = 0; ni < 2; ni++) {
                int kl0 = wn * 16 + ni * 8 + t * 2;
                float bb0 = b1[c * 64 + kl0], bb1 = b1[c * 64 + kl0 + 1];
#pragma unroll
                for (int rh = 0; rh < 2; rh++) {
#pragma unroll
                    for (int ch = 0; ch < 2; ch++) {
                        float v = accs[mi][ni][rh * 2 + ch] + (ch ? bb1 : bb0);
                        v = 0.5f * v * (1.0f + erff(v * 0.7071067811865475f));
                        int k = kl0 + ch;
                        int addr = (rgR + rh) * 528 + (k >> 3) * 66 + g * 8 +
                                   ((k >> 2) & 1) + (k & 3) * 2;
                        HH[addr] = f2tf(v);
                    }
                }
            }
        }
        __syncthreads();

        uint4 w1v[4];
        if (c < 7) {
#pragma unroll
            for (int it = 0; it < 4; it++) w1v[it] = W1g[w1src[it] + (c + 1) * 2048];
        }

#pragma unroll
        for (int k8 = 0; k8 < 8; k8++) {
            unsigned a[2][4], b[4][2];
#pragma unroll
            for (int mi = 0; mi < 2; mi++) {
                int base = ((wm * 2 + mi) * 2) * 528 + k8 * 66 + lane * 2;
                uint2 q0 = *reinterpret_cast<const uint2*>(&HH[base]);
                uint2 q1 = *reinterpret_cast<const uint2*>(&HH[base + 528]);
                a[mi][0] = q0.x; a[mi][2] = q0.y;
                a[mi][1] = q1.x; a[mi][3] = q1.y;
            }
#pragma unroll
            for (int ni = 0; ni < 4; ni++) {
                uint2 q = *reinterpret_cast<const uint2*>(&W2[(wn * 4 + ni) * 528 + k8 * 66 + lane * 2]);
                b[ni][0] = q.x; b[ni][1] = q.y;
            }
#pragma unroll
            for (int mi = 0; mi < 2; mi++)
#pragma unroll
                for (int ni = 0; ni < 4; ni++)
                    MMA_TF32(acco[mi][ni], a[mi][0], a[mi][1], a[mi][2], a[mi][3],
                             b[ni][0], b[ni][1]);
        }

        if (c < 7) {
#pragma unroll
            for (int it = 0; it < 4; it++) {
                W1[w1st[it] + 0] = w1v[it].x; W1[w1st[it] + 2] = w1v[it].y;
                W1[w1st[it] + 4] = w1v[it].z; W1[w1st[it] + 6] = w1v[it].w;
            }
        }
        __syncthreads();
    }

#pragma unroll
    for (int mi = 0; mi < 2; mi++) {
#pragma unroll
        for (int rh = 0; rh < 2; rh++) {
            int lrow = wm * 32 + mi * 16 + g + rh * 8;
            int r = bm + lrow;
            float v[8];
            float s = 0.f, q = 0.f;
#pragma unroll
            for (int ni = 0; ni < 4; ni++) {
                int cc = wn * 32 + ni * 8 + t * 2;
                float2 rr = *reinterpret_cast<const float2*>(res + (size_t)r * 128 + cc);
                float x0 = acco[mi][ni][rh * 2 + 0] + b2[cc] + rr.x;
                float x1 = acco[mi][ni][rh * 2 + 1] + b2[cc + 1] + rr.y;
                v[ni * 2 + 0] = x0; v[ni * 2 + 1] = x1;
                s += x0 + x1; q += x0 * x0 + x1 * x1;
            }
            s += __shfl_xor_sync(0xffffffffu, s, 1);
            s += __shfl_xor_sync(0xffffffffu, s, 2);
            q += __shfl_xor_sync(0xffffffffu, q, 1);
            q += __shfl_xor_sync(0xffffffffu, q, 2);
            if (t == 0) { smS[lrow][wn] = s; smQ[lrow][wn] = q; }
            __syncthreads();
            float S = smS[lrow][0] + smS[lrow][1] + smS[lrow][2] + smS[lrow][3];
            float Q = smQ[lrow][0] + smQ[lrow][1] + smQ[lrow][2] + smQ[lrow][3];
            float mu = S * (1.f / 128.f);
            float var = Q * (1.f / 128.f) - mu * mu;
            float rs = rsqrtf(var + 1e-5f);
#pragma unroll
            for (int ni = 0; ni < 4; ni++) {
                int cc = wn * 32 + ni * 8 + t * 2;
                float2 o;
                o.x = (v[ni * 2 + 0] - mu) * rs * gw[cc] + bw[cc];
                o.y = (v[ni * 2 + 1] - mu) * rs * gw[cc + 1] + bw[cc + 1];
                *reinterpret_cast<float2*>(out + (size_t)r * 128 + cc) = o;
            }
        }
    }
}

// ---------------- launch ----------------
extern "C" void kernel_launch(void* const* d_in, const int* in_sizes, int n_in,
                              void* d_out, int out_size) {
    const float* x_v    = (const float*)d_in[0];
    const float* qkv_w  = (const float*)d_in[1];
    const float* qkv_b  = (const float*)d_in[2];
    const float* proj_w = (const float*)d_in[3];
    const float* proj_b = (const float*)d_in[4];
    const float* rpb    = (const float*)d_in[5];
    const float* n1w    = (const float*)d_in[6];
    const float* n1b    = (const float*)d_in[7];
    const float* n2w    = (const float*)d_in[8];
    const float* n2b    = (const float*)d_in[9];
    const float* fc1w   = (const float*)d_in[10];
    const float* fc1b   = (const float*)d_in[11];
    const float* fc2w   = (const float*)d_in[12];
    const float* fc2b   = (const float*)d_in[13];
    float* out = (float*)d_out;

    float *qkvb, *attn, *xln, *xres, *ps;
    unsigned* wtf;
    cudaGetSymbolAddress((void**)&qkvb, g_qkv);
    cudaGetSymbolAddress((void**)&attn, g_attn);
    cudaGetSymbolAddress((void**)&xln,  g_xln);
    cudaGetSymbolAddress((void**)&xres, g_xres);
    cudaGetSymbolAddress((void**)&ps,   g_ps);
    cudaGetSymbolAddress((void**)&wtf,  g_wtf);

    cudaFuncSetAttribute(qkv_kernel, cudaFuncAttributeMaxDynamicSharedMemorySize, QKV_SMEM);
    cudaFuncSetAttribute(attn_kernel, cudaFuncAttributeMaxDynamicSharedMemorySize, SMEM_ATTN);
    cudaFuncSetAttribute(projln_kernel, cudaFuncAttributeMaxDynamicSharedMemorySize, PROJ_SMEM);
    cudaFuncSetAttribute(mlp_kernel, cudaFuncAttributeMaxDynamicSharedMemorySize, MLP_SMEM);

    // 0. weight conversion + rpb/mask table
    cvt_weights<<<768, 256>>>(qkv_w, proj_w, fc1w, fc2w, wtf);
    ps_kernel<<<dim3(256, 4), 256>>>(rpb, ps);
    // 1. qkv = gather(x_v) @ qkv_w^T + b  (outputs pre-rounded, Q pre-scaled)
    qkv_kernel<<<1024, 512, QKV_SMEM>>>(x_v, wtf, qkv_b, qkvb);
    // 2. window attention (raw staging, ps table from gmem)
    attn_kernel<<<dim3(1024, HEADS), 256, SMEM_ATTN>>>(qkvb, ps, attn);
    // 3. proj + scatter + residual + LN2
    projln_kernel<<<1024, 256, PROJ_SMEM>>>(attn, wtf + 49152, proj_b,
                                            x_v, xres, xln, n2w, n2b);
    // 4. fused MLP -> final output
    mlp_kernel<<<1024, 512, MLP_SMEM>>>(xln, wtf + 65536, wtf + 131072,
                                        fc1b, fc2b, xres, out, n1w, n1b);
}

// round 11
// speedup vs baseline: 2.1692x; 1.1785x over previous
#include <cuda_runtime.h>
#include <math.h>

// ---------------- problem constants ----------------
#define M_TOT 131072
#define HEADS 4

// ---------------- scratch ----------------
__device__ float g_qkv [(size_t)M_TOT * 3 * 128];
__device__ float g_attn[(size_t)M_TOT * 128];
__device__ float g_xln [(size_t)M_TOT * 128];
__device__ float g_xres[(size_t)M_TOT * 128];
__device__ float g_ps  [256 * 4 * 4096];     // rpb+mask, C-frag order per (winmod, head)
__device__ unsigned g_wtf[131072];           // qkv tf32(rm) | proj tf32(frag) | fc1 bf16x2 | fc2 bf16x2

__device__ __forceinline__ int perm_row(int r) {
    int b_ = r >> 7, tt = r & 127;
    int b = b_ >> 8, w = b_ & 255;
    int wh = w >> 4, ww = w & 15;
    int t = tt >> 6, n = tt & 63;
    int i = n >> 3, j = n & 7;
    int oh = (wh * 8 + i + 4) & 127;
    int ow = (ww * 8 + j + 4) & 127;
    return (b * 2 + t) * 16384 + oh * 128 + ow;
}

__device__ __forceinline__ unsigned f2tf(float f) {
    unsigned u;
    asm("cvt.rna.tf32.f32 %0, %1;" : "=r"(u) : "f"(f));
    return u;
}
__device__ __forceinline__ float round_tf(float f) { return __uint_as_float(f2tf(f)); }

// pack two floats -> bf16x2 word (lo = first arg, hi = second)
__device__ __forceinline__ unsigned pack_bf(float lo, float hi) {
    unsigned d;
    asm("cvt.rn.bf16x2.f32 %0, %1, %2;" : "=r"(d) : "f"(hi), "f"(lo));
    return d;
}

#define MMA_TF32(d, a0, a1, a2, a3, b0, b1)                                            \
    asm volatile(                                                                      \
        "mma.sync.aligned.m16n8k8.row.col.f32.tf32.tf32.f32 "                          \
        "{%0,%1,%2,%3},{%4,%5,%6,%7},{%8,%9},{%0,%1,%2,%3};"                           \
        : "+f"(d[0]), "+f"(d[1]), "+f"(d[2]), "+f"(d[3])                               \
        : "r"(a0), "r"(a1), "r"(a2), "r"(a3), "r"(b0), "r"(b1))

#define MMA_BF16(d, a0, a1, a2, a3, b0, b1)                                            \
    asm volatile(                                                                      \
        "mma.sync.aligned.m16n8k16.row.col.f32.bf16.bf16.f32 "                         \
        "{%0,%1,%2,%3},{%4,%5,%6,%7},{%8,%9},{%0,%1,%2,%3};"                           \
        : "+f"(d[0]), "+f"(d[1]), "+f"(d[2]), "+f"(d[3])                               \
        : "r"(a0), "r"(a1), "r"(a2), "r"(a3), "r"(b0), "r"(b1))

// ---------------- weight pre-conversion ----------------
// qkv tf32 row-major; proj tf32 B-frag; fc1/fc2 packed bf16x2 words (w = k/2)
__global__ void cvt_weights(const float* __restrict__ qkv_w, const float* __restrict__ proj_w,
                            const float* __restrict__ fc1_w, const float* __restrict__ fc2_w,
                            unsigned* __restrict__ wtf) {
    int i = blockIdx.x * 256 + threadIdx.x;
    if (i < 49152) { wtf[i] = f2tf(qkv_w[i]); return; }
    if (i < 65536) {
        int j = i - 49152;
        int pair = j >> 1, half = j & 1;
        int lane = pair & 31, k8 = (pair >> 5) & 15, n8 = pair >> 9;
        int g = lane >> 2, t = lane & 3;
        int n = n8 * 8 + g, k = k8 * 8 + t + (half ? 4 : 0);
        wtf[i] = f2tf(proj_w[n * 128 + k]);
        return;
    }
    if (i < 98304) {                 // fc1: [512][64 words]
        int j = i - 65536;
        int n = j >> 6, w = j & 63;
        wtf[i] = pack_bf(fc1_w[n * 128 + 2 * w], fc1_w[n * 128 + 2 * w + 1]);
        return;
    }
    {                                // fc2: [128][256 words]
        int j = i - 98304;
        int n = j >> 8, w = j & 255;
        wtf[i] = pack_bf(fc2_w[n * 512 + 2 * w], fc2_w[n * 512 + 2 * w + 1]);
    }
}

// ---------------- rpb + shift-mask table in C-frag order ----------------
__global__ void ps_kernel(const float* __restrict__ rpb, float* __restrict__ ps) {
    int wwin = blockIdx.x;
    int head = blockIdx.y;
    int wh = wwin >> 4, ww = wwin & 15;
    int tid = threadIdx.x;
    float* dst = ps + (size_t)(wwin * 4 + head) * 4096;
#pragma unroll
    for (int it = 0; it < 16; it++) {
        int e = tid + it * 256;
        int qn = e >> 6, kn = e & 63;
        int qi2 = qn >> 3, qj = qn & 7, ki = kn >> 3, kj = kn & 7;
        int rel = (qi2 - ki + 7) * 15 + (qj - kj + 7);
        float v = rpb[rel * HEADS + head];
        int gqh = wh * 8 + qi2, gqw = ww * 8 + qj;
        int gkh = wh * 8 + ki,  gkw = ww * 8 + kj;
        int rq = (gqh < 120 ? 0 : (gqh < 124 ? 1 : 2)) * 3 + (gqw < 120 ? 0 : (gqw < 124 ? 1 : 2));
        int rk = (gkh < 120 ? 0 : (gkh < 124 ? 1 : 2)) * 3 + (gkw < 120 ? 0 : (gkw < 124 ? 1 : 2));
        if (rq != rk) v -= 100.0f;
        int qtile = qn >> 4, ntile = kn >> 3;
        int ln = (qn & 7) * 4 + ((kn & 7) >> 1);
        int reg = ((qn >> 3) & 1) * 2 + (kn & 1);
        dst[((qtile * 8 + ntile) * 32 + ln) * 4 + reg] = v;
    }
}

// ---------------- qkv GEMM: A staged once, weights streamed (unchanged) ----------------
#define QKV_SMEM ((16896 + 16896) * 4)
__global__ __launch_bounds__(512) void qkv_kernel(
    const float* __restrict__ xv, const unsigned* __restrict__ Wq_,
    const float* __restrict__ bias, float* __restrict__ out) {
    extern __shared__ unsigned sm[];
    unsigned* XA = sm;
    unsigned* WB = sm + 16896;

    const uint4* Wg = reinterpret_cast<const uint4*>(Wq_);
    const int tid = threadIdx.x;
    const int lane = tid & 31;
    const int wid = tid >> 5;
    const int wm = wid >> 2, wn = wid & 3;
    const int g = lane >> 2, t = lane & 3;
    const int bm = blockIdx.x * 128;
    const float scale = 0.17677669529663687f;

#pragma unroll
    for (int it = 0; it < 8; it++) {
        int c = tid + it * 512;
        int row = c >> 5, kq = c & 31;
        int src = perm_row(bm + row);
        float4 v = *reinterpret_cast<const float4*>(xv + (size_t)src * 128 + kq * 4);
        int sts = ((row >> 4) * 2 + ((row >> 3) & 1)) * 1056 + (kq >> 1) * 66 + (row & 7) * 8 + (kq & 1);
        XA[sts + 0] = f2tf(v.x); XA[sts + 2] = f2tf(v.y);
        XA[sts + 4] = f2tf(v.z); XA[sts + 6] = f2tf(v.w);
    }

    int wsrc[4], wst[4];
#pragma unroll
    for (int it = 0; it < 4; it++) {
        int e = tid + it * 512;
        int n = e >> 5, kq = e & 31;
        wsrc[it] = n * 32 + kq;
        wst[it] = (n >> 3) * 1056 + (kq >> 1) * 66 + (n & 7) * 8 + (kq & 1);
    }
    {
        uint4 v[4];
#pragma unroll
        for (int it = 0; it < 4; it++) v[it] = Wg[wsrc[it]];
#pragma unroll
        for (int it = 0; it < 4; it++) {
            WB[wst[it] + 0] = v[it].x; WB[wst[it] + 2] = v[it].y;
            WB[wst[it] + 4] = v[it].z; WB[wst[it] + 6] = v[it].w;
        }
    }
    __syncthreads();

    int p = 0;
    for (int c = 0; c < 6; c++) {
        uint4 wv[4];
        if (c < 5) {
#pragma unroll
            for (int it = 0; it < 4; it++) wv[it] = Wg[wsrc[it] + (c + 1) * 2048];
        }
        unsigned* Wp = WB + p * 8448;

        float accs[2][2][4];
#pragma unroll
        for (int mi = 0; mi < 2; mi++)
#pragma unroll
            for (int ni = 0; ni < 2; ni++)
#pragma unroll
                for (int q = 0; q < 4; q++) accs[mi][ni][q] = 0.f;

#pragma unroll
        for (int k8 = 0; k8 < 16; k8++) {
            unsigned a[2][4], b[2][2];
#pragma unroll
            for (int mi = 0; mi < 2; mi++) {
                int base = ((wm * 2 + mi) * 2) * 1056 + k8 * 66 + lane * 2;
                uint2 q0 = *reinterpret_cast<const uint2*>(&XA[base]);
                uint2 q1 = *reinterpret_cast<const uint2*>(&XA[base + 1056]);
                a[mi][0] = q0.x; a[mi][2] = q0.y;
                a[mi][1] = q1.x; a[mi][3] = q1.y;
            }
#pragma unroll
            for (int ni = 0; ni < 2; ni++) {
                uint2 q = *reinterpret_cast<const uint2*>(&Wp[(wn * 2 + ni) * 1056 + k8 * 66 + lane * 2]);
                b[ni][0] = q.x; b[ni][1] = q.y;
            }
#pragma unroll
            for (int mi = 0; mi < 2; mi++)
#pragma unroll
                for (int ni = 0; ni < 2; ni++)
                    MMA_TF32(accs[mi][ni], a[mi][0], a[mi][1], a[mi][2], a[mi][3],
                             b[ni][0], b[ni][1]);
        }

        float sc = (c < 2) ? scale : 1.0f;
#pragma unroll
        for (int mi = 0; mi < 2; mi++) {
#pragma unroll
            for (int rh = 0; rh < 2; rh++) {
                int r = bm + wm * 32 + mi * 16 + g + rh * 8;
#pragma unroll
                for (int ni = 0; ni < 2; ni++) {
                    int col = c * 64 + wn * 16 + ni * 8 + t * 2;
                    float2 o;
                    o.x = round_tf((accs[mi][ni][rh * 2 + 0] + bias[col]) * sc);
                    o.y = round_tf((accs[mi][ni][rh * 2 + 1] + bias[col + 1]) * sc);
                    *reinterpret_cast<float2*>(out + (size_t)r * 384 + col) = o;
                }
            }
        }

        if (c < 5) {
            unsigned* Wn = WB + (p ^ 1) * 8448;
#pragma unroll
            for (int it = 0; it < 4; it++) {
                Wn[wst[it] + 0] = wv[it].x; Wn[wst[it] + 2] = wv[it].y;
                Wn[wst[it] + 4] = wv[it].z; Wn[wst[it] + 6] = wv[it].w;
            }
            p ^= 1;
        }
        __syncthreads();
    }
}

// ---------------- tensor-core window attention (unchanged) ----------------
#define SM_QA 0
#define SM_KB 4224
#define SM_VB 8448
#define SMEM_ATTN (12704 * 4)

__global__ __launch_bounds__(256) void attn_kernel(const float* __restrict__ qkv,
                                                   const float* __restrict__ ps,
                                                   float* __restrict__ attout) {
    extern __shared__ unsigned sm[];
    unsigned* QA = sm + SM_QA;
    unsigned* KB = sm + SM_KB;
    unsigned* VB = sm + SM_VB;

    const int win = blockIdx.x, head = blockIdx.y;
    const int tid = threadIdx.x;
    const int lane = tid & 31, w = tid >> 5;
    const int g = lane >> 2, t = lane & 3;
    const float* psh = ps + (size_t)((win & 255) * 4 + head) * 4096;
    const uint4* qkv4 = reinterpret_cast<const uint4*>(qkv);

#pragma unroll
    for (int it = 0; it < 4; it++) {
        int c = tid + it * 256;
        int row = c >> 3, kq = c & 7;
        size_t base4 = ((size_t)(win * 128 + row)) * 96 + head * 8 + kq;
        uint4 qv = qkv4[base4];
        uint4 kv = qkv4[base4 + 32];
        uint4 vv = qkv4[base4 + 64];
        int k8 = kq >> 1, kh = kq & 1;
        int qa = ((row >> 4) * 2 + ((row >> 3) & 1)) * 264 + k8 * 66 + (row & 7) * 8 + kh;
        QA[qa + 0] = qv.x; QA[qa + 2] = qv.y; QA[qa + 4] = qv.z; QA[qa + 6] = qv.w;
        int kb = (row >> 3) * 264 + k8 * 66 + (row & 7) * 8 + kh;
        KB[kb + 0] = kv.x; KB[kb + 2] = kv.y; KB[kb + 4] = kv.z; KB[kb + 6] = kv.w;
        int vb = (kq >> 1) * 1064 + (row >> 3) * 66 + ((kq & 1) * 4) * 8 +
                 ((row >> 2) & 1) + 2 * (row & 3);
        VB[vb + 0]  = vv.x; VB[vb + 8]  = vv.y;
        VB[vb + 16] = vv.z; VB[vb + 24] = vv.w;
    }
    __syncthreads();

    float acc[16][4];
#pragma unroll
    for (int nt = 0; nt < 16; nt++)
#pragma unroll
        for (int i = 0; i < 4; i++) acc[nt][i] = 0.f;

#pragma unroll
    for (int k8 = 0; k8 < 4; k8++) {
        int abase = (w * 2) * 264 + k8 * 66 + lane * 2;
        uint2 q0 = *reinterpret_cast<const uint2*>(&QA[abase]);
        uint2 q1 = *reinterpret_cast<const uint2*>(&QA[abase + 264]);
#pragma unroll
        for (int nt = 0; nt < 16; nt++) {
            uint2 b = *reinterpret_cast<const uint2*>(&KB[nt * 264 + k8 * 66 + lane * 2]);
            MMA_TF32(acc[nt], q0.x, q1.x, q0.y, q1.y, b.x, b.y);
        }
    }

    const int qtile = w & 3;
    float m0 = -1e30f, m1 = -1e30f;
#pragma unroll
    for (int nt = 0; nt < 16; nt++) {
        float4 p = *reinterpret_cast<const float4*>(psh + ((qtile * 8 + (nt & 7)) * 32 + lane) * 4);
        acc[nt][0] += p.x; acc[nt][1] += p.y;
        acc[nt][2] += p.z; acc[nt][3] += p.w;
        m0 = fmaxf(m0, fmaxf(acc[nt][0], acc[nt][1]));
        m1 = fmaxf(m1, fmaxf(acc[nt][2], acc[nt][3]));
    }
    m0 = fmaxf(m0, __shfl_xor_sync(0xffffffffu, m0, 1));
    m0 = fmaxf(m0, __shfl_xor_sync(0xffffffffu, m0, 2));
    m1 = fmaxf(m1, __shfl_xor_sync(0xffffffffu, m1, 1));
    m1 = fmaxf(m1, __shfl_xor_sync(0xffffffffu, m1, 2));

    float l0 = 0.f, l1 = 0.f;
#pragma unroll
    for (int nt = 0; nt < 16; nt++) {
        acc[nt][0] = __expf(acc[nt][0] - m0);
        acc[nt][1] = __expf(acc[nt][1] - m0);
        acc[nt][2] = __expf(acc[nt][2] - m1);
        acc[nt][3] = __expf(acc[nt][3] - m1);
        l0 += acc[nt][0] + acc[nt][1];
        l1 += acc[nt][2] + acc[nt][3];
    }
    l0 += __shfl_xor_sync(0xffffffffu, l0, 1);
    l0 += __shfl_xor_sync(0xffffffffu, l0, 2);
    l1 += __shfl_xor_sync(0xffffffffu, l1, 1);
    l1 += __shfl_xor_sync(0xffffffffu, l1, 2);
    float inv0 = 1.0f / l0, inv1 = 1.0f / l1;

#pragma unroll
    for (int nt = 0; nt < 16; nt++)
#pragma unroll
        for (int i = 0; i < 4; i++)
            acc[nt][i] = __uint_as_float(f2tf(acc[nt][i]));

    float oacc[4][4];
#pragma unroll
    for (int n8 = 0; n8 < 4; n8++)
#pragma unroll
        for (int i = 0; i < 4; i++) oacc[n8][i] = 0.f;

    const int s0 = (lane & 28) | (t >> 1);
    const int s1 = s0 + 2;
    const bool oddt = (t & 1);
#pragma unroll
    for (int c = 0; c < 16; c++) {
        float e0 = __shfl_sync(0xffffffffu, acc[c][0], s0);
        float o0 = __shfl_sync(0xffffffffu, acc[c][1], s0);
        float e1 = __shfl_sync(0xffffffffu, acc[c][2], s0);
        float o1 = __shfl_sync(0xffffffffu, acc[c][3], s0);
        float e2 = __shfl_sync(0xffffffffu, acc[c][0], s1);
        float o2 = __shfl_sync(0xffffffffu, acc[c][1], s1);
        float e3 = __shfl_sync(0xffffffffu, acc[c][2], s1);
        float o3 = __shfl_sync(0xffffffffu, acc[c][3], s1);
        unsigned a0 = __float_as_uint(oddt ? o0 : e0);
        unsigned a1 = __float_as_uint(oddt ? o1 : e1);
        unsigned a2 = __float_as_uint(oddt ? o2 : e2);
        unsigned a3 = __float_as_uint(oddt ? o3 : e3);
#pragma unroll
        for (int n8 = 0; n8 < 4; n8++) {
            uint2 b = *reinterpret_cast<const uint2*>(&VB[n8 * 1064 + c * 66 + lane * 2]);
            MMA_TF32(oacc[n8], a0, a1, a2, a3, b.x, b.y);
        }
    }

    int r0 = win * 128 + w * 16 + g;
#pragma unroll
    for (int n8 = 0; n8 < 4; n8++) {
        int col = head * 32 + n8 * 8 + t * 2;
        float2 o0, o1;
        o0.x = round_tf(oacc[n8][0] * inv0);
        o0.y = round_tf(oacc[n8][1] * inv0);
        o1.x = round_tf(oacc[n8][2] * inv1);
        o1.y = round_tf(oacc[n8][3] * inv1);
        *reinterpret_cast<float2*>(attout + (size_t)r0 * 128 + col) = o0;
        *reinterpret_cast<float2*>(attout + (size_t)(r0 + 8) * 128 + col) = o1;
    }
}

// ---------------- proj + scatter + residual + LN2 (unchanged) ----------------
#define PROJ_SMEM (16896 * 4)
__global__ __launch_bounds__(256) void projln_kernel(
    const float* __restrict__ attn, const unsigned* __restrict__ Wp_,
    const float* __restrict__ bias, const float* __restrict__ res,
    float* __restrict__ xres, float* __restrict__ xln,
    const float* __restrict__ gw, const float* __restrict__ bw) {
    extern __shared__ unsigned sm[];
    unsigned* OA = sm;
    __shared__ float smS[128][2], smQ[128][2];

    const int win = blockIdx.x;
    const int tid = threadIdx.x;
    const int lane = tid & 31, w = tid >> 5;
    const int g = lane >> 2, t = lane & 3;
    const int wm = w >> 1, wn = w & 1;

#pragma unroll
    for (int it = 0; it < 16; it++) {
        int c = tid + it * 256;
        int row = c >> 5, kq = c & 31;
        uint4 v = *reinterpret_cast<const uint4*>(attn + ((size_t)(win * 128 + row)) * 128 + kq * 4);
        int sts = ((row >> 4) * 2 + ((row >> 3) & 1)) * 1056 + (kq >> 1) * 66 + (row & 7) * 8 + (kq & 1);
        OA[sts + 0] = v.x; OA[sts + 2] = v.y; OA[sts + 4] = v.z; OA[sts + 6] = v.w;
    }
    __syncthreads();

    const uint2* Wp2 = reinterpret_cast<const uint2*>(Wp_);
    float acc2[2][8][4];
#pragma unroll
    for (int mi = 0; mi < 2; mi++)
#pragma unroll
        for (int ni = 0; ni < 8; ni++)
#pragma unroll
            for (int q = 0; q < 4; q++) acc2[mi][ni][q] = 0.f;

#pragma unroll
    for (int k8 = 0; k8 < 16; k8++) {
        unsigned a[2][4];
#pragma unroll
        for (int mi = 0; mi < 2; mi++) {
            int base = ((wm * 2 + mi) * 2) * 1056 + k8 * 66 + lane * 2;
            uint2 q0 = *reinterpret_cast<const uint2*>(&OA[base]);
            uint2 q1 = *reinterpret_cast<const uint2*>(&OA[base + 1056]);
            a[mi][0] = q0.x; a[mi][2] = q0.y;
            a[mi][1] = q1.x; a[mi][3] = q1.y;
        }
#pragma unroll
        for (int ni = 0; ni < 8; ni++) {
            uint2 b = Wp2[((wn * 8 + ni) * 16 + k8) * 32 + lane];
#pragma unroll
            for (int mi = 0; mi < 2; mi++)
                MMA_TF32(acc2[mi][ni], a[mi][0], a[mi][1], a[mi][2], a[mi][3], b.x, b.y);
        }
    }

#pragma unroll
    for (int mi = 0; mi < 2; mi++) {
#pragma unroll
        for (int rh = 0; rh < 2; rh++) {
            int lrow = wm * 32 + mi * 16 + g + rh * 8;
            int xrow = perm_row(win * 128 + lrow);
            float v[16];
            float s = 0.f, q = 0.f;
#pragma unroll
            for (int ni = 0; ni < 8; ni++) {
                int cc = wn * 64 + ni * 8 + t * 2;
                float2 rr = *reinterpret_cast<const float2*>(res + (size_t)xrow * 128 + cc);
                float x0 = acc2[mi][ni][rh * 2 + 0] + bias[cc] + rr.x;
                float x1 = acc2[mi][ni][rh * 2 + 1] + bias[cc + 1] + rr.y;
                *reinterpret_cast<float2*>(xres + (size_t)xrow * 128 + cc) = make_float2(x0, x1);
                v[ni * 2 + 0] = x0; v[ni * 2 + 1] = x1;
                s += x0 + x1; q += x0 * x0 + x1 * x1;
            }
            s += __shfl_xor_sync(0xffffffffu, s, 1);
            s += __shfl_xor_sync(0xffffffffu, s, 2);
            q += __shfl_xor_sync(0xffffffffu, q, 1);
            q += __shfl_xor_sync(0xffffffffu, q, 2);
            if (t == 0) { smS[lrow][wn] = s; smQ[lrow][wn] = q; }
            __syncthreads();
            float S = smS[lrow][0] + smS[lrow][1];
            float Q = smQ[lrow][0] + smQ[lrow][1];
            float mu = S * (1.f / 128.f);
            float var = Q * (1.f / 128.f) - mu * mu;
            float rs = rsqrtf(var + 1e-5f);
#pragma unroll
            for (int ni = 0; ni < 8; ni++) {
                int cc = wn * 64 + ni * 8 + t * 2;
                float2 o;
                o.x = round_tf((v[ni * 2 + 0] - mu) * rs * gw[cc] + bw[cc]);
                o.y = round_tf((v[ni * 2 + 1] - mu) * rs * gw[cc + 1] + bw[cc + 1]);
                *reinterpret_cast<float2*>(xln + (size_t)xrow * 128 + cc) = o;
            }
        }
    }
}

// ---------------- fused MLP (bf16 m16n8k16): fc1 + gelu + fc2 + residual + LN1 ----------------
// smem words: XA 0..8448 | W1 8448..12672 | W2 12672..16896 | HH 16896..21120
#define MLP_SMEM (21120 * 4)
__global__ __launch_bounds__(512) void mlp_kernel(
    const float* __restrict__ xln, const unsigned* __restrict__ W1g4_,
    const unsigned* __restrict__ W2g4_,
    const float* __restrict__ b1, const float* __restrict__ b2,
    const float* __restrict__ res, float* __restrict__ out,
    const float* __restrict__ gw, const float* __restrict__ bw) {
    extern __shared__ unsigned sm[];
    unsigned* XA = sm;            // 128 rows x 64 words: 16 rowgrps x 528
    unsigned* W1 = sm + 8448;     // 64 n x 64 words: 8 ngrps x 528
    unsigned* W2 = sm + 12672;    // 128 n x 32 words: 16 ngrps x 264
    unsigned* HH = sm + 16896;    // 128 rows x 32 words: 16 rowgrps x 264
    __shared__ float smS[128][4], smQ[128][4];

    const uint4* W1g = reinterpret_cast<const uint4*>(W1g4_);
    const uint4* W2g = reinterpret_cast<const uint4*>(W2g4_);

    const int tid = threadIdx.x;
    const int lane = tid & 31;
    const int wid = tid >> 5;
    const int wm = wid >> 2, wn = wid & 3;   // 4m x 4n
    const int g = lane >> 2, t = lane & 3;
    const int bm = blockIdx.x * 128;

    // ---- stage XA: fp32 -> bf16x2 words in A-frag-word layout ----
#pragma unroll
    for (int it = 0; it < 8; it++) {
        int c = tid + it * 512;
        int row = c >> 5, kq = c & 31;       // kq = float quad -> words 2kq, 2kq+1
        float4 v = *reinterpret_cast<const float4*>(xln + (size_t)(bm + row) * 128 + kq * 4);
        int rg = ((row >> 4) * 2 + ((row >> 3) & 1)) * 528 + (row & 7) * 8;
        int w0 = 2 * kq, w1 = 2 * kq + 1;
        XA[rg + (w0 >> 3) * 66 + ((w0 >> 2) & 1) + 2 * (w0 & 3)] = pack_bf(v.x, v.y);
        XA[rg + (w1 >> 3) * 66 + ((w1 >> 2) & 1) + 2 * (w1 & 3)] = pack_bf(v.z, v.w);
    }

    // W1 chunk: 64n x 16 uint4; W2 chunk: 128n x 8 uint4 — 2 uint4/thread each
    int w1src[2], w1st[2], w2src[2], w2st[2];
#pragma unroll
    for (int it = 0; it < 2; it++) {
        int e = tid + it * 512;              // 0..1023
        int n = e >> 4, wq = e & 15;         // W1
        w1src[it] = n * 16 + wq;             // + chunk*1024
        w1st[it] = (n >> 3) * 528 + (wq >> 1) * 66 + (n & 7) * 8 + (wq & 1);
        int n2 = e >> 3, wq2 = e & 7;        // W2
        w2src[it] = n2 * 64 + wq2;           // + chunk*8
        w2st[it] = (n2 >> 3) * 264 + (wq2 >> 1) * 66 + (n2 & 7) * 8 + (wq2 & 1);
    }

    // preload W1 chunk 0
    {
        uint4 v[2];
#pragma unroll
        for (int it = 0; it < 2; it++) v[it] = W1g[w1src[it]];
#pragma unroll
        for (int it = 0; it < 2; it++) {
            W1[w1st[it] + 0] = v[it].x; W1[w1st[it] + 2] = v[it].y;
            W1[w1st[it] + 4] = v[it].z; W1[w1st[it] + 6] = v[it].w;
        }
    }
    __syncthreads();

    float acco[2][4][4];
#pragma unroll
    for (int mi = 0; mi < 2; mi++)
#pragma unroll
        for (int ni = 0; ni < 4; ni++)
#pragma unroll
            for (int c = 0; c < 4; c++) acco[mi][ni][c] = 0.f;

    for (int c = 0; c < 8; c++) {
        // prefetch W2 chunk c
        uint4 w2v[2];
#pragma unroll
        for (int it = 0; it < 2; it++) w2v[it] = W2g[w2src[it] + c * 8];

        // ---- GEMM1: S(128x64) = X @ W1^T, K=128 -> 8 k16 steps ----
        float accs[2][2][4];
#pragma unroll
        for (int mi = 0; mi < 2; mi++)
#pragma unroll
            for (int ni = 0; ni < 2; ni++)
#pragma unroll
                for (int q = 0; q < 4; q++) accs[mi][ni][q] = 0.f;
#pragma unroll
        for (int k16 = 0; k16 < 8; k16++) {
            unsigned a[2][4], b[2][2];
#pragma unroll
            for (int mi = 0; mi < 2; mi++) {
                int base = ((wm * 2 + mi) * 2) * 528 + k16 * 66 + lane * 2;
                uint2 q0 = *reinterpret_cast<const uint2*>(&XA[base]);
                uint2 q1 = *reinterpret_cast<const uint2*>(&XA[base + 528]);
                a[mi][0] = q0.x; a[mi][2] = q0.y;
                a[mi][1] = q1.x; a[mi][3] = q1.y;
            }
#pragma unroll
            for (int ni = 0; ni < 2; ni++) {
                uint2 q = *reinterpret_cast<const uint2*>(&W1[(wn * 2 + ni) * 528 + k16 * 66 + lane * 2]);
                b[ni][0] = q.x; b[ni][1] = q.y;
            }
#pragma unroll
            for (int mi = 0; mi < 2; mi++)
#pragma unroll
                for (int ni = 0; ni < 2; ni++)
                    MMA_BF16(accs[mi][ni], a[mi][0], a[mi][1], a[mi][2], a[mi][3],
                             b[ni][0], b[ni][1]);
        }

        // store W2 stage
#pragma unroll
        for (int it = 0; it < 2; it++) {
            W2[w2st[it] + 0] = w2v[it].x; W2[w2st[it] + 2] = w2v[it].y;
            W2[w2st[it] + 4] = w2v[it].z; W2[w2st[it] + 6] = w2v[it].w;
        }

        // gelu + bias1 -> HH bf16x2 words
#pragma unroll
        for (int mi = 0; mi < 2; mi++) {
#pragma unroll
            for (int ni = 0; ni < 2; ni++) {
                int kl0 = wn * 16 + ni * 8 + t * 2;
                int w = kl0 >> 1;            // = wn*8 + ni*4 + t
                int wof = (w >> 3) * 66 + ((w >> 2) & 1) + 2 * (w & 3);
                float bb0 = b1[c * 64 + kl0], bb1 = b1[c * 64 + kl0 + 1];
#pragma unroll
                for (int rh = 0; rh < 2; rh++) {
                    float x0 = accs[mi][ni][rh * 2 + 0] + bb0;
                    float x1 = accs[mi][ni][rh * 2 + 1] + bb1;
                    x0 = 0.5f * x0 * (1.0f + erff(x0 * 0.7071067811865475f));
                    x1 = 0.5f * x1 * (1.0f + erff(x1 * 0.7071067811865475f));
                    int addr = ((wm * 2 + mi) * 2 + rh) * 264 + wof + g * 8;
                    HH[addr] = pack_bf(x0, x1);
                }
            }
        }
        __syncthreads();

        // prefetch W1 chunk c+1
        uint4 w1v[2];
        if (c < 7) {
#pragma unroll
            for (int it = 0; it < 2; it++) w1v[it] = W1g[w1src[it] + (c + 1) * 1024];
        }

        // ---- GEMM2: out(128x128) += H @ W2^T, K=64 -> 4 k16 steps ----
#pragma unroll
        for (int k16 = 0; k16 < 4; k16++) {
            unsigned a[2][4], b[4][2];
#pragma unroll
            for (int mi = 0; mi < 2; mi++) {
                int base = ((wm * 2 + mi) * 2) * 264 + k16 * 66 + lane * 2;
                uint2 q0 = *reinterpret_cast<const uint2*>(&HH[base]);
                uint2 q1 = *reinterpret_cast<const uint2*>(&HH[base + 264]);
                a[mi][0] = q0.x; a[mi][2] = q0.y;
                a[mi][1] = q1.x; a[mi][3] = q1.y;
            }
#pragma unroll
            for (int ni = 0; ni < 4; ni++) {
                uint2 q = *reinterpret_cast<const uint2*>(&W2[(wn * 4 + ni) * 264 + k16 * 66 + lane * 2]);
                b[ni][0] = q.x; b[ni][1] = q.y;
            }
#pragma unroll
            for (int mi = 0; mi < 2; mi++)
#pragma unroll
                for (int ni = 0; ni < 4; ni++)
                    MMA_BF16(acco[mi][ni], a[mi][0], a[mi][1], a[mi][2], a[mi][3],
                             b[ni][0], b[ni][1]);
        }

        if (c < 7) {
#pragma unroll
            for (int it = 0; it < 2; it++) {
                W1[w1st[it] + 0] = w1v[it].x; W1[w1st[it] + 2] = w1v[it].y;
                W1[w1st[it] + 4] = w1v[it].z; W1[w1st[it] + 6] = w1v[it].w;
            }
        }
        __syncthreads();
    }

    // ---- epilogue: bias2 + residual + LN1 -> out ----
#pragma unroll
    for (int mi = 0; mi < 2; mi++) {
#pragma unroll
        for (int rh = 0; rh < 2; rh++) {
            int lrow = wm * 32 + mi * 16 + g + rh * 8;
            int r = bm + lrow;
            float v[8];
            float s = 0.f, q = 0.f;
#pragma unroll
            for (int ni = 0; ni < 4; ni++) {
                int cc = wn * 32 + ni * 8 + t * 2;
                float2 rr = *reinterpret_cast<const float2*>(res + (size_t)r * 128 + cc);
                float x0 = acco[mi][ni][rh * 2 + 0] + b2[cc] + rr.x;
                float x1 = acco[mi][ni][rh * 2 + 1] + b2[cc + 1] + rr.y;
                v[ni * 2 + 0] = x0; v[ni * 2 + 1] = x1;
                s += x0 + x1; q += x0 * x0 + x1 * x1;
            }
            s += __shfl_xor_sync(0xffffffffu, s, 1);
            s += __shfl_xor_sync(0xffffffffu, s, 2);
            q += __shfl_xor_sync(0xffffffffu, q, 1);
            q += __shfl_xor_sync(0xffffffffu, q, 2);
            if (t == 0) { smS[lrow][wn] = s; smQ[lrow][wn] = q; }
            __syncthreads();
            float S = smS[lrow][0] + smS[lrow][1] + smS[lrow][2] + smS[lrow][3];
            float Q = smQ[lrow][0] + smQ[lrow][1] + smQ[lrow][2] + smQ[lrow][3];
            float mu = S * (1.f / 128.f);
            float var = Q * (1.f / 128.f) - mu * mu;
            float rs = rsqrtf(var + 1e-5f);
#pragma unroll
            for (int ni = 0; ni < 4; ni++) {
                int cc = wn * 32 + ni * 8 + t * 2;
                float2 o;
                o.x = (v[ni * 2 + 0] - mu) * rs * gw[cc] + bw[cc];
                o.y = (v[ni * 2 + 1] - mu) * rs * gw[cc + 1] + bw[cc + 1];
                *reinterpret_cast<float2*>(out + (size_t)r * 128 + cc) = o;
            }
        }
    }
}

// ---------------- launch ----------------
extern "C" void kernel_launch(void* const* d_in, const int* in_sizes, int n_in,
                              void* d_out, int out_size) {
    const float* x_v    = (const float*)d_in[0];
    const float* qkv_w  = (const float*)d_in[1];
    const float* qkv_b  = (const float*)d_in[2];
    const float* proj_w = (const float*)d_in[3];
    const float* proj_b = (const float*)d_in[4];
    const float* rpb    = (const float*)d_in[5];
    const float* n1w    = (const float*)d_in[6];
    const float* n1b    = (const float*)d_in[7];
    const float* n2w    = (const float*)d_in[8];
    const float* n2b    = (const float*)d_in[9];
    const float* fc1w   = (const float*)d_in[10];
    const float* fc1b   = (const float*)d_in[11];
    const float* fc2w   = (const float*)d_in[12];
    const float* fc2b   = (const float*)d_in[13];
    float* out = (float*)d_out;

    float *qkvb, *attn, *xln, *xres, *ps;
    unsigned* wtf;
    cudaGetSymbolAddress((void**)&qkvb, g_qkv);
    cudaGetSymbolAddress((void**)&attn, g_attn);
    cudaGetSymbolAddress((void**)&xln,  g_xln);
    cudaGetSymbolAddress((void**)&xres, g_xres);
    cudaGetSymbolAddress((void**)&ps,   g_ps);
    cudaGetSymbolAddress((void**)&wtf,  g_wtf);

    cudaFuncSetAttribute(qkv_kernel, cudaFuncAttributeMaxDynamicSharedMemorySize, QKV_SMEM);
    cudaFuncSetAttribute(attn_kernel, cudaFuncAttributeMaxDynamicSharedMemorySize, SMEM_ATTN);
    cudaFuncSetAttribute(projln_kernel, cudaFuncAttributeMaxDynamicSharedMemorySize, PROJ_SMEM);
    cudaFuncSetAttribute(mlp_kernel, cudaFuncAttributeMaxDynamicSharedMemorySize, MLP_SMEM);

    // 0. weight conversion (qkv/proj tf32, fc1/fc2 bf16x2) + rpb/mask table
    cvt_weights<<<512, 256>>>(qkv_w, proj_w, fc1w, fc2w, wtf);
    ps_kernel<<<dim3(256, 4), 256>>>(rpb, ps);
    // 1. qkv = gather(x_v) @ qkv_w^T + b  (outputs pre-rounded, Q pre-scaled)
    qkv_kernel<<<1024, 512, QKV_SMEM>>>(x_v, wtf, qkv_b, qkvb);
    // 2. window attention
    attn_kernel<<<dim3(1024, HEADS), 256, SMEM_ATTN>>>(qkvb, ps, attn);
    // 3. proj + scatter + residual + LN2
    projln_kernel<<<1024, 256, PROJ_SMEM>>>(attn, wtf + 49152, proj_b,
                                            x_v, xres, xln, n2w, n2b);
    // 4. fused MLP (bf16 tensor cores) -> final output
    mlp_kernel<<<1024, 512, MLP_SMEM>>>(xln, wtf + 65536, wtf + 98304,
                                        fc1b, fc2b, xres, out, n1w, n1b);
}

// round 12
// speedup vs baseline: 2.3108x; 1.0653x over previous
#include <cuda_runtime.h>
#include <math.h>

// ---------------- problem constants ----------------
#define M_TOT 131072
#define HEADS 4

// ---------------- scratch ----------------
__device__ float g_qkv [(size_t)M_TOT * 3 * 128];
__device__ float g_attn[(size_t)M_TOT * 64];      // bf16x2 words (128 cols)
__device__ float g_xln [(size_t)M_TOT * 128];
__device__ float g_xres[(size_t)M_TOT * 128];
__device__ float g_ps  [256 * 4 * 4096];          // rpb+mask, C-frag order
__device__ unsigned g_wtf[122880];  // qkv tf32(rm) | proj bf16(frag) | fc1 bf16x2 | fc2 bf16x2

__device__ __forceinline__ int perm_row(int r) {
    int b_ = r >> 7, tt = r & 127;
    int b = b_ >> 8, w = b_ & 255;
    int wh = w >> 4, ww = w & 15;
    int t = tt >> 6, n = tt & 63;
    int i = n >> 3, j = n & 7;
    int oh = (wh * 8 + i + 4) & 127;
    int ow = (ww * 8 + j + 4) & 127;
    return (b * 2 + t) * 16384 + oh * 128 + ow;
}

__device__ __forceinline__ unsigned f2tf(float f) {
    unsigned u;
    asm("cvt.rna.tf32.f32 %0, %1;" : "=r"(u) : "f"(f));
    return u;
}
__device__ __forceinline__ float round_tf(float f) { return __uint_as_float(f2tf(f)); }

// pack two floats -> bf16x2 word (lo = first arg in low half)
__device__ __forceinline__ unsigned pack_bf(float lo, float hi) {
    unsigned d;
    asm("cvt.rn.bf16x2.f32 %0, %1, %2;" : "=r"(d) : "f"(hi), "f"(lo));
    return d;
}

#define MMA_TF32(d, a0, a1, a2, a3, b0, b1)                                            \
    asm volatile(                                                                      \
        "mma.sync.aligned.m16n8k8.row.col.f32.tf32.tf32.f32 "                          \
        "{%0,%1,%2,%3},{%4,%5,%6,%7},{%8,%9},{%0,%1,%2,%3};"                           \
        : "+f"(d[0]), "+f"(d[1]), "+f"(d[2]), "+f"(d[3])                               \
        : "r"(a0), "r"(a1), "r"(a2), "r"(a3), "r"(b0), "r"(b1))

#define MMA_BF16(d, a0, a1, a2, a3, b0, b1)                                            \
    asm volatile(                                                                      \
        "mma.sync.aligned.m16n8k16.row.col.f32.bf16.bf16.f32 "                         \
        "{%0,%1,%2,%3},{%4,%5,%6,%7},{%8,%9},{%0,%1,%2,%3};"                           \
        : "+f"(d[0]), "+f"(d[1]), "+f"(d[2]), "+f"(d[3])                               \
        : "r"(a0), "r"(a1), "r"(a2), "r"(a3), "r"(b0), "r"(b1))

// ---------------- weight pre-conversion ----------------
// qkv tf32 rm [0,49152) | proj bf16 B-frag [49152,57344) | fc1 bf16x2 [57344,90112) | fc2 [90112,122880)
__global__ void cvt_weights(const float* __restrict__ qkv_w, const float* __restrict__ proj_w,
                            const float* __restrict__ fc1_w, const float* __restrict__ fc2_w,
                            unsigned* __restrict__ wtf) {
    int i = blockIdx.x * 256 + threadIdx.x;
    if (i < 49152) { wtf[i] = f2tf(qkv_w[i]); return; }
    if (i < 57344) {                 // proj: uint2 pairs (b0,b1) per (n8, kc, lane)
        int j = i - 49152;           // 0..8191
        int half = j & 1, pos = j >> 1;
        int lane = pos & 31, kc = (pos >> 5) & 7, n8 = pos >> 8;
        int g = lane >> 2, t = lane & 3;
        int n = n8 * 8 + g;
        int kb = 16 * kc + (half ? 8 : 0) + 2 * t;
        wtf[i] = pack_bf(proj_w[n * 128 + kb], proj_w[n * 128 + kb + 1]);
        return;
    }
    if (i < 90112) {                 // fc1: [512][64 words]
        int j = i - 57344;
        int n = j >> 6, w = j & 63;
        wtf[i] = pack_bf(fc1_w[n * 128 + 2 * w], fc1_w[n * 128 + 2 * w + 1]);
        return;
    }
    {                                // fc2: [128][256 words]
        int j = i - 90112;
        int n = j >> 8, w = j & 255;
        wtf[i] = pack_bf(fc2_w[n * 512 + 2 * w], fc2_w[n * 512 + 2 * w + 1]);
    }
}

// ---------------- rpb + shift-mask table in C-frag order ----------------
__global__ void ps_kernel(const float* __restrict__ rpb, float* __restrict__ ps) {
    int wwin = blockIdx.x;
    int head = blockIdx.y;
    int wh = wwin >> 4, ww = wwin & 15;
    int tid = threadIdx.x;
    float* dst = ps + (size_t)(wwin * 4 + head) * 4096;
#pragma unroll
    for (int it = 0; it < 16; it++) {
        int e = tid + it * 256;
        int qn = e >> 6, kn = e & 63;
        int qi2 = qn >> 3, qj = qn & 7, ki = kn >> 3, kj = kn & 7;
        int rel = (qi2 - ki + 7) * 15 + (qj - kj + 7);
        float v = rpb[rel * HEADS + head];
        int gqh = wh * 8 + qi2, gqw = ww * 8 + qj;
        int gkh = wh * 8 + ki,  gkw = ww * 8 + kj;
        int rq = (gqh < 120 ? 0 : (gqh < 124 ? 1 : 2)) * 3 + (gqw < 120 ? 0 : (gqw < 124 ? 1 : 2));
        int rk = (gkh < 120 ? 0 : (gkh < 124 ? 1 : 2)) * 3 + (gkw < 120 ? 0 : (gkw < 124 ? 1 : 2));
        if (rq != rk) v -= 100.0f;
        int qtile = qn >> 4, ntile = kn >> 3;
        int ln = (qn & 7) * 4 + ((kn & 7) >> 1);
        int reg = ((qn >> 3) & 1) * 2 + (kn & 1);
        dst[((qtile * 8 + ntile) * 32 + ln) * 4 + reg] = v;
    }
}

// ---------------- qkv GEMM: A staged once, weights streamed (unchanged) ----------------
#define QKV_SMEM ((16896 + 16896) * 4)
__global__ __launch_bounds__(512) void qkv_kernel(
    const float* __restrict__ xv, const unsigned* __restrict__ Wq_,
    const float* __restrict__ bias, float* __restrict__ out) {
    extern __shared__ unsigned sm[];
    unsigned* XA = sm;
    unsigned* WB = sm + 16896;

    const uint4* Wg = reinterpret_cast<const uint4*>(Wq_);
    const int tid = threadIdx.x;
    const int lane = tid & 31;
    const int wid = tid >> 5;
    const int wm = wid >> 2, wn = wid & 3;
    const int g = lane >> 2, t = lane & 3;
    const int bm = blockIdx.x * 128;
    const float scale = 0.17677669529663687f;

#pragma unroll
    for (int it = 0; it < 8; it++) {
        int c = tid + it * 512;
        int row = c >> 5, kq = c & 31;
        int src = perm_row(bm + row);
        float4 v = *reinterpret_cast<const float4*>(xv + (size_t)src * 128 + kq * 4);
        int sts = ((row >> 4) * 2 + ((row >> 3) & 1)) * 1056 + (kq >> 1) * 66 + (row & 7) * 8 + (kq & 1);
        XA[sts + 0] = f2tf(v.x); XA[sts + 2] = f2tf(v.y);
        XA[sts + 4] = f2tf(v.z); XA[sts + 6] = f2tf(v.w);
    }

    int wsrc[4], wst[4];
#pragma unroll
    for (int it = 0; it < 4; it++) {
        int e = tid + it * 512;
        int n = e >> 5, kq = e & 31;
        wsrc[it] = n * 32 + kq;
        wst[it] = (n >> 3) * 1056 + (kq >> 1) * 66 + (n & 7) * 8 + (kq & 1);
    }
    {
        uint4 v[4];
#pragma unroll
        for (int it = 0; it < 4; it++) v[it] = Wg[wsrc[it]];
#pragma unroll
        for (int it = 0; it < 4; it++) {
            WB[wst[it] + 0] = v[it].x; WB[wst[it] + 2] = v[it].y;
            WB[wst[it] + 4] = v[it].z; WB[wst[it] + 6] = v[it].w;
        }
    }
    __syncthreads();

    int p = 0;
    for (int c = 0; c < 6; c++) {
        uint4 wv[4];
        if (c < 5) {
#pragma unroll
            for (int it = 0; it < 4; it++) wv[it] = Wg[wsrc[it] + (c + 1) * 2048];
        }
        unsigned* Wp = WB + p * 8448;

        float accs[2][2][4];
#pragma unroll
        for (int mi = 0; mi < 2; mi++)
#pragma unroll
            for (int ni = 0; ni < 2; ni++)
#pragma unroll
                for (int q = 0; q < 4; q++) accs[mi][ni][q] = 0.f;

#pragma unroll
        for (int k8 = 0; k8 < 16; k8++) {
            unsigned a[2][4], b[2][2];
#pragma unroll
            for (int mi = 0; mi < 2; mi++) {
                int base = ((wm * 2 + mi) * 2) * 1056 + k8 * 66 + lane * 2;
                uint2 q0 = *reinterpret_cast<const uint2*>(&XA[base]);
                uint2 q1 = *reinterpret_cast<const uint2*>(&XA[base + 1056]);
                a[mi][0] = q0.x; a[mi][2] = q0.y;
                a[mi][1] = q1.x; a[mi][3] = q1.y;
            }
#pragma unroll
            for (int ni = 0; ni < 2; ni++) {
                uint2 q = *reinterpret_cast<const uint2*>(&Wp[(wn * 2 + ni) * 1056 + k8 * 66 + lane * 2]);
                b[ni][0] = q.x; b[ni][1] = q.y;
            }
#pragma unroll
            for (int mi = 0; mi < 2; mi++)
#pragma unroll
                for (int ni = 0; ni < 2; ni++)
                    MMA_TF32(accs[mi][ni], a[mi][0], a[mi][1], a[mi][2], a[mi][3],
                             b[ni][0], b[ni][1]);
        }

        float sc = (c < 2) ? scale : 1.0f;
#pragma unroll
        for (int mi = 0; mi < 2; mi++) {
#pragma unroll
            for (int rh = 0; rh < 2; rh++) {
                int r = bm + wm * 32 + mi * 16 + g + rh * 8;
#pragma unroll
                for (int ni = 0; ni < 2; ni++) {
                    int col = c * 64 + wn * 16 + ni * 8 + t * 2;
                    float2 o;
                    o.x = round_tf((accs[mi][ni][rh * 2 + 0] + bias[col]) * sc);
                    o.y = round_tf((accs[mi][ni][rh * 2 + 1] + bias[col + 1]) * sc);
                    *reinterpret_cast<float2*>(out + (size_t)r * 384 + col) = o;
                }
            }
        }

        if (c < 5) {
            unsigned* Wn = WB + (p ^ 1) * 8448;
#pragma unroll
            for (int it = 0; it < 4; it++) {
                Wn[wst[it] + 0] = wv[it].x; Wn[wst[it] + 2] = wv[it].y;
                Wn[wst[it] + 4] = wv[it].z; Wn[wst[it] + 6] = wv[it].w;
            }
            p ^= 1;
        }
        __syncthreads();
    }
}

// ---------------- window attention: tf32 QK + bf16 PV (shuffle-free) ----------------
// smem words: QA 0..4224 | KB 4224..8448 | VB(bf16) 8448..10560
#define SM_QA 0
#define SM_KB 4224
#define SM_VB 8448
#define SMEM_ATTN (10560 * 4)

__global__ __launch_bounds__(256) void attn_kernel(const float* __restrict__ qkv,
                                                   const float* __restrict__ ps,
                                                   unsigned* __restrict__ attout) {
    extern __shared__ unsigned sm[];
    unsigned* QA = sm + SM_QA;
    unsigned* KB = sm + SM_KB;
    unsigned* VB = sm + SM_VB;

    const int win = blockIdx.x, head = blockIdx.y;
    const int tid = threadIdx.x;
    const int lane = tid & 31, w = tid >> 5;
    const int g = lane >> 2, t = lane & 3;
    const float* psh = ps + (size_t)((win & 255) * 4 + head) * 4096;
    const uint4* qkv4 = reinterpret_cast<const uint4*>(qkv);

    // stage Q, K (raw tf32 bits)
#pragma unroll
    for (int it = 0; it < 4; it++) {
        int c = tid + it * 256;
        int row = c >> 3, kq = c & 7;
        size_t base4 = ((size_t)(win * 128 + row)) * 96 + head * 8 + kq;
        uint4 qv = qkv4[base4];
        uint4 kv = qkv4[base4 + 32];
        int k8 = kq >> 1, kh = kq & 1;
        int qa = ((row >> 4) * 2 + ((row >> 3) & 1)) * 264 + k8 * 66 + (row & 7) * 8 + kh;
        QA[qa + 0] = qv.x; QA[qa + 2] = qv.y; QA[qa + 4] = qv.z; QA[qa + 6] = qv.w;
        int kb = (row >> 3) * 264 + k8 * 66 + (row & 7) * 8 + kh;
        KB[kb + 0] = kv.x; KB[kb + 2] = kv.y; KB[kb + 4] = kv.z; KB[kb + 6] = kv.w;
    }
    // stage V as bf16 pairs along tokens: word(n=dim, kw=tokenpair)
#pragma unroll
    for (int it = 0; it < 2; it++) {
        int e = tid + it * 256;          // 0..511
        int kq = e & 7, tp = e >> 3;     // tp = token pair 0..63
        size_t vb4 = ((size_t)(win * 128 + 2 * tp)) * 96 + head * 8 + 64 + kq;
        float4 ve = *reinterpret_cast<const float4*>(qkv + (vb4 << 2));
        float4 vo = *reinterpret_cast<const float4*>(qkv + ((vb4 + 96) << 2));
        int kc = tp >> 3, kw = tp & 7;
        int off = (kw & 3) * 2 + (kw >> 2);
        float e4[4] = {ve.x, ve.y, ve.z, ve.w};
        float o4[4] = {vo.x, vo.y, vo.z, vo.w};
#pragma unroll
        for (int dd = 0; dd < 4; dd++) {
            int n = kq * 4 + dd;
            VB[(n >> 3) * 528 + kc * 66 + (n & 7) * 8 + off] = pack_bf(e4[dd], o4[dd]);
        }
    }
    __syncthreads();

    // S = Q @ K^T (tf32)
    float acc[16][4];
#pragma unroll
    for (int nt = 0; nt < 16; nt++)
#pragma unroll
        for (int i = 0; i < 4; i++) acc[nt][i] = 0.f;

#pragma unroll
    for (int k8 = 0; k8 < 4; k8++) {
        int abase = (w * 2) * 264 + k8 * 66 + lane * 2;
        uint2 q0 = *reinterpret_cast<const uint2*>(&QA[abase]);
        uint2 q1 = *reinterpret_cast<const uint2*>(&QA[abase + 264]);
#pragma unroll
        for (int nt = 0; nt < 16; nt++) {
            uint2 b = *reinterpret_cast<const uint2*>(&KB[nt * 264 + k8 * 66 + lane * 2]);
            MMA_TF32(acc[nt], q0.x, q1.x, q0.y, q1.y, b.x, b.y);
        }
    }

    // + rpb/mask, softmax
    const int qtile = w & 3;
    float m0 = -1e30f, m1 = -1e30f;
#pragma unroll
    for (int nt = 0; nt < 16; nt++) {
        float4 p = *reinterpret_cast<const float4*>(psh + ((qtile * 8 + (nt & 7)) * 32 + lane) * 4);
        acc[nt][0] += p.x; acc[nt][1] += p.y;
        acc[nt][2] += p.z; acc[nt][3] += p.w;
        m0 = fmaxf(m0, fmaxf(acc[nt][0], acc[nt][1]));
        m1 = fmaxf(m1, fmaxf(acc[nt][2], acc[nt][3]));
    }
    m0 = fmaxf(m0, __shfl_xor_sync(0xffffffffu, m0, 1));
    m0 = fmaxf(m0, __shfl_xor_sync(0xffffffffu, m0, 2));
    m1 = fmaxf(m1, __shfl_xor_sync(0xffffffffu, m1, 1));
    m1 = fmaxf(m1, __shfl_xor_sync(0xffffffffu, m1, 2));

    float l0 = 0.f, l1 = 0.f;
#pragma unroll
    for (int nt = 0; nt < 16; nt++) {
        acc[nt][0] = __expf(acc[nt][0] - m0);
        acc[nt][1] = __expf(acc[nt][1] - m0);
        acc[nt][2] = __expf(acc[nt][2] - m1);
        acc[nt][3] = __expf(acc[nt][3] - m1);
        l0 += acc[nt][0] + acc[nt][1];
        l1 += acc[nt][2] + acc[nt][3];
    }
    l0 += __shfl_xor_sync(0xffffffffu, l0, 1);
    l0 += __shfl_xor_sync(0xffffffffu, l0, 2);
    l1 += __shfl_xor_sync(0xffffffffu, l1, 1);
    l1 += __shfl_xor_sync(0xffffffffu, l1, 2);
    float inv0 = 1.0f / l0, inv1 = 1.0f / l1;

    // O = P @ V (bf16): C-frag cols (2t,2t+1) pack directly into bf16 A k-pairs
    float oacc[4][4];
#pragma unroll
    for (int n8 = 0; n8 < 4; n8++)
#pragma unroll
        for (int i = 0; i < 4; i++) oacc[n8][i] = 0.f;

#pragma unroll
    for (int kc = 0; kc < 8; kc++) {
        unsigned a0 = pack_bf(acc[2 * kc][0], acc[2 * kc][1]);
        unsigned a1 = pack_bf(acc[2 * kc][2], acc[2 * kc][3]);
        unsigned a2 = pack_bf(acc[2 * kc + 1][0], acc[2 * kc + 1][1]);
        unsigned a3 = pack_bf(acc[2 * kc + 1][2], acc[2 * kc + 1][3]);
#pragma unroll
        for (int n8 = 0; n8 < 4; n8++) {
            uint2 b = *reinterpret_cast<const uint2*>(&VB[n8 * 528 + kc * 66 + lane * 2]);
            MMA_BF16(oacc[n8], a0, a1, a2, a3, b.x, b.y);
        }
    }

    // write packed bf16x2 output (64 words/row)
    int r0 = win * 128 + w * 16 + g;
#pragma unroll
    for (int n8 = 0; n8 < 4; n8++) {
        int colw = head * 16 + n8 * 4 + t;
        attout[(size_t)r0 * 64 + colw]       = pack_bf(oacc[n8][0] * inv0, oacc[n8][1] * inv0);
        attout[(size_t)(r0 + 8) * 64 + colw] = pack_bf(oacc[n8][2] * inv1, oacc[n8][3] * inv1);
    }
}

// ---------------- proj (bf16) + scatter + residual + LN2 ----------------
#define PROJ_SMEM (8448 * 4)
__global__ __launch_bounds__(256) void projln_kernel(
    const unsigned* __restrict__ attn, const unsigned* __restrict__ Wp_,
    const float* __restrict__ bias, const float* __restrict__ res,
    float* __restrict__ xres, float* __restrict__ xln,
    const float* __restrict__ gw, const float* __restrict__ bw) {
    extern __shared__ unsigned sm[];
    unsigned* OA = sm;   // 16 rowgrps x 528 words (bf16x2)
    __shared__ float smS[128][2], smQ[128][2];

    const int win = blockIdx.x;
    const int tid = threadIdx.x;
    const int lane = tid & 31, w = tid >> 5;
    const int g = lane >> 2, t = lane & 3;
    const int wm = w >> 1, wn = w & 1;

    // stage A: packed words -> A-frag word layout
    const uint4* attn4 = reinterpret_cast<const uint4*>(attn);
#pragma unroll
    for (int it = 0; it < 8; it++) {
        int e = tid + it * 256;      // 0..2047
        int row = e >> 4, q4 = e & 15;
        uint4 v = attn4[((size_t)(win * 128 + row)) * 16 + q4];
        int base = ((row >> 4) * 2 + ((row >> 3) & 1)) * 528 + (row & 7) * 8 +
                   (q4 >> 1) * 66 + (q4 & 1);
        OA[base + 0] = v.x; OA[base + 2] = v.y; OA[base + 4] = v.z; OA[base + 6] = v.w;
    }
    __syncthreads();

    const uint2* Wp2 = reinterpret_cast<const uint2*>(Wp_);
    float acc2[2][8][4];
#pragma unroll
    for (int mi = 0; mi < 2; mi++)
#pragma unroll
        for (int ni = 0; ni < 8; ni++)
#pragma unroll
            for (int q = 0; q < 4; q++) acc2[mi][ni][q] = 0.f;

#pragma unroll
    for (int k16 = 0; k16 < 8; k16++) {
        unsigned a[2][4];
#pragma unroll
        for (int mi = 0; mi < 2; mi++) {
            int base = ((wm * 2 + mi) * 2) * 528 + k16 * 66 + lane * 2;
            uint2 q0 = *reinterpret_cast<const uint2*>(&OA[base]);
            uint2 q1 = *reinterpret_cast<const uint2*>(&OA[base + 528]);
            a[mi][0] = q0.x; a[mi][2] = q0.y;
            a[mi][1] = q1.x; a[mi][3] = q1.y;
        }
#pragma unroll
        for (int ni = 0; ni < 8; ni++) {
            uint2 b = Wp2[((wn * 8 + ni) * 8 + k16) * 32 + lane];
#pragma unroll
            for (int mi = 0; mi < 2; mi++)
                MMA_BF16(acc2[mi][ni], a[mi][0], a[mi][1], a[mi][2], a[mi][3], b.x, b.y);
        }
    }

#pragma unroll
    for (int mi = 0; mi < 2; mi++) {
#pragma unroll
        for (int rh = 0; rh < 2; rh++) {
            int lrow = wm * 32 + mi * 16 + g + rh * 8;
            int xrow = perm_row(win * 128 + lrow);
            float v[16];
            float s = 0.f, q = 0.f;
#pragma unroll
            for (int ni = 0; ni < 8; ni++) {
                int cc = wn * 64 + ni * 8 + t * 2;
                float2 rr = *reinterpret_cast<const float2*>(res + (size_t)xrow * 128 + cc);
                float x0 = acc2[mi][ni][rh * 2 + 0] + bias[cc] + rr.x;
                float x1 = acc2[mi][ni][rh * 2 + 1] + bias[cc + 1] + rr.y;
                *reinterpret_cast<float2*>(xres + (size_t)xrow * 128 + cc) = make_float2(x0, x1);
                v[ni * 2 + 0] = x0; v[ni * 2 + 1] = x1;
                s += x0 + x1; q += x0 * x0 + x1 * x1;
            }
            s += __shfl_xor_sync(0xffffffffu, s, 1);
            s += __shfl_xor_sync(0xffffffffu, s, 2);
            q += __shfl_xor_sync(0xffffffffu, q, 1);
            q += __shfl_xor_sync(0xffffffffu, q, 2);
            if (t == 0) { smS[lrow][wn] = s; smQ[lrow][wn] = q; }
            __syncthreads();
            float S = smS[lrow][0] + smS[lrow][1];
            float Q = smQ[lrow][0] + smQ[lrow][1];
            float mu = S * (1.f / 128.f);
            float var = Q * (1.f / 128.f) - mu * mu;
            float rs = rsqrtf(var + 1e-5f);
#pragma unroll
            for (int ni = 0; ni < 8; ni++) {
                int cc = wn * 64 + ni * 8 + t * 2;
                float2 o;
                o.x = round_tf((v[ni * 2 + 0] - mu) * rs * gw[cc] + bw[cc]);
                o.y = round_tf((v[ni * 2 + 1] - mu) * rs * gw[cc + 1] + bw[cc + 1]);
                *reinterpret_cast<float2*>(xln + (size_t)xrow * 128 + cc) = o;
            }
        }
    }
}

// ---------------- fused MLP (bf16): fc1 + gelu + fc2 + residual + LN1 (unchanged) ----------------
#define MLP_SMEM (21120 * 4)
__global__ __launch_bounds__(512) void mlp_kernel(
    const float* __restrict__ xln, const unsigned* __restrict__ W1g4_,
    const unsigned* __restrict__ W2g4_,
    const float* __restrict__ b1, const float* __restrict__ b2,
    const float* __restrict__ res, float* __restrict__ out,
    const float* __restrict__ gw, const float* __restrict__ bw) {
    extern __shared__ unsigned sm[];
    unsigned* XA = sm;
    unsigned* W1 = sm + 8448;
    unsigned* W2 = sm + 12672;
    unsigned* HH = sm + 16896;
    __shared__ float smS[128][4], smQ[128][4];

    const uint4* W1g = reinterpret_cast<const uint4*>(W1g4_);
    const uint4* W2g = reinterpret_cast<const uint4*>(W2g4_);

    const int tid = threadIdx.x;
    const int lane = tid & 31;
    const int wid = tid >> 5;
    const int wm = wid >> 2, wn = wid & 3;
    const int g = lane >> 2, t = lane & 3;
    const int bm = blockIdx.x * 128;

#pragma unroll
    for (int it = 0; it < 8; it++) {
        int c = tid + it * 512;
        int row = c >> 5, kq = c & 31;
        float4 v = *reinterpret_cast<const float4*>(xln + (size_t)(bm + row) * 128 + kq * 4);
        int rg = ((row >> 4) * 2 + ((row >> 3) & 1)) * 528 + (row & 7) * 8;
        int w0 = 2 * kq, w1 = 2 * kq + 1;
        XA[rg + (w0 >> 3) * 66 + ((w0 >> 2) & 1) + 2 * (w0 & 3)] = pack_bf(v.x, v.y);
        XA[rg + (w1 >> 3) * 66 + ((w1 >> 2) & 1) + 2 * (w1 & 3)] = pack_bf(v.z, v.w);
    }

    int w1src[2], w1st[2], w2src[2], w2st[2];
#pragma unroll
    for (int it = 0; it < 2; it++) {
        int e = tid + it * 512;
        int n = e >> 4, wq = e & 15;
        w1src[it] = n * 16 + wq;
        w1st[it] = (n >> 3) * 528 + (wq >> 1) * 66 + (n & 7) * 8 + (wq & 1);
        int n2 = e >> 3, wq2 = e & 7;
        w2src[it] = n2 * 64 + wq2;
        w2st[it] = (n2 >> 3) * 264 + (wq2 >> 1) * 66 + (n2 & 7) * 8 + (wq2 & 1);
    }

    {
        uint4 v[2];
#pragma unroll
        for (int it = 0; it < 2; it++) v[it] = W1g[w1src[it]];
#pragma unroll
        for (int it = 0; it < 2; it++) {
            W1[w1st[it] + 0] = v[it].x; W1[w1st[it] + 2] = v[it].y;
            W1[w1st[it] + 4] = v[it].z; W1[w1st[it] + 6] = v[it].w;
        }
    }
    __syncthreads();

    float acco[2][4][4];
#pragma unroll
    for (int mi = 0; mi < 2; mi++)
#pragma unroll
        for (int ni = 0; ni < 4; ni++)
#pragma unroll
            for (int c = 0; c < 4; c++) acco[mi][ni][c] = 0.f;

    for (int c = 0; c < 8; c++) {
        uint4 w2v[2];
#pragma unroll
        for (int it = 0; it < 2; it++) w2v[it] = W2g[w2src[it] + c * 8];

        float accs[2][2][4];
#pragma unroll
        for (int mi = 0; mi < 2; mi++)
#pragma unroll
            for (int ni = 0; ni < 2; ni++)
#pragma unroll
                for (int q = 0; q < 4; q++) accs[mi][ni][q] = 0.f;
#pragma unroll
        for (int k16 = 0; k16 < 8; k16++) {
            unsigned a[2][4], b[2][2];
#pragma unroll
            for (int mi = 0; mi < 2; mi++) {
                int base = ((wm * 2 + mi) * 2) * 528 + k16 * 66 + lane * 2;
                uint2 q0 = *reinterpret_cast<const uint2*>(&XA[base]);
                uint2 q1 = *reinterpret_cast<const uint2*>(&XA[base + 528]);
                a[mi][0] = q0.x; a[mi][2] = q0.y;
                a[mi][1] = q1.x; a[mi][3] = q1.y;
            }
#pragma unroll
            for (int ni = 0; ni < 2; ni++) {
                uint2 q = *reinterpret_cast<const uint2*>(&W1[(wn * 2 + ni) * 528 + k16 * 66 + lane * 2]);
                b[ni][0] = q.x; b[ni][1] = q.y;
            }
#pragma unroll
            for (int mi = 0; mi < 2; mi++)
#pragma unroll
                for (int ni = 0; ni < 2; ni++)
                    MMA_BF16(accs[mi][ni], a[mi][0], a[mi][1], a[mi][2], a[mi][3],
                             b[ni][0], b[ni][1]);
        }

#pragma unroll
        for (int it = 0; it < 2; it++) {
            W2[w2st[it] + 0] = w2v[it].x; W2[w2st[it] + 2] = w2v[it].y;
            W2[w2st[it] + 4] = w2v[it].z; W2[w2st[it] + 6] = w2v[it].w;
        }

#pragma unroll
        for (int mi = 0; mi < 2; mi++) {
#pragma unroll
            for (int ni = 0; ni < 2; ni++) {
                int kl0 = wn * 16 + ni * 8 + t * 2;
                int ww = kl0 >> 1;
                int wof = (ww >> 3) * 66 + ((ww >> 2) & 1) + 2 * (ww & 3);
                float bb0 = b1[c * 64 + kl0], bb1 = b1[c * 64 + kl0 + 1];
#pragma unroll
                for (int rh = 0; rh < 2; rh++) {
                    float x0 = accs[mi][ni][rh * 2 + 0] + bb0;
                    float x1 = accs[mi][ni][rh * 2 + 1] + bb1;
                    x0 = 0.5f * x0 * (1.0f + erff(x0 * 0.7071067811865475f));
                    x1 = 0.5f * x1 * (1.0f + erff(x1 * 0.7071067811865475f));
                    int addr = ((wm * 2 + mi) * 2 + rh) * 264 + wof + g * 8;
                    HH[addr] = pack_bf(x0, x1);
                }
            }
        }
        __syncthreads();

        uint4 w1v[2];
        if (c < 7) {
#pragma unroll
            for (int it = 0; it < 2; it++) w1v[it] = W1g[w1src[it] + (c + 1) * 1024];
        }

#pragma unroll
        for (int k16 = 0; k16 < 4; k16++) {
            unsigned a[2][4], b[4][2];
#pragma unroll
            for (int mi = 0; mi < 2; mi++) {
                int base = ((wm * 2 + mi) * 2) * 264 + k16 * 66 + lane * 2;
                uint2 q0 = *reinterpret_cast<const uint2*>(&HH[base]);
                uint2 q1 = *reinterpret_cast<const uint2*>(&HH[base + 264]);
                a[mi][0] = q0.x; a[mi][2] = q0.y;
                a[mi][1] = q1.x; a[mi][3] = q1.y;
            }
#pragma unroll
            for (int ni = 0; ni < 4; ni++) {
                uint2 q = *reinterpret_cast<const uint2*>(&W2[(wn * 4 + ni) * 264 + k16 * 66 + lane * 2]);
                b[ni][0] = q.x; b[ni][1] = q.y;
            }
#pragma unroll
            for (int mi = 0; mi < 2; mi++)
#pragma unroll
                for (int ni = 0; ni < 4; ni++)
                    MMA_BF16(acco[mi][ni], a[mi][0], a[mi][1], a[mi][2], a[mi][3],
                             b[ni][0], b[ni][1]);
        }

        if (c < 7) {
#pragma unroll
            for (int it = 0; it < 2; it++) {
                W1[w1st[it] + 0] = w1v[it].x; W1[w1st[it] + 2] = w1v[it].y;
                W1[w1st[it] + 4] = w1v[it].z; W1[w1st[it] + 6] = w1v[it].w;
            }
        }
        __syncthreads();
    }

#pragma unroll
    for (int mi = 0; mi < 2; mi++) {
#pragma unroll
        for (int rh = 0; rh < 2; rh++) {
            int lrow = wm * 32 + mi * 16 + g + rh * 8;
            int r = bm + lrow;
            float v[8];
            float s = 0.f, q = 0.f;
#pragma unroll
            for (int ni = 0; ni < 4; ni++) {
                int cc = wn * 32 + ni * 8 + t * 2;
                float2 rr = *reinterpret_cast<const float2*>(res + (size_t)r * 128 + cc);
                float x0 = acco[mi][ni][rh * 2 + 0] + b2[cc] + rr.x;
                float x1 = acco[mi][ni][rh * 2 + 1] + b2[cc + 1] + rr.y;
                v[ni * 2 + 0] = x0; v[ni * 2 + 1] = x1;
                s += x0 + x1; q += x0 * x0 + x1 * x1;
            }
            s += __shfl_xor_sync(0xffffffffu, s, 1);
            s += __shfl_xor_sync(0xffffffffu, s, 2);
            q += __shfl_xor_sync(0xffffffffu, q, 1);
            q += __shfl_xor_sync(0xffffffffu, q, 2);
            if (t == 0) { smS[lrow][wn] = s; smQ[lrow][wn] = q; }
            __syncthreads();
            float S = smS[lrow][0] + smS[lrow][1] + smS[lrow][2] + smS[lrow][3];
            float Q = smQ[lrow][0] + smQ[lrow][1] + smQ[lrow][2] + smQ[lrow][3];
            float mu = S * (1.f / 128.f);
            float var = Q * (1.f / 128.f) - mu * mu;
            float rs = rsqrtf(var + 1e-5f);
#pragma unroll
            for (int ni = 0; ni < 4; ni++) {
                int cc = wn * 32 + ni * 8 + t * 2;
                float2 o;
                o.x = (v[ni * 2 + 0] - mu) * rs * gw[cc] + bw[cc];
                o.y = (v[ni * 2 + 1] - mu) * rs * gw[cc + 1] + bw[cc + 1];
                *reinterpret_cast<float2*>(out + (size_t)r * 128 + cc) = o;
            }
        }
    }
}

// ---------------- launch ----------------
extern "C" void kernel_launch(void* const* d_in, const int* in_sizes, int n_in,
                              void* d_out, int out_size) {
    const float* x_v    = (const float*)d_in[0];
    const float* qkv_w  = (const float*)d_in[1];
    const float* qkv_b  = (const float*)d_in[2];
    const float* proj_w = (const float*)d_in[3];
    const float* proj_b = (const float*)d_in[4];
    const float* rpb    = (const float*)d_in[5];
    const float* n1w    = (const float*)d_in[6];
    const float* n1b    = (const float*)d_in[7];
    const float* n2w    = (const float*)d_in[8];
    const float* n2b    = (const float*)d_in[9];
    const float* fc1w   = (const float*)d_in[10];
    const float* fc1b   = (const float*)d_in[11];
    const float* fc2w   = (const float*)d_in[12];
    const float* fc2b   = (const float*)d_in[13];
    float* out = (float*)d_out;

    float *qkvb, *xln, *xres, *ps;
    unsigned *attn, *wtf;
    cudaGetSymbolAddress((void**)&qkvb, g_qkv);
    cudaGetSymbolAddress((void**)&attn, g_attn);
    cudaGetSymbolAddress((void**)&xln,  g_xln);
    cudaGetSymbolAddress((void**)&xres, g_xres);
    cudaGetSymbolAddress((void**)&ps,   g_ps);
    cudaGetSymbolAddress((void**)&wtf,  g_wtf);

    cudaFuncSetAttribute(qkv_kernel, cudaFuncAttributeMaxDynamicSharedMemorySize, QKV_SMEM);
    cudaFuncSetAttribute(attn_kernel, cudaFuncAttributeMaxDynamicSharedMemorySize, SMEM_ATTN);
    cudaFuncSetAttribute(projln_kernel, cudaFuncAttributeMaxDynamicSharedMemorySize, PROJ_SMEM);
    cudaFuncSetAttribute(mlp_kernel, cudaFuncAttributeMaxDynamicSharedMemorySize, MLP_SMEM);

    // 0. weight conversion + rpb/mask table
    cvt_weights<<<480, 256>>>(qkv_w, proj_w, fc1w, fc2w, wtf);
    ps_kernel<<<dim3(256, 4), 256>>>(rpb, ps);
    // 1. qkv = gather(x_v) @ qkv_w^T + b  (pre-rounded, Q pre-scaled)
    qkv_kernel<<<1024, 512, QKV_SMEM>>>(x_v, wtf, qkv_b, qkvb);
    // 2. window attention: tf32 QK + bf16 PV, writes packed bf16x2
    attn_kernel<<<dim3(1024, HEADS), 256, SMEM_ATTN>>>(qkvb, ps, attn);
    // 3. proj (bf16) + scatter + residual + LN2
    projln_kernel<<<1024, 256, PROJ_SMEM>>>(attn, wtf + 49152, proj_b,
                                            x_v, xres, xln, n2w, n2b);
    // 4. fused MLP (bf16) -> final output
    mlp_kernel<<<1024, 512, MLP_SMEM>>>(xln, wtf + 57344, wtf + 90112,
                                        fc1b, fc2b, xres, out, n1w, n1b);
}

// round 13
// speedup vs baseline: 2.6468x; 1.1454x over previous
#include <cuda_runtime.h>
#include <math.h>

// ---------------- problem constants ----------------
#define M_TOT 131072
#define HEADS 4

// ---------------- scratch ----------------
__device__ unsigned g_qkv [(size_t)M_TOT * 192];  // packed bf16x2: Q|K|V words
__device__ unsigned g_attn[(size_t)M_TOT * 64];   // packed bf16x2 (128 cols)
__device__ float g_xln [(size_t)M_TOT * 128];
__device__ float g_xres[(size_t)M_TOT * 128];
__device__ float g_ps  [256 * 4 * 4096];          // rpb+mask, C-frag order
__device__ unsigned g_wtf[98304];  // qkv bf16(rm) | proj bf16(frag) | fc1 bf16 | fc2 bf16

__device__ __forceinline__ int perm_row(int r) {
    int b_ = r >> 7, tt = r & 127;
    int b = b_ >> 8, w = b_ & 255;
    int wh = w >> 4, ww = w & 15;
    int t = tt >> 6, n = tt & 63;
    int i = n >> 3, j = n & 7;
    int oh = (wh * 8 + i + 4) & 127;
    int ow = (ww * 8 + j + 4) & 127;
    return (b * 2 + t) * 16384 + oh * 128 + ow;
}

__device__ __forceinline__ unsigned f2tf(float f) {
    unsigned u;
    asm("cvt.rna.tf32.f32 %0, %1;" : "=r"(u) : "f"(f));
    return u;
}
__device__ __forceinline__ float round_tf(float f) { return __uint_as_float(f2tf(f)); }

// pack two floats -> bf16x2 word (lo = first arg in low half)
__device__ __forceinline__ unsigned pack_bf(float lo, float hi) {
    unsigned d;
    asm("cvt.rn.bf16x2.f32 %0, %1, %2;" : "=r"(d) : "f"(hi), "f"(lo));
    return d;
}

#define MMA_BF16(d, a0, a1, a2, a3, b0, b1)                                            \
    asm volatile(                                                                      \
        "mma.sync.aligned.m16n8k16.row.col.f32.bf16.bf16.f32 "                         \
        "{%0,%1,%2,%3},{%4,%5,%6,%7},{%8,%9},{%0,%1,%2,%3};"                           \
        : "+f"(d[0]), "+f"(d[1]), "+f"(d[2]), "+f"(d[3])                               \
        : "r"(a0), "r"(a1), "r"(a2), "r"(a3), "r"(b0), "r"(b1))

// ---------------- weight pre-conversion (all bf16 packed) ----------------
// qkv rm [0,24576) | proj B-frag [24576,32768) | fc1 [32768,65536) | fc2 [65536,98304)
__global__ void cvt_weights(const float* __restrict__ qkv_w, const float* __restrict__ proj_w,
                            const float* __restrict__ fc1_w, const float* __restrict__ fc2_w,
                            unsigned* __restrict__ wtf) {
    int i = blockIdx.x * 256 + threadIdx.x;
    if (i < 24576) {                 // qkv: [384][64 words]
        int n = i >> 6, w = i & 63;
        wtf[i] = pack_bf(qkv_w[n * 128 + 2 * w], qkv_w[n * 128 + 2 * w + 1]);
        return;
    }
    if (i < 32768) {                 // proj: uint2 pairs (b0,b1) per (n8, kc, lane)
        int j = i - 24576;
        int half = j & 1, pos = j >> 1;
        int lane = pos & 31, kc = (pos >> 5) & 7, n8 = pos >> 8;
        int g = lane >> 2, t = lane & 3;
        int n = n8 * 8 + g;
        int kb = 16 * kc + (half ? 8 : 0) + 2 * t;
        wtf[i] = pack_bf(proj_w[n * 128 + kb], proj_w[n * 128 + kb + 1]);
        return;
    }
    if (i < 65536) {                 // fc1: [512][64 words]
        int j = i - 32768;
        int n = j >> 6, w = j & 63;
        wtf[i] = pack_bf(fc1_w[n * 128 + 2 * w], fc1_w[n * 128 + 2 * w + 1]);
        return;
    }
    {                                // fc2: [128][256 words]
        int j = i - 65536;
        int n = j >> 8, w = j & 255;
        wtf[i] = pack_bf(fc2_w[n * 512 + 2 * w], fc2_w[n * 512 + 2 * w + 1]);
    }
}

// ---------------- rpb + shift-mask table in C-frag order ----------------
__global__ void ps_kernel(const float* __restrict__ rpb, float* __restrict__ ps) {
    int wwin = blockIdx.x;
    int head = blockIdx.y;
    int wh = wwin >> 4, ww = wwin & 15;
    int tid = threadIdx.x;
    float* dst = ps + (size_t)(wwin * 4 + head) * 4096;
#pragma unroll
    for (int it = 0; it < 16; it++) {
        int e = tid + it * 256;
        int qn = e >> 6, kn = e & 63;
        int qi2 = qn >> 3, qj = qn & 7, ki = kn >> 3, kj = kn & 7;
        int rel = (qi2 - ki + 7) * 15 + (qj - kj + 7);
        float v = rpb[rel * HEADS + head];
        int gqh = wh * 8 + qi2, gqw = ww * 8 + qj;
        int gkh = wh * 8 + ki,  gkw = ww * 8 + kj;
        int rq = (gqh < 120 ? 0 : (gqh < 124 ? 1 : 2)) * 3 + (gqw < 120 ? 0 : (gqw < 124 ? 1 : 2));
        int rk = (gkh < 120 ? 0 : (gkh < 124 ? 1 : 2)) * 3 + (gkw < 120 ? 0 : (gkw < 124 ? 1 : 2));
        if (rq != rk) v -= 100.0f;
        int qtile = qn >> 4, ntile = kn >> 3;
        int ln = (qn & 7) * 4 + ((kn & 7) >> 1);
        int reg = ((qn >> 3) & 1) * 2 + (kn & 1);
        dst[((qtile * 8 + ntile) * 32 + ln) * 4 + reg] = v;
    }
}

// ---------------- qkv GEMM (bf16): A staged once, weights streamed ----------------
// smem words: XA 8448 | WB 2 x 4224
#define QKV_SMEM ((8448 + 8448) * 4)
__global__ __launch_bounds__(512) void qkv_kernel(
    const float* __restrict__ xv, const unsigned* __restrict__ Wq_,
    const float* __restrict__ bias, unsigned* __restrict__ out) {
    extern __shared__ unsigned sm[];
    unsigned* XA = sm;
    unsigned* WB = sm + 8448;

    const uint4* Wg = reinterpret_cast<const uint4*>(Wq_);
    const int tid = threadIdx.x;
    const int lane = tid & 31;
    const int wid = tid >> 5;
    const int wm = wid >> 2, wn = wid & 3;
    const int g = lane >> 2, t = lane & 3;
    const int bm = blockIdx.x * 128;
    const float scale = 0.17677669529663687f;

    // stage XA: perm gather fp32 -> bf16x2 words, A-frag word layout
#pragma unroll
    for (int it = 0; it < 8; it++) {
        int c = tid + it * 512;
        int row = c >> 5, kq = c & 31;
        int src = perm_row(bm + row);
        float4 v = *reinterpret_cast<const float4*>(xv + (size_t)src * 128 + kq * 4);
        int rg = ((row >> 4) * 2 + ((row >> 3) & 1)) * 528 + (row & 7) * 8;
        int w0 = 2 * kq, w1 = 2 * kq + 1;
        XA[rg + (w0 >> 3) * 66 + ((w0 >> 2) & 1) + 2 * (w0 & 3)] = pack_bf(v.x, v.y);
        XA[rg + (w1 >> 3) * 66 + ((w1 >> 2) & 1) + 2 * (w1 & 3)] = pack_bf(v.z, v.w);
    }

    int wsrc[2], wst[2];
#pragma unroll
    for (int it = 0; it < 2; it++) {
        int e = tid + it * 512;              // 0..1023
        int n = e >> 4, wq = e & 15;
        wsrc[it] = n * 16 + wq;              // + chunk*1024 (uint4 units)
        wst[it] = (n >> 3) * 528 + (wq >> 1) * 66 + (n & 7) * 8 + (wq & 1);
    }
    {
        uint4 v[2];
#pragma unroll
        for (int it = 0; it < 2; it++) v[it] = Wg[wsrc[it]];
#pragma unroll
        for (int it = 0; it < 2; it++) {
            WB[wst[it] + 0] = v[it].x; WB[wst[it] + 2] = v[it].y;
            WB[wst[it] + 4] = v[it].z; WB[wst[it] + 6] = v[it].w;
        }
    }
    __syncthreads();

    int p = 0;
    for (int c = 0; c < 6; c++) {
        uint4 wv[2];
        if (c < 5) {
#pragma unroll
            for (int it = 0; it < 2; it++) wv[it] = Wg[wsrc[it] + (c + 1) * 1024];
        }
        unsigned* Wp = WB + p * 4224;

        float accs[2][2][4];
#pragma unroll
        for (int mi = 0; mi < 2; mi++)
#pragma unroll
            for (int ni = 0; ni < 2; ni++)
#pragma unroll
                for (int q = 0; q < 4; q++) accs[mi][ni][q] = 0.f;

#pragma unroll
        for (int k16 = 0; k16 < 8; k16++) {
            unsigned a[2][4], b[2][2];
#pragma unroll
            for (int mi = 0; mi < 2; mi++) {
                int base = ((wm * 2 + mi) * 2) * 528 + k16 * 66 + lane * 2;
                uint2 q0 = *reinterpret_cast<const uint2*>(&XA[base]);
                uint2 q1 = *reinterpret_cast<const uint2*>(&XA[base + 528]);
                a[mi][0] = q0.x; a[mi][2] = q0.y;
                a[mi][1] = q1.x; a[mi][3] = q1.y;
            }
#pragma unroll
            for (int ni = 0; ni < 2; ni++) {
                uint2 q = *reinterpret_cast<const uint2*>(&Wp[(wn * 2 + ni) * 528 + k16 * 66 + lane * 2]);
                b[ni][0] = q.x; b[ni][1] = q.y;
            }
#pragma unroll
            for (int mi = 0; mi < 2; mi++)
#pragma unroll
                for (int ni = 0; ni < 2; ni++)
                    MMA_BF16(accs[mi][ni], a[mi][0], a[mi][1], a[mi][2], a[mi][3],
                             b[ni][0], b[ni][1]);
        }

        float sc = (c < 2) ? scale : 1.0f;   // chunks 0,1 = Q columns
#pragma unroll
        for (int mi = 0; mi < 2; mi++) {
#pragma unroll
            for (int rh = 0; rh < 2; rh++) {
                int r = bm + wm * 32 + mi * 16 + g + rh * 8;
#pragma unroll
                for (int ni = 0; ni < 2; ni++) {
                    int cw = c * 32 + wn * 8 + ni * 4 + t;
                    int col = 2 * cw;
                    out[(size_t)r * 192 + cw] =
                        pack_bf((accs[mi][ni][rh * 2 + 0] + bias[col]) * sc,
                                (accs[mi][ni][rh * 2 + 1] + bias[col + 1]) * sc);
                }
            }
        }

        if (c < 5) {
            unsigned* Wn = WB + (p ^ 1) * 4224;
#pragma unroll
            for (int it = 0; it < 2; it++) {
                Wn[wst[it] + 0] = wv[it].x; Wn[wst[it] + 2] = wv[it].y;
                Wn[wst[it] + 4] = wv[it].z; Wn[wst[it] + 6] = wv[it].w;
            }
            p ^= 1;
        }
        __syncthreads();
    }
}

// ---------------- window attention: all bf16 (QK + PV) ----------------
// smem words: QA 0..2112 | KB 2112..4224 | VB 4224..6336
#define SM_QA 0
#define SM_KB 2112
#define SM_VB 4224
#define SMEM_ATTN (6336 * 4)

__global__ __launch_bounds__(256) void attn_kernel(const unsigned* __restrict__ qkv,
                                                   const float* __restrict__ ps,
                                                   unsigned* __restrict__ attout) {
    extern __shared__ unsigned sm[];
    unsigned* QA = sm + SM_QA;
    unsigned* KB = sm + SM_KB;
    unsigned* VB = sm + SM_VB;

    const int win = blockIdx.x, head = blockIdx.y;
    const int tid = threadIdx.x;
    const int lane = tid & 31, w = tid >> 5;
    const int g = lane >> 2, t = lane & 3;
    const float* psh = ps + (size_t)((win & 255) * 4 + head) * 4096;
    const uint4* qkv4 = reinterpret_cast<const uint4*>(qkv);

    // stage Q (A word layout) and K (B word layout)
#pragma unroll
    for (int it = 0; it < 2; it++) {
        int e = tid + it * 256;          // 0..511
        int row = e >> 2, q4 = e & 3;
        size_t idx = ((size_t)(win * 128 + row)) * 48 + head * 4 + q4;
        uint4 qv = qkv4[idx];
        uint4 kv = qkv4[idx + 16];
        int rgq = ((row >> 4) * 2 + ((row >> 3) & 1)) * 132 + (row & 7) * 8;
        int rgk = (row >> 3) * 132 + (row & 7) * 8;
        unsigned qw[4] = {qv.x, qv.y, qv.z, qv.w};
        unsigned kw[4] = {kv.x, kv.y, kv.z, kv.w};
#pragma unroll
        for (int j = 0; j < 4; j++) {
            int wd = q4 * 4 + j;
            int off = (wd >> 3) * 66 + ((wd >> 2) & 1) + 2 * (wd & 3);
            QA[rgq + off] = qw[j];
            KB[rgk + off] = kw[j];
        }
    }
    // stage V: repack dim-pairs -> token-pairs via byte_perm
    {
        int e = tid;                     // 0..255
        int tp = e >> 2, q4 = e & 3;     // token pair, uint4 index
        size_t idxe = ((size_t)(win * 128 + 2 * tp)) * 48 + head * 4 + 32 + q4;
        uint4 ve = qkv4[idxe];
        uint4 vo = qkv4[idxe + 48];
        int kc = tp >> 3, kw2 = tp & 7;
        int off = (kw2 & 3) * 2 + (kw2 >> 2);
        unsigned ew[4] = {ve.x, ve.y, ve.z, ve.w};
        unsigned ow[4] = {vo.x, vo.y, vo.z, vo.w};
#pragma unroll
        for (int j = 0; j < 4; j++) {
            int wd = q4 * 4 + j;         // word -> dims 2wd, 2wd+1
            unsigned d0 = __byte_perm(ew[j], ow[j], 0x5410);
            unsigned d1 = __byte_perm(ew[j], ow[j], 0x7632);
            int n0 = 2 * wd, n1 = 2 * wd + 1;
            VB[(n0 >> 3) * 528 + kc * 66 + (n0 & 7) * 8 + off] = d0;
            VB[(n1 >> 3) * 528 + kc * 66 + (n1 & 7) * 8 + off] = d1;
        }
    }
    __syncthreads();

    // S = Q @ K^T (bf16, K=32 -> 2 k16 steps)
    float acc[16][4];
#pragma unroll
    for (int nt = 0; nt < 16; nt++)
#pragma unroll
        for (int i = 0; i < 4; i++) acc[nt][i] = 0.f;

#pragma unroll
    for (int k16 = 0; k16 < 2; k16++) {
        int abase = (w * 2) * 132 + k16 * 66 + lane * 2;
        uint2 q0 = *reinterpret_cast<const uint2*>(&QA[abase]);
        uint2 q1 = *reinterpret_cast<const uint2*>(&QA[abase + 132]);
#pragma unroll
        for (int nt = 0; nt < 16; nt++) {
            uint2 b = *reinterpret_cast<const uint2*>(&KB[nt * 132 + k16 * 66 + lane * 2]);
            MMA_BF16(acc[nt], q0.x, q1.x, q0.y, q1.y, b.x, b.y);
        }
    }

    // + rpb/mask, softmax
    const int qtile = w & 3;
    float m0 = -1e30f, m1 = -1e30f;
#pragma unroll
    for (int nt = 0; nt < 16; nt++) {
        float4 p = *reinterpret_cast<const float4*>(psh + ((qtile * 8 + (nt & 7)) * 32 + lane) * 4);
        acc[nt][0] += p.x; acc[nt][1] += p.y;
        acc[nt][2] += p.z; acc[nt][3] += p.w;
        m0 = fmaxf(m0, fmaxf(acc[nt][0], acc[nt][1]));
        m1 = fmaxf(m1, fmaxf(acc[nt][2], acc[nt][3]));
    }
    m0 = fmaxf(m0, __shfl_xor_sync(0xffffffffu, m0, 1));
    m0 = fmaxf(m0, __shfl_xor_sync(0xffffffffu, m0, 2));
    m1 = fmaxf(m1, __shfl_xor_sync(0xffffffffu, m1, 1));
    m1 = fmaxf(m1, __shfl_xor_sync(0xffffffffu, m1, 2));

    float l0 = 0.f, l1 = 0.f;
#pragma unroll
    for (int nt = 0; nt < 16; nt++) {
        acc[nt][0] = __expf(acc[nt][0] - m0);
        acc[nt][1] = __expf(acc[nt][1] - m0);
        acc[nt][2] = __expf(acc[nt][2] - m1);
        acc[nt][3] = __expf(acc[nt][3] - m1);
        l0 += acc[nt][0] + acc[nt][1];
        l1 += acc[nt][2] + acc[nt][3];
    }
    l0 += __shfl_xor_sync(0xffffffffu, l0, 1);
    l0 += __shfl_xor_sync(0xffffffffu, l0, 2);
    l1 += __shfl_xor_sync(0xffffffffu, l1, 1);
    l1 += __shfl_xor_sync(0xffffffffu, l1, 2);
    float inv0 = 1.0f / l0, inv1 = 1.0f / l1;

    // O = P @ V (bf16): C-frag cols pack directly into bf16 A k-pairs
    float oacc[4][4];
#pragma unroll
    for (int n8 = 0; n8 < 4; n8++)
#pragma unroll
        for (int i = 0; i < 4; i++) oacc[n8][i] = 0.f;

#pragma unroll
    for (int kc = 0; kc < 8; kc++) {
        unsigned a0 = pack_bf(acc[2 * kc][0], acc[2 * kc][1]);
        unsigned a1 = pack_bf(acc[2 * kc][2], acc[2 * kc][3]);
        unsigned a2 = pack_bf(acc[2 * kc + 1][0], acc[2 * kc + 1][1]);
        unsigned a3 = pack_bf(acc[2 * kc + 1][2], acc[2 * kc + 1][3]);
#pragma unroll
        for (int n8 = 0; n8 < 4; n8++) {
            uint2 b = *reinterpret_cast<const uint2*>(&VB[n8 * 528 + kc * 66 + lane * 2]);
            MMA_BF16(oacc[n8], a0, a1, a2, a3, b.x, b.y);
        }
    }

    int r0 = win * 128 + w * 16 + g;
#pragma unroll
    for (int n8 = 0; n8 < 4; n8++) {
        int colw = head * 16 + n8 * 4 + t;
        attout[(size_t)r0 * 64 + colw]       = pack_bf(oacc[n8][0] * inv0, oacc[n8][1] * inv0);
        attout[(size_t)(r0 + 8) * 64 + colw] = pack_bf(oacc[n8][2] * inv1, oacc[n8][3] * inv1);
    }
}

// ---------------- proj (bf16) + scatter + residual + LN2 (unchanged) ----------------
#define PROJ_SMEM (8448 * 4)
__global__ __launch_bounds__(256) void projln_kernel(
    const unsigned* __restrict__ attn, const unsigned* __restrict__ Wp_,
    const float* __restrict__ bias, const float* __restrict__ res,
    float* __restrict__ xres, float* __restrict__ xln,
    const float* __restrict__ gw, const float* __restrict__ bw) {
    extern __shared__ unsigned sm[];
    unsigned* OA = sm;
    __shared__ float smS[128][2], smQ[128][2];

    const int win = blockIdx.x;
    const int tid = threadIdx.x;
    const int lane = tid & 31, w = tid >> 5;
    const int g = lane >> 2, t = lane & 3;
    const int wm = w >> 1, wn = w & 1;

    const uint4* attn4 = reinterpret_cast<const uint4*>(attn);
#pragma unroll
    for (int it = 0; it < 8; it++) {
        int e = tid + it * 256;
        int row = e >> 4, q4 = e & 15;
        uint4 v = attn4[((size_t)(win * 128 + row)) * 16 + q4];
        int base = ((row >> 4) * 2 + ((row >> 3) & 1)) * 528 + (row & 7) * 8 +
                   (q4 >> 1) * 66 + (q4 & 1);
        OA[base + 0] = v.x; OA[base + 2] = v.y; OA[base + 4] = v.z; OA[base + 6] = v.w;
    }
    __syncthreads();

    const uint2* Wp2 = reinterpret_cast<const uint2*>(Wp_);
    float acc2[2][8][4];
#pragma unroll
    for (int mi = 0; mi < 2; mi++)
#pragma unroll
        for (int ni = 0; ni < 8; ni++)
#pragma unroll
            for (int q = 0; q < 4; q++) acc2[mi][ni][q] = 0.f;

#pragma unroll
    for (int k16 = 0; k16 < 8; k16++) {
        unsigned a[2][4];
#pragma unroll
        for (int mi = 0; mi < 2; mi++) {
            int base = ((wm * 2 + mi) * 2) * 528 + k16 * 66 + lane * 2;
            uint2 q0 = *reinterpret_cast<const uint2*>(&OA[base]);
            uint2 q1 = *reinterpret_cast<const uint2*>(&OA[base + 528]);
            a[mi][0] = q0.x; a[mi][2] = q0.y;
            a[mi][1] = q1.x; a[mi][3] = q1.y;
        }
#pragma unroll
        for (int ni = 0; ni < 8; ni++) {
            uint2 b = Wp2[((wn * 8 + ni) * 8 + k16) * 32 + lane];
#pragma unroll
            for (int mi = 0; mi < 2; mi++)
                MMA_BF16(acc2[mi][ni], a[mi][0], a[mi][1], a[mi][2], a[mi][3], b.x, b.y);
        }
    }

#pragma unroll
    for (int mi = 0; mi < 2; mi++) {
#pragma unroll
        for (int rh = 0; rh < 2; rh++) {
            int lrow = wm * 32 + mi * 16 + g + rh * 8;
            int xrow = perm_row(win * 128 + lrow);
            float v[16];
            float s = 0.f, q = 0.f;
#pragma unroll
            for (int ni = 0; ni < 8; ni++) {
                int cc = wn * 64 + ni * 8 + t * 2;
                float2 rr = *reinterpret_cast<const float2*>(res + (size_t)xrow * 128 + cc);
                float x0 = acc2[mi][ni][rh * 2 + 0] + bias[cc] + rr.x;
                float x1 = acc2[mi][ni][rh * 2 + 1] + bias[cc + 1] + rr.y;
                *reinterpret_cast<float2*>(xres + (size_t)xrow * 128 + cc) = make_float2(x0, x1);
                v[ni * 2 + 0] = x0; v[ni * 2 + 1] = x1;
                s += x0 + x1; q += x0 * x0 + x1 * x1;
            }
            s += __shfl_xor_sync(0xffffffffu, s, 1);
            s += __shfl_xor_sync(0xffffffffu, s, 2);
            q += __shfl_xor_sync(0xffffffffu, q, 1);
            q += __shfl_xor_sync(0xffffffffu, q, 2);
            if (t == 0) { smS[lrow][wn] = s; smQ[lrow][wn] = q; }
            __syncthreads();
            float S = smS[lrow][0] + smS[lrow][1];
            float Q = smQ[lrow][0] + smQ[lrow][1];
            float mu = S * (1.f / 128.f);
            float var = Q * (1.f / 128.f) - mu * mu;
            float rs = rsqrtf(var + 1e-5f);
#pragma unroll
            for (int ni = 0; ni < 8; ni++) {
                int cc = wn * 64 + ni * 8 + t * 2;
                float2 o;
                o.x = round_tf((v[ni * 2 + 0] - mu) * rs * gw[cc] + bw[cc]);
                o.y = round_tf((v[ni * 2 + 1] - mu) * rs * gw[cc + 1] + bw[cc + 1]);
                *reinterpret_cast<float2*>(xln + (size_t)xrow * 128 + cc) = o;
            }
        }
    }
}

// ---------------- fused MLP (bf16): fc1 + gelu + fc2 + residual + LN1 (unchanged) ----------------
#define MLP_SMEM (21120 * 4)
__global__ __launch_bounds__(512) void mlp_kernel(
    const float* __restrict__ xln, const unsigned* __restrict__ W1g4_,
    const unsigned* __restrict__ W2g4_,
    const float* __restrict__ b1, const float* __restrict__ b2,
    const float* __restrict__ res, float* __restrict__ out,
    const float* __restrict__ gw, const float* __restrict__ bw) {
    extern __shared__ unsigned sm[];
    unsigned* XA = sm;
    unsigned* W1 = sm + 8448;
    unsigned* W2 = sm + 12672;
    unsigned* HH = sm + 16896;
    __shared__ float smS[128][4], smQ[128][4];

    const uint4* W1g = reinterpret_cast<const uint4*>(W1g4_);
    const uint4* W2g = reinterpret_cast<const uint4*>(W2g4_);

    const int tid = threadIdx.x;
    const int lane = tid & 31;
    const int wid = tid >> 5;
    const int wm = wid >> 2, wn = wid & 3;
    const int g = lane >> 2, t = lane & 3;
    const int bm = blockIdx.x * 128;

#pragma unroll
    for (int it = 0; it < 8; it++) {
        int c = tid + it * 512;
        int row = c >> 5, kq = c & 31;
        float4 v = *reinterpret_cast<const float4*>(xln + (size_t)(bm + row) * 128 + kq * 4);
        int rg = ((row >> 4) * 2 + ((row >> 3) & 1)) * 528 + (row & 7) * 8;
        int w0 = 2 * kq, w1 = 2 * kq + 1;
        XA[rg + (w0 >> 3) * 66 + ((w0 >> 2) & 1) + 2 * (w0 & 3)] = pack_bf(v.x, v.y);
        XA[rg + (w1 >> 3) * 66 + ((w1 >> 2) & 1) + 2 * (w1 & 3)] = pack_bf(v.z, v.w);
    }

    int w1src[2], w1st[2], w2src[2], w2st[2];
#pragma unroll
    for (int it = 0; it < 2; it++) {
        int e = tid + it * 512;
        int n = e >> 4, wq = e & 15;
        w1src[it] = n * 16 + wq;
        w1st[it] = (n >> 3) * 528 + (wq >> 1) * 66 + (n & 7) * 8 + (wq & 1);
        int n2 = e >> 3, wq2 = e & 7;
        w2src[it] = n2 * 64 + wq2;
        w2st[it] = (n2 >> 3) * 264 + (wq2 >> 1) * 66 + (n2 & 7) * 8 + (wq2 & 1);
    }

    {
        uint4 v[2];
#pragma unroll
        for (int it = 0; it < 2; it++) v[it] = W1g[w1src[it]];
#pragma unroll
        for (int it = 0; it < 2; it++) {
            W1[w1st[it] + 0] = v[it].x; W1[w1st[it] + 2] = v[it].y;
            W1[w1st[it] + 4] = v[it].z; W1[w1st[it] + 6] = v[it].w;
        }
    }
    __syncthreads();

    float acco[2][4][4];
#pragma unroll
    for (int mi = 0; mi < 2; mi++)
#pragma unroll
        for (int ni = 0; ni < 4; ni++)
#pragma unroll
            for (int c = 0; c < 4; c++) acco[mi][ni][c] = 0.f;

    for (int c = 0; c < 8; c++) {
        uint4 w2v[2];
#pragma unroll
        for (int it = 0; it < 2; it++) w2v[it] = W2g[w2src[it] + c * 8];

        float accs[2][2][4];
#pragma unroll
        for (int mi = 0; mi < 2; mi++)
#pragma unroll
            for (int ni = 0; ni < 2; ni++)
#pragma unroll
                for (int q = 0; q < 4; q++) accs[mi][ni][q] = 0.f;
#pragma unroll
        for (int k16 = 0; k16 < 8; k16++) {
            unsigned a[2][4], b[2][2];
#pragma unroll
            for (int mi = 0; mi < 2; mi++) {
                int base = ((wm * 2 + mi) * 2) * 528 + k16 * 66 + lane * 2;
                uint2 q0 = *reinterpret_cast<const uint2*>(&XA[base]);
                uint2 q1 = *reinterpret_cast<const uint2*>(&XA[base + 528]);
                a[mi][0] = q0.x; a[mi][2] = q0.y;
                a[mi][1] = q1.x; a[mi][3] = q1.y;
            }
#pragma unroll
            for (int ni = 0; ni < 2; ni++) {
                uint2 q = *reinterpret_cast<const uint2*>(&W1[(wn * 2 + ni) * 528 + k16 * 66 + lane * 2]);
                b[ni][0] = q.x; b[ni][1] = q.y;
            }
#pragma unroll
            for (int mi = 0; mi < 2; mi++)
#pragma unroll
                for (int ni = 0; ni < 2; ni++)
                    MMA_BF16(accs[mi][ni], a[mi][0], a[mi][1], a[mi][2], a[mi][3],
                             b[ni][0], b[ni][1]);
        }

#pragma unroll
        for (int it = 0; it < 2; it++) {
            W2[w2st[it] + 0] = w2v[it].x; W2[w2st[it] + 2] = w2v[it].y;
            W2[w2st[it] + 4] = w2v[it].z; W2[w2st[it] + 6] = w2v[it].w;
        }

#pragma unroll
        for (int mi = 0; mi < 2; mi++) {
#pragma unroll
            for (int ni = 0; ni < 2; ni++) {
                int kl0 = wn * 16 + ni * 8 + t * 2;
                int ww = kl0 >> 1;
                int wof = (ww >> 3) * 66 + ((ww >> 2) & 1) + 2 * (ww & 3);
                float bb0 = b1[c * 64 + kl0], bb1 = b1[c * 64 + kl0 + 1];
#pragma unroll
                for (int rh = 0; rh < 2; rh++) {
                    float x0 = accs[mi][ni][rh * 2 + 0] + bb0;
                    float x1 = accs[mi][ni][rh * 2 + 1] + bb1;
                    x0 = 0.5f * x0 * (1.0f + erff(x0 * 0.7071067811865475f));
                    x1 = 0.5f * x1 * (1.0f + erff(x1 * 0.7071067811865475f));
                    int addr = ((wm * 2 + mi) * 2 + rh) * 264 + wof + g * 8;
                    HH[addr] = pack_bf(x0, x1);
                }
            }
        }
        __syncthreads();

        uint4 w1v[2];
        if (c < 7) {
#pragma unroll
            for (int it = 0; it < 2; it++) w1v[it] = W1g[w1src[it] + (c + 1) * 1024];
        }

#pragma unroll
        for (int k16 = 0; k16 < 4; k16++) {
            unsigned a[2][4], b[4][2];
#pragma unroll
            for (int mi = 0; mi < 2; mi++) {
                int base = ((wm * 2 + mi) * 2) * 264 + k16 * 66 + lane * 2;
                uint2 q0 = *reinterpret_cast<const uint2*>(&HH[base]);
                uint2 q1 = *reinterpret_cast<const uint2*>(&HH[base + 264]);
                a[mi][0] = q0.x; a[mi][2] = q0.y;
                a[mi][1] = q1.x; a[mi][3] = q1.y;
            }
#pragma unroll
            for (int ni = 0; ni < 4; ni++) {
                uint2 q = *reinterpret_cast<const uint2*>(&W2[(wn * 4 + ni) * 264 + k16 * 66 + lane * 2]);
                b[ni][0] = q.x; b[ni][1] = q.y;
            }
#pragma unroll
            for (int mi = 0; mi < 2; mi++)
#pragma unroll
                for (int ni = 0; ni < 4; ni++)
                    MMA_BF16(acco[mi][ni], a[mi][0], a[mi][1], a[mi][2], a[mi][3],
                             b[ni][0], b[ni][1]);
        }

        if (c < 7) {
#pragma unroll
            for (int it = 0; it < 2; it++) {
                W1[w1st[it] + 0] = w1v[it].x; W1[w1st[it] + 2] = w1v[it].y;
                W1[w1st[it] + 4] = w1v[it].z; W1[w1st[it] + 6] = w1v[it].w;
            }
        }
        __syncthreads();
    }

#pragma unroll
    for (int mi = 0; mi < 2; mi++) {
#pragma unroll
        for (int rh = 0; rh < 2; rh++) {
            int lrow = wm * 32 + mi * 16 + g + rh * 8;
            int r = bm + lrow;
            float v[8];
            float s = 0.f, q = 0.f;
#pragma unroll
            for (int ni = 0; ni < 4; ni++) {
                int cc = wn * 32 + ni * 8 + t * 2;
                float2 rr = *reinterpret_cast<const float2*>(res + (size_t)r * 128 + cc);
                float x0 = acco[mi][ni][rh * 2 + 0] + b2[cc] + rr.x;
                float x1 = acco[mi][ni][rh * 2 + 1] + b2[cc + 1] + rr.y;
                v[ni * 2 + 0] = x0; v[ni * 2 + 1] = x1;
                s += x0 + x1; q += x0 * x0 + x1 * x1;
            }
            s += __shfl_xor_sync(0xffffffffu, s, 1);
            s += __shfl_xor_sync(0xffffffffu, s, 2);
            q += __shfl_xor_sync(0xffffffffu, q, 1);
            q += __shfl_xor_sync(0xffffffffu, q, 2);
            if (t == 0) { smS[lrow][wn] = s; smQ[lrow][wn] = q; }
            __syncthreads();
            float S = smS[lrow][0] + smS[lrow][1] + smS[lrow][2] + smS[lrow][3];
            float Q = smQ[lrow][0] + smQ[lrow][1] + smQ[lrow][2] + smQ[lrow][3];
            float mu = S * (1.f / 128.f);
            float var = Q * (1.f / 128.f) - mu * mu;
            float rs = rsqrtf(var + 1e-5f);
#pragma unroll
            for (int ni = 0; ni < 4; ni++) {
                int cc = wn * 32 + ni * 8 + t * 2;
                float2 o;
                o.x = (v[ni * 2 + 0] - mu) * rs * gw[cc] + bw[cc];
                o.y = (v[ni * 2 + 1] - mu) * rs * gw[cc + 1] + bw[cc + 1];
                *reinterpret_cast<float2*>(out + (size_t)r * 128 + cc) = o;
            }
        }
    }
}

// ---------------- launch ----------------
extern "C" void kernel_launch(void* const* d_in, const int* in_sizes, int n_in,
                              void* d_out, int out_size) {
    const float* x_v    = (const float*)d_in[0];
    const float* qkv_w  = (const float*)d_in[1];
    const float* qkv_b  = (const float*)d_in[2];
    const float* proj_w = (const float*)d_in[3];
    const float* proj_b = (const float*)d_in[4];
    const float* rpb    = (const float*)d_in[5];
    const float* n1w    = (const float*)d_in[6];
    const float* n1b    = (const float*)d_in[7];
    const float* n2w    = (const float*)d_in[8];
    const float* n2b    = (const float*)d_in[9];
    const float* fc1w   = (const float*)d_in[10];
    const float* fc1b   = (const float*)d_in[11];
    const float* fc2w   = (const float*)d_in[12];
    const float* fc2b   = (const float*)d_in[13];
    float* out = (float*)d_out;

    float *xln, *xres, *ps;
    unsigned *qkvb, *attn, *wtf;
    cudaGetSymbolAddress((void**)&qkvb, g_qkv);
    cudaGetSymbolAddress((void**)&attn, g_attn);
    cudaGetSymbolAddress((void**)&xln,  g_xln);
    cudaGetSymbolAddress((void**)&xres, g_xres);
    cudaGetSymbolAddress((void**)&ps,   g_ps);
    cudaGetSymbolAddress((void**)&wtf,  g_wtf);

    cudaFuncSetAttribute(qkv_kernel, cudaFuncAttributeMaxDynamicSharedMemorySize, QKV_SMEM);
    cudaFuncSetAttribute(attn_kernel, cudaFuncAttributeMaxDynamicSharedMemorySize, SMEM_ATTN);
    cudaFuncSetAttribute(projln_kernel, cudaFuncAttributeMaxDynamicSharedMemorySize, PROJ_SMEM);
    cudaFuncSetAttribute(mlp_kernel, cudaFuncAttributeMaxDynamicSharedMemorySize, MLP_SMEM);

    // 0. weight conversion (all bf16 packed) + rpb/mask table
    cvt_weights<<<384, 256>>>(qkv_w, proj_w, fc1w, fc2w, wtf);
    ps_kernel<<<dim3(256, 4), 256>>>(rpb, ps);
    // 1. qkv (bf16) = gather(x_v) @ qkv_w^T + b, packed bf16x2 output
    qkv_kernel<<<1024, 512, QKV_SMEM>>>(x_v, wtf, qkv_b, qkvb);
    // 2. window attention: all-bf16 QK + PV
    attn_kernel<<<dim3(1024, HEADS), 256, SMEM_ATTN>>>(qkvb, ps, attn);
    // 3. proj (bf16) + scatter + residual + LN2
    projln_kernel<<<1024, 256, PROJ_SMEM>>>(attn, wtf + 24576, proj_b,
                                            x_v, xres, xln, n2w, n2b);
    // 4. fused MLP (bf16) -> final output
    mlp_kernel<<<1024, 512, MLP_SMEM>>>(xln, wtf + 32768, wtf + 65536,
                                        fc1b, fc2b, xres, out, n1w, n1b);
}